// round 2
// baseline (speedup 1.0000x reference)
#include <cuda_runtime.h>

#define UQ   2048
#define BB   4
#define DD   512
#define RR   64
#define SSL  64
#define MML  64
#define QL   2176   // R + U + S
#define KVL  2176   // M + R + U
#define NH   8
#define DH   64
#define NEGINF (-100000000.0f)
#define MROWS (QL*BB)          // 8704
#define RCU_ROWS 2112
#define RCU_SZ (2112*4*512)    // 4,325,376
#define MASK_N (QL*KVL)        // 4,734,976

// -------------------- device scratch (no allocation allowed) ----------------
__device__ float g_qin  [QL  * BB * DD];
__device__ float g_kvin [KVL * BB * DD];
__device__ float g_query[QL  * BB * DD];
__device__ float g_kv   [KVL * BB * 2 * DD];
__device__ float g_attn [QL  * BB * DD];
__device__ unsigned char g_mask[MASK_N];
__device__ int g_mask_kind;           // 0=u8, 1=i32, 2=f32, 3=bf16

// -------------------- mask dtype sniff (deterministic, on-device) -----------
// Scans the first 1MB of the raw mask buffer (smallest possible buffer is
// MASK_N bytes = 4.7MB, so this is always in-bounds) and classifies how the
// harness encoded the boolean mask.
__global__ void mask_sniff_kernel(const unsigned char* __restrict__ raw) {
    __shared__ int sh[3];  // gt1_low, gt1_high, nz_off
    int f_gt1_low = 0, f_gt1_high = 0, f_nz_off = 0;
    const int SCAN = 1 << 20;
    for (int i = threadIdx.x * 4; i < SCAN; i += blockDim.x * 4) {
        uchar4 v = *(const uchar4*)(raw + i);   // i % 4 == 0 aligned
        if (v.x > 1) f_gt1_low = 1;
        if (v.y > 1) f_gt1_low = 1;
        if (v.z > 1) f_gt1_high = 1;
        if (v.w > 1) f_gt1_high = 1;
        if (v.y | v.z | v.w) f_nz_off = 1;
    }
    if (threadIdx.x == 0) { sh[0] = 0; sh[1] = 0; sh[2] = 0; }
    __syncthreads();
    if (f_gt1_low)  atomicOr(&sh[0], 1);
    if (f_gt1_high) atomicOr(&sh[1], 1);
    if (f_nz_off)   atomicOr(&sh[2], 1);
    __syncthreads();
    if (threadIdx.x == 0) {
        int kind;
        if (sh[0])      kind = 3;   // bf16 (0x80,0x3F in low half-group)
        else if (sh[1]) kind = 2;   // f32  (0x80,0x3F at bytes 2,3)
        else if (sh[2]) kind = 0;   // u8   (0/1 bytes at all positions)
        else            kind = 1;   // i32  (0/1 only at pos%4==0)
        g_mask_kind = kind;
    }
}

__global__ void mask_convert_kernel(const void* __restrict__ raw) {
    int kind = g_mask_kind;
    int i = blockIdx.x * blockDim.x + threadIdx.x;
    int stride = gridDim.x * blockDim.x;
    if (kind == 0) {
        const unsigned char* p = (const unsigned char*)raw;
        for (int e = i; e < MASK_N; e += stride) g_mask[e] = p[e] ? 1 : 0;
    } else if (kind == 1) {
        const int* p = (const int*)raw;
        for (int e = i; e < MASK_N; e += stride) g_mask[e] = p[e] ? 1 : 0;
    } else if (kind == 2) {
        const float* p = (const float*)raw;
        for (int e = i; e < MASK_N; e += stride) g_mask[e] = (p[e] != 0.f) ? 1 : 0;
    } else {
        const unsigned short* p = (const unsigned short*)raw;
        for (int e = i; e < MASK_N; e += stride)
            g_mask[e] = ((p[e] & 0x7fff) != 0) ? 1 : 0;   // bf16 +-0 -> false
    }
}

// -------------------- gather: build q_in and kv_in --------------------------
__global__ void gather_kernel(const float* __restrict__ utt,
                              const float* __restrict__ rc,
                              const float* __restrict__ summ,
                              const float* __restrict__ mem) {
    const int VB = BB * DD / 4;   // 512 float4 per sequence position
    const int total = QL * VB;
    int i = blockIdx.x * blockDim.x + threadIdx.x;
    if (i < total) {
        int q = i / VB, rem = i - q * VB;
        const float4* src; int sr;
        if (q < RR)           { src = (const float4*)rc;   sr = q; }
        else if (q < RR + UQ) { src = (const float4*)utt;  sr = q - RR; }
        else                  { src = (const float4*)summ; sr = q - RR - UQ; }
        ((float4*)g_qin)[i] = src[(size_t)sr * VB + rem];
    } else if (i < 2 * total) {
        int j = i - total;
        int k = j / VB, rem = j - k * VB;
        const float4* src; int sr;
        if (k < MML)           { src = (const float4*)mem; sr = k; }
        else if (k < MML + RR) { src = (const float4*)rc;  sr = k - MML; }
        else                   { src = (const float4*)utt; sr = k - MML - RR; }
        ((float4*)g_kvin)[j] = src[(size_t)sr * VB + rem];
    }
}

// -------------------- fp32 SGEMM: C[M,N] = A[M,512] @ W[512,N] + bias -------
template<int NN, int MODE>
__global__ __launch_bounds__(256)
void sgemm_kernel(const float* __restrict__ A, const float* __restrict__ W,
                  const float* __restrict__ bias, float* __restrict__ C) {
    __shared__ float As[8 * 128];
    __shared__ float Bs[8 * 128];
    const int tid = threadIdx.x;
    const int tr = tid >> 4, tc = tid & 15;
    const int m0 = blockIdx.y * 128;
    const int n0 = blockIdx.x * 128;

    float acc[8][8];
    #pragma unroll
    for (int i = 0; i < 8; i++)
        #pragma unroll
        for (int j = 0; j < 8; j++) acc[i][j] = 0.f;

    const int rowA = tid >> 1;
    const int ka   = (tid & 1) << 2;
    const int kb   = tid >> 5;
    const int nb   = (tid & 31) << 2;

    for (int k0 = 0; k0 < 512; k0 += 8) {
        __syncthreads();
        float4 av = *(const float4*)(A + (size_t)(m0 + rowA) * 512 + k0 + ka);
        As[(ka + 0) * 128 + rowA] = av.x;
        As[(ka + 1) * 128 + rowA] = av.y;
        As[(ka + 2) * 128 + rowA] = av.z;
        As[(ka + 3) * 128 + rowA] = av.w;
        *(float4*)(Bs + kb * 128 + nb) =
            *(const float4*)(W + (size_t)(k0 + kb) * NN + n0 + nb);
        __syncthreads();
        #pragma unroll
        for (int kk = 0; kk < 8; kk++) {
            float a[8], bv[8];
            *(float4*)(a)     = *(const float4*)(As + kk * 128 + tr * 8);
            *(float4*)(a + 4) = *(const float4*)(As + kk * 128 + tr * 8 + 4);
            *(float4*)(bv)     = *(const float4*)(Bs + kk * 128 + tc * 8);
            *(float4*)(bv + 4) = *(const float4*)(Bs + kk * 128 + tc * 8 + 4);
            #pragma unroll
            for (int i = 0; i < 8; i++)
                #pragma unroll
                for (int j = 0; j < 8; j++)
                    acc[i][j] = fmaf(a[i], bv[j], acc[i][j]);
        }
    }

    #pragma unroll
    for (int i = 0; i < 8; i++) {
        int m = m0 + tr * 8 + i;
        #pragma unroll
        for (int j = 0; j < 8; j++) {
            int n = n0 + tc * 8 + j;
            float v = acc[i][j] + __ldg(bias + n);
            if (MODE == 0) {
                C[(size_t)m * NN + n] = v;
            } else {
                int q = m >> 2, b = m & 3;   // B = 4
                if (q < RCU_ROWS) {
                    C[(size_t)m * DD + n] = v;
                } else if (q < QL - 1) {
                    v = fminf(fmaxf(v, -10.f), 10.f);
                    C[RCU_SZ + (size_t)((q - RCU_ROWS) * BB + b) * DD + n] = v;
                }
            }
        }
    }
}

// -------------------- flash attention (fp32, online softmax) ----------------
__global__ __launch_bounds__(256)
void attn_kernel(const int* __restrict__ lengths) {
    extern __shared__ float smdyn[];
    float* Qs = smdyn;
    float* Ks = smdyn + 64 * 68;   // reused for P after scores are consumed
    float* Vs = smdyn + 2 * 64 * 68;

    const int tid = threadIdx.x;
    const int b = blockIdx.y >> 3;
    const int h = blockIdx.y & 7;
    const int q0 = blockIdx.x * 64;
    const int tr = tid >> 4, tc = tid & 15;
    const int r0 = tr * 4, c0 = tc * 4;
    const int limit = (KVL - UQ) + __ldg(lengths + b);   // pad: k >= limit masked

    #pragma unroll
    for (int it = 0; it < 4; it++) {
        int v = tid + it * 256;
        int row = v >> 4, c4 = (v & 15) << 2;
        float4 qv = *(const float4*)(g_query +
                     ((size_t)(q0 + row) * BB + b) * DD + h * DH + c4);
        qv.x *= 0.125f; qv.y *= 0.125f; qv.z *= 0.125f; qv.w *= 0.125f;
        *(float4*)(Qs + row * 68 + c4) = qv;
    }

    float m_i[4], l_i[4], o[4][4];
    #pragma unroll
    for (int i = 0; i < 4; i++) {
        m_i[i] = -3.0e38f; l_i[i] = 0.f;
        #pragma unroll
        for (int n = 0; n < 4; n++) o[i][n] = 0.f;
    }

    for (int k0 = 0; k0 < KVL; k0 += 64) {
        __syncthreads();
        #pragma unroll
        for (int it = 0; it < 4; it++) {
            int v = tid + it * 256;
            int row = v >> 4, c4 = (v & 15) << 2;
            size_t base = ((size_t)(k0 + row) * BB + b) * (2 * DD) + h * DH + c4;
            *(float4*)(Ks + row * 68 + c4) = *(const float4*)(g_kv + base);
            *(float4*)(Vs + row * 68 + c4) = *(const float4*)(g_kv + base + DD);
        }
        __syncthreads();

        float s[4][4];
        #pragma unroll
        for (int i = 0; i < 4; i++)
            #pragma unroll
            for (int j = 0; j < 4; j++) s[i][j] = 0.f;
        #pragma unroll
        for (int d = 0; d < 64; d += 4) {
            float4 qa[4], kb4[4];
            #pragma unroll
            for (int i = 0; i < 4; i++)
                qa[i] = *(const float4*)(Qs + (r0 + i) * 68 + d);
            #pragma unroll
            for (int j = 0; j < 4; j++)
                kb4[j] = *(const float4*)(Ks + (c0 + j) * 68 + d);
            #pragma unroll
            for (int i = 0; i < 4; i++)
                #pragma unroll
                for (int j = 0; j < 4; j++) {
                    s[i][j] = fmaf(qa[i].x, kb4[j].x, s[i][j]);
                    s[i][j] = fmaf(qa[i].y, kb4[j].y, s[i][j]);
                    s[i][j] = fmaf(qa[i].z, kb4[j].z, s[i][j]);
                    s[i][j] = fmaf(qa[i].w, kb4[j].w, s[i][j]);
                }
        }

        // masks: normalized attention mask (1 = masked) + length padding
        #pragma unroll
        for (int i = 0; i < 4; i++) {
            int qg = q0 + r0 + i;
            uchar4 mv = *(const uchar4*)(g_mask + (size_t)qg * KVL + k0 + c0);
            int kg = k0 + c0;
            if (mv.x || kg + 0 >= limit) s[i][0] = NEGINF;
            if (mv.y || kg + 1 >= limit) s[i][1] = NEGINF;
            if (mv.z || kg + 2 >= limit) s[i][2] = NEGINF;
            if (mv.w || kg + 3 >= limit) s[i][3] = NEGINF;
        }

        #pragma unroll
        for (int i = 0; i < 4; i++) {
            float tm = fmaxf(fmaxf(s[i][0], s[i][1]), fmaxf(s[i][2], s[i][3]));
            #pragma unroll
            for (int off = 8; off >= 1; off >>= 1)
                tm = fmaxf(tm, __shfl_xor_sync(0xffffffffu, tm, off, 16));
            float mn = fmaxf(m_i[i], tm);
            float corr = __expf(m_i[i] - mn);
            float ps = 0.f;
            #pragma unroll
            for (int j = 0; j < 4; j++) {
                float p = __expf(s[i][j] - mn);
                s[i][j] = p; ps += p;
            }
            #pragma unroll
            for (int off = 8; off >= 1; off >>= 1)
                ps += __shfl_xor_sync(0xffffffffu, ps, off, 16);
            l_i[i] = l_i[i] * corr + ps;
            m_i[i] = mn;
            #pragma unroll
            for (int n = 0; n < 4; n++) o[i][n] *= corr;
        }

        __syncthreads();
        #pragma unroll
        for (int i = 0; i < 4; i++)
            *(float4*)(Ks + (r0 + i) * 68 + c0) =
                make_float4(s[i][0], s[i][1], s[i][2], s[i][3]);
        __syncthreads();

        #pragma unroll 8
        for (int j = 0; j < 64; j++) {
            float4 vv = *(const float4*)(Vs + j * 68 + c0);
            float p0 = Ks[(r0 + 0) * 68 + j];
            float p1 = Ks[(r0 + 1) * 68 + j];
            float p2 = Ks[(r0 + 2) * 68 + j];
            float p3 = Ks[(r0 + 3) * 68 + j];
            o[0][0] = fmaf(p0, vv.x, o[0][0]); o[0][1] = fmaf(p0, vv.y, o[0][1]);
            o[0][2] = fmaf(p0, vv.z, o[0][2]); o[0][3] = fmaf(p0, vv.w, o[0][3]);
            o[1][0] = fmaf(p1, vv.x, o[1][0]); o[1][1] = fmaf(p1, vv.y, o[1][1]);
            o[1][2] = fmaf(p1, vv.z, o[1][2]); o[1][3] = fmaf(p1, vv.w, o[1][3]);
            o[2][0] = fmaf(p2, vv.x, o[2][0]); o[2][1] = fmaf(p2, vv.y, o[2][1]);
            o[2][2] = fmaf(p2, vv.z, o[2][2]); o[2][3] = fmaf(p2, vv.w, o[2][3]);
            o[3][0] = fmaf(p3, vv.x, o[3][0]); o[3][1] = fmaf(p3, vv.y, o[3][1]);
            o[3][2] = fmaf(p3, vv.z, o[3][2]); o[3][3] = fmaf(p3, vv.w, o[3][3]);
        }
    }

    #pragma unroll
    for (int i = 0; i < 4; i++) {
        float inv = 1.0f / l_i[i];
        size_t base = ((size_t)(q0 + r0 + i) * BB + b) * DD + h * DH + c0;
        *(float4*)(g_attn + base) =
            make_float4(o[i][0] * inv, o[i][1] * inv, o[i][2] * inv, o[i][3] * inv);
    }
}

// -------------------- launch ------------------------------------------------
extern "C" void kernel_launch(void* const* d_in, const int* in_sizes, int n_in,
                              void* d_out, int out_size) {
    const float* utt          = (const float*)d_in[0];
    const int*   lengths      = (const int*)d_in[1];
    const float* rc           = (const float*)d_in[2];
    const float* summ         = (const float*)d_in[3];
    const float* mem          = (const float*)d_in[4];
    const void*  mask_raw     = (const void*)d_in[5];
    const float* w_q   = (const float*)d_in[6];
    const float* b_q   = (const float*)d_in[7];
    const float* w_kv  = (const float*)d_in[8];
    const float* b_kv  = (const float*)d_in[9];
    const float* w_out = (const float*)d_in[10];
    const float* b_out = (const float*)d_in[11];
    float* out = (float*)d_out;

    void *p;
    cudaGetSymbolAddress(&p, g_qin);   float* qin   = (float*)p;
    cudaGetSymbolAddress(&p, g_kvin);  float* kvin  = (float*)p;
    cudaGetSymbolAddress(&p, g_query); float* query = (float*)p;
    cudaGetSymbolAddress(&p, g_kv);    float* kvbuf = (float*)p;
    cudaGetSymbolAddress(&p, g_attn);  float* attn  = (float*)p;

    // 0. mask dtype sniff + normalize to uint8
    mask_sniff_kernel<<<1, 1024>>>((const unsigned char*)mask_raw);
    mask_convert_kernel<<<512, 256>>>(mask_raw);

    // 1. gather q_in / kv_in
    {
        int totalv = 2 * QL * (BB * DD / 4);
        gather_kernel<<<(totalv + 255) / 256, 256>>>(utt, rc, summ, mem);
    }
    // 2. Q projection
    {
        dim3 g(DD / 128, MROWS / 128);
        sgemm_kernel<512, 0><<<g, 256>>>(qin, w_q, b_q, query);
    }
    // 3. KV projection
    {
        dim3 g(1024 / 128, MROWS / 128);
        sgemm_kernel<1024, 0><<<g, 256>>>(kvin, w_kv, b_kv, kvbuf);
    }
    // 4. attention
    {
        const int smem = 3 * 64 * 68 * 4;   // 52224
        cudaFuncSetAttribute(attn_kernel,
                             cudaFuncAttributeMaxDynamicSharedMemorySize, smem);
        dim3 g(QL / 64, BB * NH);
        attn_kernel<<<g, 256, smem>>>(lengths);
    }
    // 5. output projection with slice/clip epilogue -> d_out
    {
        dim3 g(DD / 128, MROWS / 128);
        sgemm_kernel<512, 1><<<g, 256>>>(attn, w_out, b_out, out);
    }
}

// round 3
// speedup vs baseline: 3.2583x; 3.2583x over previous
#include <cuda_runtime.h>
#include <cstdint>

#define UQ   2048
#define BB   4
#define DD   512
#define QL   2176
#define KVL  2176
#define NH   8
#define DH   64
#define NEGINF (-100000000.0f)
#define MROWS (QL*BB)          // 8704
#define RCU_ROWS 2112
#define RCU_SZ (2112*4*512)
#define MASK_N (QL*KVL)

// -------------------- device scratch ----------------------------------------
__device__ float g_qin  [QL  * BB * DD];
__device__ float g_kvin [KVL * BB * DD];
__device__ float g_query[QL  * BB * DD];
__device__ float g_kv   [KVL * BB * 2 * DD];
__device__ float g_attn [QL  * BB * DD];
__device__ unsigned char g_mask[MASK_N];
__device__ int g_mask_kind;

// -------------------- tf32 helpers ------------------------------------------
__device__ __forceinline__ uint32_t f2tf(float x) {
    uint32_t r; asm("cvt.rna.tf32.f32 %0, %1;" : "=r"(r) : "f"(x)); return r;
}
__device__ __forceinline__ void mma8(float* c,
    uint32_t a0, uint32_t a1, uint32_t a2, uint32_t a3,
    uint32_t b0, uint32_t b1) {
    asm volatile(
        "mma.sync.aligned.m16n8k8.row.col.f32.tf32.tf32.f32 "
        "{%0,%1,%2,%3}, {%4,%5,%6,%7}, {%8,%9}, {%0,%1,%2,%3};\n"
        : "+f"(c[0]), "+f"(c[1]), "+f"(c[2]), "+f"(c[3])
        : "r"(a0), "r"(a1), "r"(a2), "r"(a3), "r"(b0), "r"(b1));
}

// -------------------- mask dtype sniff + normalize ---------------------------
__global__ void mask_sniff_kernel(const unsigned char* __restrict__ raw) {
    __shared__ int sh[3];
    int f_gt1_low = 0, f_gt1_high = 0, f_nz_off = 0;
    const int SCAN = 1 << 20;
    for (int i = threadIdx.x * 4; i < SCAN; i += blockDim.x * 4) {
        uchar4 v = *(const uchar4*)(raw + i);
        if (v.x > 1) f_gt1_low = 1;
        if (v.y > 1) f_gt1_low = 1;
        if (v.z > 1) f_gt1_high = 1;
        if (v.w > 1) f_gt1_high = 1;
        if (v.y | v.z | v.w) f_nz_off = 1;
    }
    if (threadIdx.x == 0) { sh[0] = 0; sh[1] = 0; sh[2] = 0; }
    __syncthreads();
    if (f_gt1_low)  atomicOr(&sh[0], 1);
    if (f_gt1_high) atomicOr(&sh[1], 1);
    if (f_nz_off)   atomicOr(&sh[2], 1);
    __syncthreads();
    if (threadIdx.x == 0) {
        int kind;
        if (sh[0])      kind = 3;
        else if (sh[1]) kind = 2;
        else if (sh[2]) kind = 0;
        else            kind = 1;
        g_mask_kind = kind;
    }
}

__global__ void mask_convert_kernel(const void* __restrict__ raw) {
    int kind = g_mask_kind;
    int i = blockIdx.x * blockDim.x + threadIdx.x;
    int stride = gridDim.x * blockDim.x;
    if (kind == 0) {
        const unsigned char* p = (const unsigned char*)raw;
        for (int e = i; e < MASK_N; e += stride) g_mask[e] = p[e] ? 1 : 0;
    } else if (kind == 1) {
        const int* p = (const int*)raw;
        for (int e = i; e < MASK_N; e += stride) g_mask[e] = p[e] ? 1 : 0;
    } else if (kind == 2) {
        const float* p = (const float*)raw;
        for (int e = i; e < MASK_N; e += stride) g_mask[e] = (p[e] != 0.f) ? 1 : 0;
    } else {
        const unsigned short* p = (const unsigned short*)raw;
        for (int e = i; e < MASK_N; e += stride)
            g_mask[e] = ((p[e] & 0x7fff) != 0) ? 1 : 0;
    }
}

// -------------------- gather -------------------------------------------------
__global__ void gather_kernel(const float* __restrict__ utt,
                              const float* __restrict__ rc,
                              const float* __restrict__ summ,
                              const float* __restrict__ mem) {
    const int VB = BB * DD / 4;
    const int total = QL * VB;
    int i = blockIdx.x * blockDim.x + threadIdx.x;
    if (i < total) {
        int q = i / VB, rem = i - q * VB;
        const float4* src; int sr;
        if (q < 64)        { src = (const float4*)rc;   sr = q; }
        else if (q < 2112) { src = (const float4*)utt;  sr = q - 64; }
        else               { src = (const float4*)summ; sr = q - 2112; }
        ((float4*)g_qin)[i] = src[(size_t)sr * VB + rem];
    } else if (i < 2 * total) {
        int j = i - total;
        int k = j / VB, rem = j - k * VB;
        const float4* src; int sr;
        if (k < 64)       { src = (const float4*)mem; sr = k; }
        else if (k < 128) { src = (const float4*)rc;  sr = k - 64; }
        else              { src = (const float4*)utt; sr = k - 128; }
        ((float4*)g_kvin)[j] = src[(size_t)sr * VB + rem];
    }
}

// -------------------- tf32 GEMM: C[M,N] = A[M,512] @ W[512,N] + bias ---------
// 128x128 block tile, BK=32, 256 threads = 8 warps (4 along M x 2 along N),
// warp tile 32x64 via m16n8k8 fragments. Pitches 36/132 -> conflict-free.
template<int NN, int MODE>
__global__ __launch_bounds__(256)
void tf32_gemm(const float* __restrict__ A, const float* __restrict__ W,
               const float* __restrict__ bias, float* __restrict__ C) {
    __shared__ uint32_t As[128 * 36];
    __shared__ uint32_t Bs[32 * 132];
    const int tid = threadIdx.x;
    const int wid = tid >> 5, lane = tid & 31;
    const int g = lane >> 2, tig = lane & 3;
    const int wm = wid & 3, wn = wid >> 2;
    const int m0 = blockIdx.y * 128, n0 = blockIdx.x * 128;

    float acc[2][8][4];
    #pragma unroll
    for (int mf = 0; mf < 2; mf++)
        #pragma unroll
        for (int nf = 0; nf < 8; nf++)
            #pragma unroll
            for (int e = 0; e < 4; e++) acc[mf][nf][e] = 0.f;

    for (int k0 = 0; k0 < 512; k0 += 32) {
        __syncthreads();
        #pragma unroll
        for (int l = 0; l < 4; l++) {
            int idx = tid + l * 256;
            int row = idx >> 3, c4 = (idx & 7) << 2;
            float4 v = *(const float4*)(A + (size_t)(m0 + row) * 512 + k0 + c4);
            uint32_t* d = As + row * 36 + c4;
            d[0] = f2tf(v.x); d[1] = f2tf(v.y); d[2] = f2tf(v.z); d[3] = f2tf(v.w);
        }
        #pragma unroll
        for (int l = 0; l < 4; l++) {
            int idx = tid + l * 256;
            int kr = idx >> 5, c4 = (idx & 31) << 2;
            float4 v = *(const float4*)(W + (size_t)(k0 + kr) * NN + n0 + c4);
            uint32_t* d = Bs + kr * 132 + c4;
            d[0] = f2tf(v.x); d[1] = f2tf(v.y); d[2] = f2tf(v.z); d[3] = f2tf(v.w);
        }
        __syncthreads();
        #pragma unroll
        for (int ks = 0; ks < 4; ks++) {
            uint32_t a[2][4];
            #pragma unroll
            for (int mf = 0; mf < 2; mf++) {
                const uint32_t* p = As + (wm * 32 + mf * 16 + g) * 36 + ks * 8 + tig;
                a[mf][0] = p[0];
                a[mf][1] = p[8 * 36];
                a[mf][2] = p[4];
                a[mf][3] = p[8 * 36 + 4];
            }
            #pragma unroll
            for (int nf = 0; nf < 8; nf++) {
                const uint32_t* p = Bs + (ks * 8 + tig) * 132 + wn * 64 + nf * 8 + g;
                uint32_t b0 = p[0], b1 = p[4 * 132];
                mma8(acc[0][nf], a[0][0], a[0][1], a[0][2], a[0][3], b0, b1);
                mma8(acc[1][nf], a[1][0], a[1][1], a[1][2], a[1][3], b0, b1);
            }
        }
    }

    #pragma unroll
    for (int mf = 0; mf < 2; mf++) {
        int row0 = m0 + wm * 32 + mf * 16 + g;
        int row1 = row0 + 8;
        #pragma unroll
        for (int nf = 0; nf < 8; nf++) {
            int col = n0 + wn * 64 + nf * 8 + 2 * tig;
            float bi0 = __ldg(bias + col), bi1 = __ldg(bias + col + 1);
            float v00 = acc[mf][nf][0] + bi0, v01 = acc[mf][nf][1] + bi1;
            float v10 = acc[mf][nf][2] + bi0, v11 = acc[mf][nf][3] + bi1;
            if (MODE == 0) {
                *(float2*)(C + (size_t)row0 * NN + col) = make_float2(v00, v01);
                *(float2*)(C + (size_t)row1 * NN + col) = make_float2(v10, v11);
            } else {
                int rows[2] = {row0, row1};
                float vs[2][2] = {{v00, v01}, {v10, v11}};
                #pragma unroll
                for (int r = 0; r < 2; r++) {
                    int m = rows[r];
                    int q = m >> 2, b = m & 3;
                    if (q < RCU_ROWS) {
                        *(float2*)(C + (size_t)m * DD + col) =
                            make_float2(vs[r][0], vs[r][1]);
                    } else if (q < QL - 1) {
                        float a0 = fminf(fmaxf(vs[r][0], -10.f), 10.f);
                        float a1 = fminf(fmaxf(vs[r][1], -10.f), 10.f);
                        *(float2*)(C + RCU_SZ +
                            (size_t)((q - RCU_ROWS) * BB + b) * DD + col) =
                            make_float2(a0, a1);
                    }
                }
            }
        }
    }
}

// -------------------- tf32 flash attention -----------------------------------
// Br=Bc=64, 4 warps, each warp owns 16 query rows (1 m-frag), 8 n-frags.
// smem pitch 68 -> bank-conflict-free fragment loads. P reuses the K region.
__global__ __launch_bounds__(128)
void attn_tf32(const int* __restrict__ lengths) {
    extern __shared__ uint32_t sm[];
    uint32_t* Qs = sm;
    uint32_t* Ks = sm + 64 * 68;   // reused as P
    uint32_t* Vs = sm + 2 * 64 * 68;

    const int tid = threadIdx.x;
    const int wid = tid >> 5, lane = tid & 31;
    const int g = lane >> 2, tig = lane & 3;
    const int b = blockIdx.y >> 3, h = blockIdx.y & 7;
    const int q0 = blockIdx.x * 64;
    const int wrow = wid * 16;
    const int limit = (KVL - UQ) + __ldg(lengths + b);
    const int qg0 = q0 + wrow + g;
    const int qg1 = qg0 + 8;

    // load + scale + tf32-convert Q tile
    #pragma unroll
    for (int l = 0; l < 8; l++) {
        int idx = tid + l * 128;
        int row = idx >> 4, c4 = (idx & 15) << 2;
        float4 v = *(const float4*)(g_query +
                    ((size_t)(q0 + row) * BB + b) * DD + h * DH + c4);
        uint32_t* d = Qs + row * 68 + c4;
        d[0] = f2tf(v.x * 0.125f); d[1] = f2tf(v.y * 0.125f);
        d[2] = f2tf(v.z * 0.125f); d[3] = f2tf(v.w * 0.125f);
    }

    float m_[2] = {-3.0e38f, -3.0e38f};
    float l_[2] = {0.f, 0.f};
    float o[8][4];
    #pragma unroll
    for (int nf = 0; nf < 8; nf++)
        #pragma unroll
        for (int e = 0; e < 4; e++) o[nf][e] = 0.f;

    for (int k0 = 0; k0 < KVL; k0 += 64) {
        __syncthreads();   // prior P reads complete
        #pragma unroll
        for (int l = 0; l < 8; l++) {
            int idx = tid + l * 128;
            int row = idx >> 4, c4 = (idx & 15) << 2;
            size_t base = ((size_t)(k0 + row) * BB + b) * (2 * DD) + h * DH + c4;
            float4 kv = *(const float4*)(g_kv + base);
            float4 vv = *(const float4*)(g_kv + base + DD);
            uint32_t* dk = Ks + row * 68 + c4;
            dk[0] = f2tf(kv.x); dk[1] = f2tf(kv.y);
            dk[2] = f2tf(kv.z); dk[3] = f2tf(kv.w);
            uint32_t* dv = Vs + row * 68 + c4;
            dv[0] = f2tf(vv.x); dv[1] = f2tf(vv.y);
            dv[2] = f2tf(vv.z); dv[3] = f2tf(vv.w);
        }
        __syncthreads();

        // S = Q @ K^T
        float s[8][4];
        #pragma unroll
        for (int nf = 0; nf < 8; nf++)
            #pragma unroll
            for (int e = 0; e < 4; e++) s[nf][e] = 0.f;
        #pragma unroll
        for (int ks = 0; ks < 8; ks++) {
            const uint32_t* pa = Qs + (wrow + g) * 68 + ks * 8 + tig;
            uint32_t a0 = pa[0], a1 = pa[8 * 68], a2 = pa[4], a3 = pa[8 * 68 + 4];
            #pragma unroll
            for (int nf = 0; nf < 8; nf++) {
                const uint32_t* pb = Ks + (nf * 8 + g) * 68 + ks * 8 + tig;
                mma8(s[nf], a0, a1, a2, a3, pb[0], pb[4]);
            }
        }

        // mask (1 = masked) + length padding
        #pragma unroll
        for (int nf = 0; nf < 8; nf++) {
            int cg = k0 + nf * 8 + 2 * tig;
            uchar2 mv0 = *(const uchar2*)(g_mask + (size_t)qg0 * KVL + cg);
            uchar2 mv1 = *(const uchar2*)(g_mask + (size_t)qg1 * KVL + cg);
            if (mv0.x || cg     >= limit) s[nf][0] = NEGINF;
            if (mv0.y || cg + 1 >= limit) s[nf][1] = NEGINF;
            if (mv1.x || cg     >= limit) s[nf][2] = NEGINF;
            if (mv1.y || cg + 1 >= limit) s[nf][3] = NEGINF;
        }

        // online softmax (2 rows per thread, reduce over 4-lane group)
        float tm0 = -3.0e38f, tm1 = -3.0e38f;
        #pragma unroll
        for (int nf = 0; nf < 8; nf++) {
            tm0 = fmaxf(tm0, fmaxf(s[nf][0], s[nf][1]));
            tm1 = fmaxf(tm1, fmaxf(s[nf][2], s[nf][3]));
        }
        tm0 = fmaxf(tm0, __shfl_xor_sync(0xffffffffu, tm0, 1));
        tm0 = fmaxf(tm0, __shfl_xor_sync(0xffffffffu, tm0, 2));
        tm1 = fmaxf(tm1, __shfl_xor_sync(0xffffffffu, tm1, 1));
        tm1 = fmaxf(tm1, __shfl_xor_sync(0xffffffffu, tm1, 2));
        float mn0 = fmaxf(m_[0], tm0), mn1 = fmaxf(m_[1], tm1);
        float corr0 = __expf(m_[0] - mn0), corr1 = __expf(m_[1] - mn1);
        float ps0 = 0.f, ps1 = 0.f;
        #pragma unroll
        for (int nf = 0; nf < 8; nf++) {
            s[nf][0] = __expf(s[nf][0] - mn0);
            s[nf][1] = __expf(s[nf][1] - mn0);
            s[nf][2] = __expf(s[nf][2] - mn1);
            s[nf][3] = __expf(s[nf][3] - mn1);
            ps0 += s[nf][0] + s[nf][1];
            ps1 += s[nf][2] + s[nf][3];
        }
        ps0 += __shfl_xor_sync(0xffffffffu, ps0, 1);
        ps0 += __shfl_xor_sync(0xffffffffu, ps0, 2);
        ps1 += __shfl_xor_sync(0xffffffffu, ps1, 1);
        ps1 += __shfl_xor_sync(0xffffffffu, ps1, 2);
        l_[0] = l_[0] * corr0 + ps0; m_[0] = mn0;
        l_[1] = l_[1] * corr1 + ps1; m_[1] = mn1;
        #pragma unroll
        for (int nf = 0; nf < 8; nf++) {
            o[nf][0] *= corr0; o[nf][1] *= corr0;
            o[nf][2] *= corr1; o[nf][3] *= corr1;
        }

        __syncthreads();   // all warps done reading Ks
        // store P (tf32) into Ks region
        #pragma unroll
        for (int nf = 0; nf < 8; nf++) {
            int cl = nf * 8 + 2 * tig;
            uint32_t* p0 = Ks + (wrow + g) * 68 + cl;
            p0[0] = f2tf(s[nf][0]); p0[1] = f2tf(s[nf][1]);
            uint32_t* p1 = Ks + (wrow + g + 8) * 68 + cl;
            p1[0] = f2tf(s[nf][2]); p1[1] = f2tf(s[nf][3]);
        }
        __syncthreads();

        // O += P @ V
        #pragma unroll
        for (int ks = 0; ks < 8; ks++) {
            const uint32_t* pa = Ks + (wrow + g) * 68 + ks * 8 + tig;
            uint32_t a0 = pa[0], a1 = pa[8 * 68], a2 = pa[4], a3 = pa[8 * 68 + 4];
            #pragma unroll
            for (int nf = 0; nf < 8; nf++) {
                const uint32_t* pb = Vs + (ks * 8 + tig) * 68 + nf * 8 + g;
                mma8(o[nf], a0, a1, a2, a3, pb[0], pb[4 * 68]);
            }
        }
    }

    float inv0 = 1.0f / l_[0], inv1 = 1.0f / l_[1];
    #pragma unroll
    for (int nf = 0; nf < 8; nf++) {
        int col = h * DH + nf * 8 + 2 * tig;
        *(float2*)(g_attn + ((size_t)qg0 * BB + b) * DD + col) =
            make_float2(o[nf][0] * inv0, o[nf][1] * inv0);
        *(float2*)(g_attn + ((size_t)qg1 * BB + b) * DD + col) =
            make_float2(o[nf][2] * inv1, o[nf][3] * inv1);
    }
}

// -------------------- launch ------------------------------------------------
extern "C" void kernel_launch(void* const* d_in, const int* in_sizes, int n_in,
                              void* d_out, int out_size) {
    const float* utt      = (const float*)d_in[0];
    const int*   lengths  = (const int*)d_in[1];
    const float* rc       = (const float*)d_in[2];
    const float* summ     = (const float*)d_in[3];
    const float* mem      = (const float*)d_in[4];
    const void*  mask_raw = (const void*)d_in[5];
    const float* w_q   = (const float*)d_in[6];
    const float* b_q   = (const float*)d_in[7];
    const float* w_kv  = (const float*)d_in[8];
    const float* b_kv  = (const float*)d_in[9];
    const float* w_out = (const float*)d_in[10];
    const float* b_out = (const float*)d_in[11];
    float* out = (float*)d_out;

    void *p;
    cudaGetSymbolAddress(&p, g_qin);   float* qin   = (float*)p;
    cudaGetSymbolAddress(&p, g_kvin);  float* kvin  = (float*)p;
    cudaGetSymbolAddress(&p, g_query); float* query = (float*)p;
    cudaGetSymbolAddress(&p, g_kv);    float* kvbuf = (float*)p;
    cudaGetSymbolAddress(&p, g_attn);  float* attn  = (float*)p;

    // 0. mask dtype sniff + normalize
    mask_sniff_kernel<<<1, 1024>>>((const unsigned char*)mask_raw);
    mask_convert_kernel<<<512, 256>>>(mask_raw);

    // 1. gather
    {
        int totalv = 2 * QL * (BB * DD / 4);
        gather_kernel<<<(totalv + 255) / 256, 256>>>(utt, rc, summ, mem);
    }
    // 2. Q projection (8704 x 512)
    {
        dim3 g(DD / 128, MROWS / 128);
        tf32_gemm<512, 0><<<g, 256>>>(qin, w_q, b_q, query);
    }
    // 3. KV projection (8704 x 1024)
    {
        dim3 g(1024 / 128, MROWS / 128);
        tf32_gemm<1024, 0><<<g, 256>>>(kvin, w_kv, b_kv, kvbuf);
    }
    // 4. attention (tf32 mma flash)
    {
        const int smem = 3 * 64 * 68 * 4;   // 52224 B
        cudaFuncSetAttribute(attn_tf32,
                             cudaFuncAttributeMaxDynamicSharedMemorySize, smem);
        dim3 g(QL / 64, BB * NH);
        attn_tf32<<<g, 128, smem>>>(lengths);
    }
    // 5. output projection + slice/clip epilogue
    {
        dim3 g(DD / 128, MROWS / 128);
        tf32_gemm<512, 1><<<g, 256>>>(attn, w_out, b_out, out);
    }
}

// round 4
// speedup vs baseline: 5.0832x; 1.5601x over previous
#include <cuda_runtime.h>
#include <cuda_fp16.h>
#include <cstdint>

#define UQ   2048
#define BB   4
#define DD   512
#define QL   2176
#define KVL  2176
#define NH   8
#define DH   64
#define NEGINF (-100000000.0f)
#define MROWS (QL*BB)          // 8704
#define RCU_ROWS 2112
#define RCU_SZ (2112*4*512)
#define MASK_N (QL*KVL)
#define QSCALE (0.125f * 1.44269504088896f)   // dh^-0.5 * log2(e)

// -------------------- device scratch ----------------------------------------
__device__ float  g_qin [QL  * BB * DD];
__device__ float  g_kvin[KVL * BB * DD];
__device__ float  g_attn[QL  * BB * DD];
__device__ __half g_q16 [MROWS * DD];     // pre-scaled by QSCALE
__device__ __half g_k16 [MROWS * DD];
__device__ __half g_v16 [MROWS * DD];     // k-pair interleaved: [((k>>1)*4+b)*512+c]*2+(k&1)
__device__ unsigned char g_mask[MASK_N];
__device__ int g_mask_kind;

// -------------------- helpers ------------------------------------------------
__device__ __forceinline__ uint32_t f2tf(float x) {
    uint32_t r; asm("cvt.rna.tf32.f32 %0, %1;" : "=r"(r) : "f"(x)); return r;
}
__device__ __forceinline__ void mma8(float* c,
    uint32_t a0, uint32_t a1, uint32_t a2, uint32_t a3,
    uint32_t b0, uint32_t b1) {
    asm volatile(
        "mma.sync.aligned.m16n8k8.row.col.f32.tf32.tf32.f32 "
        "{%0,%1,%2,%3}, {%4,%5,%6,%7}, {%8,%9}, {%0,%1,%2,%3};\n"
        : "+f"(c[0]), "+f"(c[1]), "+f"(c[2]), "+f"(c[3])
        : "r"(a0), "r"(a1), "r"(a2), "r"(a3), "r"(b0), "r"(b1));
}
__device__ __forceinline__ void hmma(float* c,
    uint32_t a0, uint32_t a1, uint32_t a2, uint32_t a3,
    uint32_t b0, uint32_t b1) {
    asm volatile(
        "mma.sync.aligned.m16n8k16.row.col.f32.f16.f16.f32 "
        "{%0,%1,%2,%3}, {%4,%5,%6,%7}, {%8,%9}, {%0,%1,%2,%3};\n"
        : "+f"(c[0]), "+f"(c[1]), "+f"(c[2]), "+f"(c[3])
        : "r"(a0), "r"(a1), "r"(a2), "r"(a3), "r"(b0), "r"(b1));
}
__device__ __forceinline__ uint32_t packh2(float lo, float hi) {
    uint32_t r; asm("cvt.rn.f16x2.f32 %0, %1, %2;" : "=r"(r) : "f"(hi), "f"(lo));
    return r;
}
__device__ __forceinline__ float ex2(float x) {
    float r; asm("ex2.approx.f32 %0, %1;" : "=f"(r) : "f"(x)); return r;
}
__device__ __forceinline__ uint32_t s2u(const void* p) {
    return (uint32_t)__cvta_generic_to_shared(p);
}
#define CP16(dst, src) \
    asm volatile("cp.async.cg.shared.global [%0], [%1], 16;\n" :: "r"(dst), "l"(src))
#define CP_COMMIT() asm volatile("cp.async.commit_group;\n")

// -------------------- mask dtype sniff + normalize ---------------------------
__global__ void mask_sniff_kernel(const unsigned char* __restrict__ raw) {
    __shared__ int sh[3];
    int f_gt1_low = 0, f_gt1_high = 0, f_nz_off = 0;
    const int SCAN = 1 << 20;
    for (int i = threadIdx.x * 4; i < SCAN; i += blockDim.x * 4) {
        uchar4 v = *(const uchar4*)(raw + i);
        if (v.x > 1) f_gt1_low = 1;
        if (v.y > 1) f_gt1_low = 1;
        if (v.z > 1) f_gt1_high = 1;
        if (v.w > 1) f_gt1_high = 1;
        if (v.y | v.z | v.w) f_nz_off = 1;
    }
    if (threadIdx.x == 0) { sh[0] = 0; sh[1] = 0; sh[2] = 0; }
    __syncthreads();
    if (f_gt1_low)  atomicOr(&sh[0], 1);
    if (f_gt1_high) atomicOr(&sh[1], 1);
    if (f_nz_off)   atomicOr(&sh[2], 1);
    __syncthreads();
    if (threadIdx.x == 0) {
        int kind;
        if (sh[0])      kind = 3;
        else if (sh[1]) kind = 2;
        else if (sh[2]) kind = 0;
        else            kind = 1;
        g_mask_kind = kind;
    }
}

__global__ void mask_convert_kernel(const void* __restrict__ raw) {
    int kind = g_mask_kind;
    int i = blockIdx.x * blockDim.x + threadIdx.x;
    int stride = gridDim.x * blockDim.x;
    if (kind == 0) {
        const unsigned char* p = (const unsigned char*)raw;
        for (int e = i; e < MASK_N; e += stride) g_mask[e] = p[e] ? 1 : 0;
    } else if (kind == 1) {
        const int* p = (const int*)raw;
        for (int e = i; e < MASK_N; e += stride) g_mask[e] = p[e] ? 1 : 0;
    } else if (kind == 2) {
        const float* p = (const float*)raw;
        for (int e = i; e < MASK_N; e += stride) g_mask[e] = (p[e] != 0.f) ? 1 : 0;
    } else {
        const unsigned short* p = (const unsigned short*)raw;
        for (int e = i; e < MASK_N; e += stride)
            g_mask[e] = ((p[e] & 0x7fff) != 0) ? 1 : 0;
    }
}

// -------------------- gather -------------------------------------------------
__global__ void gather_kernel(const float* __restrict__ utt,
                              const float* __restrict__ rc,
                              const float* __restrict__ summ,
                              const float* __restrict__ mem) {
    const int VB = BB * DD / 4;
    const int total = QL * VB;
    int i = blockIdx.x * blockDim.x + threadIdx.x;
    if (i < total) {
        int q = i / VB, rem = i - q * VB;
        const float4* src; int sr;
        if (q < 64)        { src = (const float4*)rc;   sr = q; }
        else if (q < 2112) { src = (const float4*)utt;  sr = q - 64; }
        else               { src = (const float4*)summ; sr = q - 2112; }
        ((float4*)g_qin)[i] = src[(size_t)sr * VB + rem];
    } else if (i < 2 * total) {
        int j = i - total;
        int k = j / VB, rem = j - k * VB;
        const float4* src; int sr;
        if (k < 64)       { src = (const float4*)mem; sr = k; }
        else if (k < 128) { src = (const float4*)rc;  sr = k - 64; }
        else              { src = (const float4*)utt; sr = k - 128; }
        ((float4*)g_kvin)[j] = src[(size_t)sr * VB + rem];
    }
}

// -------------------- tf32 GEMM ----------------------------------------------
// MODE 0: fp32 store   MODE 1: out-proj scatter (slice/clip)
// MODE 2: Q epilogue -> g_q16 (fp16, scaled by QSCALE)
// MODE 3: KV epilogue -> g_k16 (cols<512) / g_v16 pair-interleaved (cols>=512)
template<int NN, int MODE>
__global__ __launch_bounds__(256)
void tf32_gemm(const float* __restrict__ A, const float* __restrict__ W,
               const float* __restrict__ bias, float* __restrict__ C) {
    __shared__ uint32_t As[128 * 36];
    __shared__ uint32_t Bs[32 * 132];
    const int tid = threadIdx.x;
    const int wid = tid >> 5, lane = tid & 31;
    const int g = lane >> 2, tig = lane & 3;
    const int wm = wid & 3, wn = wid >> 2;
    const int m0 = blockIdx.y * 128, n0 = blockIdx.x * 128;

    float acc[2][8][4];
    #pragma unroll
    for (int mf = 0; mf < 2; mf++)
        #pragma unroll
        for (int nf = 0; nf < 8; nf++)
            #pragma unroll
            for (int e = 0; e < 4; e++) acc[mf][nf][e] = 0.f;

    for (int k0 = 0; k0 < 512; k0 += 32) {
        __syncthreads();
        #pragma unroll
        for (int l = 0; l < 4; l++) {
            int idx = tid + l * 256;
            int row = idx >> 3, c4 = (idx & 7) << 2;
            float4 v = *(const float4*)(A + (size_t)(m0 + row) * 512 + k0 + c4);
            uint32_t* d = As + row * 36 + c4;
            d[0] = f2tf(v.x); d[1] = f2tf(v.y); d[2] = f2tf(v.z); d[3] = f2tf(v.w);
        }
        #pragma unroll
        for (int l = 0; l < 4; l++) {
            int idx = tid + l * 256;
            int kr = idx >> 5, c4 = (idx & 31) << 2;
            float4 v = *(const float4*)(W + (size_t)(k0 + kr) * NN + n0 + c4);
            uint32_t* d = Bs + kr * 132 + c4;
            d[0] = f2tf(v.x); d[1] = f2tf(v.y); d[2] = f2tf(v.z); d[3] = f2tf(v.w);
        }
        __syncthreads();
        #pragma unroll
        for (int ks = 0; ks < 4; ks++) {
            uint32_t a[2][4];
            #pragma unroll
            for (int mf = 0; mf < 2; mf++) {
                const uint32_t* p = As + (wm * 32 + mf * 16 + g) * 36 + ks * 8 + tig;
                a[mf][0] = p[0];
                a[mf][1] = p[8 * 36];
                a[mf][2] = p[4];
                a[mf][3] = p[8 * 36 + 4];
            }
            #pragma unroll
            for (int nf = 0; nf < 8; nf++) {
                const uint32_t* p = Bs + (ks * 8 + tig) * 132 + wn * 64 + nf * 8 + g;
                uint32_t b0 = p[0], b1 = p[4 * 132];
                mma8(acc[0][nf], a[0][0], a[0][1], a[0][2], a[0][3], b0, b1);
                mma8(acc[1][nf], a[1][0], a[1][1], a[1][2], a[1][3], b0, b1);
            }
        }
    }

    #pragma unroll
    for (int mf = 0; mf < 2; mf++) {
        int row0 = m0 + wm * 32 + mf * 16 + g;
        int row1 = row0 + 8;
        #pragma unroll
        for (int nf = 0; nf < 8; nf++) {
            int col = n0 + wn * 64 + nf * 8 + 2 * tig;
            float bi0 = __ldg(bias + col), bi1 = __ldg(bias + col + 1);
            float v00 = acc[mf][nf][0] + bi0, v01 = acc[mf][nf][1] + bi1;
            float v10 = acc[mf][nf][2] + bi0, v11 = acc[mf][nf][3] + bi1;
            if (MODE == 0) {
                *(float2*)(C + (size_t)row0 * NN + col) = make_float2(v00, v01);
                *(float2*)(C + (size_t)row1 * NN + col) = make_float2(v10, v11);
            } else if (MODE == 1) {
                int rows[2] = {row0, row1};
                float vs[2][2] = {{v00, v01}, {v10, v11}};
                #pragma unroll
                for (int r = 0; r < 2; r++) {
                    int m = rows[r];
                    int q = m >> 2, b = m & 3;
                    if (q < RCU_ROWS) {
                        *(float2*)(C + (size_t)m * DD + col) =
                            make_float2(vs[r][0], vs[r][1]);
                    } else if (q < QL - 1) {
                        float a0 = fminf(fmaxf(vs[r][0], -10.f), 10.f);
                        float a1 = fminf(fmaxf(vs[r][1], -10.f), 10.f);
                        *(float2*)(C + RCU_SZ +
                            (size_t)((q - RCU_ROWS) * BB + b) * DD + col) =
                            make_float2(a0, a1);
                    }
                }
            } else if (MODE == 2) {
                *(__half2*)(&g_q16[(size_t)row0 * DD + col]) =
                    __floats2half2_rn(v00 * QSCALE, v01 * QSCALE);
                *(__half2*)(&g_q16[(size_t)row1 * DD + col]) =
                    __floats2half2_rn(v10 * QSCALE, v11 * QSCALE);
            } else {   // MODE 3
                if (col < 512) {
                    *(__half2*)(&g_k16[(size_t)row0 * DD + col]) =
                        __floats2half2_rn(v00, v01);
                    *(__half2*)(&g_k16[(size_t)row1 * DD + col]) =
                        __floats2half2_rn(v10, v11);
                } else {
                    int vc = col - 512;
                    int rows[2] = {row0, row1};
                    float vs[2][2] = {{v00, v01}, {v10, v11}};
                    #pragma unroll
                    for (int r = 0; r < 2; r++) {
                        int k = rows[r] >> 2, b = rows[r] & 3;
                        size_t base = (((size_t)(k >> 1) * BB + b) * DD + vc) * 2 + (k & 1);
                        g_v16[base]     = __float2half_rn(vs[r][0]);
                        g_v16[base + 2] = __float2half_rn(vs[r][1]);
                    }
                }
            }
        }
    }
}

// -------------------- fp16 flash attention -----------------------------------
// Br=128, Bc=64, 256 threads (8 warps x 16 rows). cp.async double-buffered K/V.
// smem (uint32 units): Qs[128*36] | stage0: Ks[64*36]+Vs[32*72] | stage1 same.
// P stays in registers (S C-frag == PV A-frag for fp16 m16n8k16).
__global__ __launch_bounds__(256)
void attn_h16(const int* __restrict__ lengths) {
    extern __shared__ uint32_t sm[];
    uint32_t* Qs = sm;

    const int tid = threadIdx.x;
    const int wid = tid >> 5, lane = tid & 31;
    const int g = lane >> 2, tig = lane & 3;
    const int b = blockIdx.y >> 3, h = blockIdx.y & 7;
    const int q0 = blockIdx.x * 128;
    const int wrow = wid * 16;
    const int limit = 128 + __ldg(lengths + b);
    const int qg0 = q0 + wrow + g;
    const int qg1 = qg0 + 8;

    // issue Q loads (fp16, pre-scaled)
    #pragma unroll
    for (int l = 0; l < 4; l++) {
        int item = tid + l * 256;
        int row = item >> 3, c = item & 7;
        const __half* src = g_q16 + ((size_t)(q0 + row) * BB + b) * DD + h * DH + c * 8;
        CP16(s2u(Qs + row * 36 + c * 4), src);
    }
    // issue K/V tile 0
    {
        uint32_t* Ks = sm + 4608;
        uint32_t* Vs = Ks + 2304;
        #pragma unroll
        for (int l = 0; l < 2; l++) {
            int item = tid + l * 256;
            int row = item >> 3, c = item & 7;
            const __half* src = g_k16 + ((size_t)row * BB + b) * DD + h * DH + c * 8;
            CP16(s2u(Ks + row * 36 + c * 4), src);
        }
        #pragma unroll
        for (int l = 0; l < 2; l++) {
            int item = tid + l * 256;
            int row = item >> 4, c = item & 15;
            const __half* src = g_v16 + (((size_t)row * BB + b) * DD + h * DH + c * 4) * 2;
            CP16(s2u(Vs + row * 72 + c * 4), src);
        }
    }
    CP_COMMIT();

    float m_[2] = {-3.0e38f, -3.0e38f};
    float l_[2] = {0.f, 0.f};
    float o[8][4];
    #pragma unroll
    for (int nf = 0; nf < 8; nf++)
        #pragma unroll
        for (int e = 0; e < 4; e++) o[nf][e] = 0.f;

    const int NT = KVL / 64;   // 34
    for (int t = 0; t < NT; t++) {
        if (t + 1 < NT) {
            int k0 = (t + 1) * 64;
            uint32_t* Ks = sm + 4608 + ((t + 1) & 1) * 4608;
            uint32_t* Vs = Ks + 2304;
            #pragma unroll
            for (int l = 0; l < 2; l++) {
                int item = tid + l * 256;
                int row = item >> 3, c = item & 7;
                const __half* src = g_k16 + ((size_t)(k0 + row) * BB + b) * DD + h * DH + c * 8;
                CP16(s2u(Ks + row * 36 + c * 4), src);
            }
            int p0 = k0 >> 1;
            #pragma unroll
            for (int l = 0; l < 2; l++) {
                int item = tid + l * 256;
                int row = item >> 4, c = item & 15;
                const __half* src = g_v16 + (((size_t)(p0 + row) * BB + b) * DD + h * DH + c * 4) * 2;
                CP16(s2u(Vs + row * 72 + c * 4), src);
            }
            CP_COMMIT();
            asm volatile("cp.async.wait_group 1;\n");
        } else {
            asm volatile("cp.async.wait_group 0;\n");
        }
        __syncthreads();

        uint32_t* Ks = sm + 4608 + (t & 1) * 4608;
        uint32_t* Vs = Ks + 2304;

        // S = Q @ K^T  (fp16 m16n8k16, fp32 accum)
        float s[8][4];
        #pragma unroll
        for (int nf = 0; nf < 8; nf++)
            #pragma unroll
            for (int e = 0; e < 4; e++) s[nf][e] = 0.f;
        #pragma unroll
        for (int kc = 0; kc < 4; kc++) {
            const uint32_t* pa = Qs + (wrow + g) * 36 + kc * 8 + tig;
            uint32_t a0 = pa[0], a1 = pa[8 * 36], a2 = pa[4], a3 = pa[8 * 36 + 4];
            #pragma unroll
            for (int nf = 0; nf < 8; nf++) {
                const uint32_t* pb = Ks + (nf * 8 + g) * 36 + kc * 8 + tig;
                hmma(s[nf], a0, a1, a2, a3, pb[0], pb[4]);
            }
        }

        // mask (1 = masked) + length padding
        int kbase = t * 64;
        #pragma unroll
        for (int nf = 0; nf < 8; nf++) {
            int cg = kbase + nf * 8 + 2 * tig;
            uchar2 mv0 = *(const uchar2*)(g_mask + (size_t)qg0 * KVL + cg);
            uchar2 mv1 = *(const uchar2*)(g_mask + (size_t)qg1 * KVL + cg);
            if (mv0.x || cg     >= limit) s[nf][0] = NEGINF;
            if (mv0.y || cg + 1 >= limit) s[nf][1] = NEGINF;
            if (mv1.x || cg     >= limit) s[nf][2] = NEGINF;
            if (mv1.y || cg + 1 >= limit) s[nf][3] = NEGINF;
        }

        // online softmax in log2 domain (Q pre-scaled by log2(e))
        float tm0 = -3.0e38f, tm1 = -3.0e38f;
        #pragma unroll
        for (int nf = 0; nf < 8; nf++) {
            tm0 = fmaxf(tm0, fmaxf(s[nf][0], s[nf][1]));
            tm1 = fmaxf(tm1, fmaxf(s[nf][2], s[nf][3]));
        }
        tm0 = fmaxf(tm0, __shfl_xor_sync(0xffffffffu, tm0, 1));
        tm0 = fmaxf(tm0, __shfl_xor_sync(0xffffffffu, tm0, 2));
        tm1 = fmaxf(tm1, __shfl_xor_sync(0xffffffffu, tm1, 1));
        tm1 = fmaxf(tm1, __shfl_xor_sync(0xffffffffu, tm1, 2));
        float mn0 = fmaxf(m_[0], tm0), mn1 = fmaxf(m_[1], tm1);
        float corr0 = ex2(m_[0] - mn0), corr1 = ex2(m_[1] - mn1);
        float ps0 = 0.f, ps1 = 0.f;
        #pragma unroll
        for (int nf = 0; nf < 8; nf++) {
            s[nf][0] = ex2(s[nf][0] - mn0);
            s[nf][1] = ex2(s[nf][1] - mn0);
            s[nf][2] = ex2(s[nf][2] - mn1);
            s[nf][3] = ex2(s[nf][3] - mn1);
            ps0 += s[nf][0] + s[nf][1];
            ps1 += s[nf][2] + s[nf][3];
        }
        ps0 += __shfl_xor_sync(0xffffffffu, ps0, 1);
        ps0 += __shfl_xor_sync(0xffffffffu, ps0, 2);
        ps1 += __shfl_xor_sync(0xffffffffu, ps1, 1);
        ps1 += __shfl_xor_sync(0xffffffffu, ps1, 2);
        l_[0] = l_[0] * corr0 + ps0; m_[0] = mn0;
        l_[1] = l_[1] * corr1 + ps1; m_[1] = mn1;
        #pragma unroll
        for (int nf = 0; nf < 8; nf++) {
            o[nf][0] *= corr0; o[nf][1] *= corr0;
            o[nf][2] *= corr1; o[nf][3] *= corr1;
        }

        // O += P @ V   (P: C-frag -> fp16 A-frag, no smem roundtrip)
        #pragma unroll
        for (int kc = 0; kc < 4; kc++) {
            uint32_t pa0 = packh2(s[2 * kc][0],     s[2 * kc][1]);
            uint32_t pa1 = packh2(s[2 * kc][2],     s[2 * kc][3]);
            uint32_t pa2 = packh2(s[2 * kc + 1][0], s[2 * kc + 1][1]);
            uint32_t pa3 = packh2(s[2 * kc + 1][2], s[2 * kc + 1][3]);
            #pragma unroll
            for (int nf = 0; nf < 8; nf++) {
                const uint32_t* pb = Vs + (kc * 8 + tig) * 72 + nf * 8 + g;
                hmma(o[nf], pa0, pa1, pa2, pa3, pb[0], pb[4 * 72]);
            }
        }
        __syncthreads();   // all warps done with this stage before reload
    }

    float inv0 = 1.0f / l_[0], inv1 = 1.0f / l_[1];
    #pragma unroll
    for (int nf = 0; nf < 8; nf++) {
        int col = h * DH + nf * 8 + 2 * tig;
        *(float2*)(g_attn + ((size_t)qg0 * BB + b) * DD + col) =
            make_float2(o[nf][0] * inv0, o[nf][1] * inv0);
        *(float2*)(g_attn + ((size_t)qg1 * BB + b) * DD + col) =
            make_float2(o[nf][2] * inv1, o[nf][3] * inv1);
    }
}

// -------------------- launch ------------------------------------------------
extern "C" void kernel_launch(void* const* d_in, const int* in_sizes, int n_in,
                              void* d_out, int out_size) {
    const float* utt      = (const float*)d_in[0];
    const int*   lengths  = (const int*)d_in[1];
    const float* rc       = (const float*)d_in[2];
    const float* summ     = (const float*)d_in[3];
    const float* mem      = (const float*)d_in[4];
    const void*  mask_raw = (const void*)d_in[5];
    const float* w_q   = (const float*)d_in[6];
    const float* b_q   = (const float*)d_in[7];
    const float* w_kv  = (const float*)d_in[8];
    const float* b_kv  = (const float*)d_in[9];
    const float* w_out = (const float*)d_in[10];
    const float* b_out = (const float*)d_in[11];
    float* out = (float*)d_out;

    void *p;
    cudaGetSymbolAddress(&p, g_qin);  float* qin  = (float*)p;
    cudaGetSymbolAddress(&p, g_kvin); float* kvin = (float*)p;
    cudaGetSymbolAddress(&p, g_attn); float* attn = (float*)p;

    // 0. mask dtype sniff + normalize
    mask_sniff_kernel<<<1, 1024>>>((const unsigned char*)mask_raw);
    mask_convert_kernel<<<512, 256>>>(mask_raw);

    // 1. gather
    {
        int totalv = 2 * QL * (BB * DD / 4);
        gather_kernel<<<(totalv + 255) / 256, 256>>>(utt, rc, summ, mem);
    }
    // 2. Q projection -> g_q16 (fp16, scaled)
    {
        dim3 g(DD / 128, MROWS / 128);
        tf32_gemm<512, 2><<<g, 256>>>(qin, w_q, b_q, nullptr);
    }
    // 3. KV projection -> g_k16 / g_v16 (fp16)
    {
        dim3 g(1024 / 128, MROWS / 128);
        tf32_gemm<1024, 3><<<g, 256>>>(kvin, w_kv, b_kv, nullptr);
    }
    // 4. fp16 flash attention
    {
        const int smem = 13824 * 4;   // 55296 B
        cudaFuncSetAttribute(attn_h16,
                             cudaFuncAttributeMaxDynamicSharedMemorySize, smem);
        dim3 g(QL / 128, BB * NH);
        attn_h16<<<g, 256, smem>>>(lengths);
    }
    // 5. output projection + slice/clip epilogue
    {
        dim3 g(DD / 128, MROWS / 128);
        tf32_gemm<512, 1><<<g, 256>>>(attn, w_out, b_out, out);
    }
}

// round 5
// speedup vs baseline: 7.0965x; 1.3961x over previous
#include <cuda_runtime.h>
#include <cuda_fp16.h>
#include <cstdint>

#define UQ   2048
#define BB   4
#define DD   512
#define QL   2176
#define KVL  2176
#define NH   8
#define DH   64
#define NEGINF (-100000000.0f)
#define MROWS (QL*BB)          // 8704
#define RCU_ROWS 2112
#define RCU_SZ (2112*4*512)
#define MASK_N (QL*KVL)
#define QSCALE (0.125f * 1.44269504088896f)   // dh^-0.5 * log2(e)

// -------------------- device scratch ----------------------------------------
__device__ __half g_qin16 [MROWS * DD];   // gathered q_in, fp16
__device__ __half g_kvin16[MROWS * DD];   // gathered kv_in, fp16
__device__ __half g_q16   [MROWS * DD];   // Q-proj result, pre-scaled
__device__ __half g_k16   [MROWS * DD];
__device__ __half g_v16   [MROWS * DD];   // k-pair interleaved
__device__ __half g_attn16[MROWS * DD];
__device__ __half g_wqt [512 * 512];      // W^T fp16
__device__ __half g_wkvt[1024 * 512];
__device__ __half g_wot [512 * 512];
__device__ unsigned char g_mask[MASK_N];
__device__ int g_flags[3];

// -------------------- helpers ------------------------------------------------
__device__ __forceinline__ void hmma(float* c,
    uint32_t a0, uint32_t a1, uint32_t a2, uint32_t a3,
    uint32_t b0, uint32_t b1) {
    asm volatile(
        "mma.sync.aligned.m16n8k16.row.col.f32.f16.f16.f32 "
        "{%0,%1,%2,%3}, {%4,%5,%6,%7}, {%8,%9}, {%0,%1,%2,%3};\n"
        : "+f"(c[0]), "+f"(c[1]), "+f"(c[2]), "+f"(c[3])
        : "r"(a0), "r"(a1), "r"(a2), "r"(a3), "r"(b0), "r"(b1));
}
__device__ __forceinline__ uint32_t packh2(float lo, float hi) {
    uint32_t r; asm("cvt.rn.f16x2.f32 %0, %1, %2;" : "=r"(r) : "f"(hi), "f"(lo));
    return r;
}
__device__ __forceinline__ float ex2(float x) {
    float r; asm("ex2.approx.f32 %0, %1;" : "=f"(r) : "f"(x)); return r;
}
__device__ __forceinline__ uint32_t s2u(const void* p) {
    return (uint32_t)__cvta_generic_to_shared(p);
}
#define CP16(dst, src) \
    asm volatile("cp.async.cg.shared.global [%0], [%1], 16;\n" :: "r"(dst), "l"(src))
#define CP_COMMIT() asm volatile("cp.async.commit_group;\n")

// -------------------- mask prep ----------------------------------------------
__global__ void flags_reset() { g_flags[0] = 0; g_flags[1] = 0; g_flags[2] = 0; }

__global__ void mask_sniff(const unsigned char* __restrict__ raw) {
    int f0 = 0, f1 = 0, f2 = 0;
    const int SCAN = 1 << 20;
    int stride = gridDim.x * blockDim.x * 4;
    for (int i = (blockIdx.x * blockDim.x + threadIdx.x) * 4; i < SCAN; i += stride) {
        uchar4 v = *(const uchar4*)(raw + i);
        if (v.x > 1 || v.y > 1) f0 = 1;
        if (v.z > 1 || v.w > 1) f1 = 1;
        if (v.y | v.z | v.w)    f2 = 1;
    }
    if (f0) atomicOr(&g_flags[0], 1);
    if (f1) atomicOr(&g_flags[1], 1);
    if (f2) atomicOr(&g_flags[2], 1);
}

__global__ void mask_convert(const void* __restrict__ raw) {
    int kind;
    if (g_flags[0])      kind = 3;   // bf16
    else if (g_flags[1]) kind = 2;   // f32
    else if (g_flags[2]) kind = 0;   // u8
    else                 kind = 1;   // i32
    int i = blockIdx.x * blockDim.x + threadIdx.x;
    int stride = gridDim.x * blockDim.x;
    if (kind == 0) {
        const unsigned char* p = (const unsigned char*)raw;
        for (int e = i; e < MASK_N; e += stride) g_mask[e] = p[e] ? 1 : 0;
    } else if (kind == 1) {
        const int* p = (const int*)raw;
        for (int e = i; e < MASK_N; e += stride) g_mask[e] = p[e] ? 1 : 0;
    } else if (kind == 2) {
        const float* p = (const float*)raw;
        for (int e = i; e < MASK_N; e += stride) g_mask[e] = (p[e] != 0.f) ? 1 : 0;
    } else {
        const unsigned short* p = (const unsigned short*)raw;
        for (int e = i; e < MASK_N; e += stride)
            g_mask[e] = ((p[e] & 0x7fff) != 0) ? 1 : 0;
    }
}

// -------------------- gather + fp16 convert ----------------------------------
// q_in rows 0..255 = rc, 256..8447 = utt, 8448..8703 = summ (flat copies).
// kv_in rows 0..255 = mem, 256..511 = rc, 512..8703 = utt.
__global__ void in_convert(const float* __restrict__ utt,
                           const float* __restrict__ rc,
                           const float* __restrict__ summ,
                           const float* __restrict__ mem) {
    const int QN = MROWS * 128;   // float4 count per matrix
    int i = blockIdx.x * blockDim.x + threadIdx.x;
    if (i < QN) {
        int row = i >> 7;
        float4 v;
        if (row < 256)       v = ((const float4*)rc)[i];
        else if (row < 8448) v = ((const float4*)utt)[i - 256 * 128];
        else                 v = ((const float4*)summ)[i - 8448 * 128];
        uint2 o; o.x = packh2(v.x, v.y); o.y = packh2(v.z, v.w);
        ((uint2*)g_qin16)[i] = o;
    } else if (i < 2 * QN) {
        int j = i - QN;
        int row = j >> 7;
        float4 v;
        if (row < 256)      v = ((const float4*)mem)[j];
        else if (row < 512) v = ((const float4*)rc)[j - 256 * 128];
        else                v = ((const float4*)utt)[j - 512 * 128];
        uint2 o; o.x = packh2(v.x, v.y); o.y = packh2(v.z, v.w);
        ((uint2*)g_kvin16)[j] = o;
    }
}

// -------------------- weight transpose + fp16 convert ------------------------
// W[512][NN] -> Wt[NN][512] fp16
template<int NN>
__global__ void wconv(const float* __restrict__ W, __half* __restrict__ Wt) {
    __shared__ float tile[32][33];
    int bx = blockIdx.x, by = blockIdx.y;
    int x = threadIdx.x & 31, y0 = threadIdx.x >> 5;
    #pragma unroll
    for (int yy = y0; yy < 32; yy += 8)
        tile[yy][x] = W[(size_t)(by * 32 + yy) * NN + bx * 32 + x];
    __syncthreads();
    #pragma unroll
    for (int yy = y0; yy < 32; yy += 8)
        Wt[(size_t)(bx * 32 + yy) * 512 + by * 32 + x] =
            __float2half_rn(tile[x][yy]);
}

// -------------------- fp16 GEMM: C[M,N] = A[M,512] @ Wt^T + bias -------------
// A[M][512] fp16 row-major, Wt[N][512] fp16 row-major. 128x128 tile, BK=64,
// 2-stage cp.async double buffer. 8 warps = 4M x 2N, warp tile 32x64.
// MODE 1: out-proj scatter(slice/clip) fp32 -> C
// MODE 2: -> g_q16 (scaled by QSCALE)     MODE 3: -> g_k16 / g_v16
template<int NN, int MODE>
__global__ __launch_bounds__(256, 2)
void h16_gemm(const __half* __restrict__ A, const __half* __restrict__ Wt,
              const float* __restrict__ bias, float* __restrict__ C) {
    extern __shared__ uint32_t sm[];   // As[2][4608] | Bs[2][4608]
    const int tid = threadIdx.x;
    const int wid = tid >> 5, lane = tid & 31;
    const int g = lane >> 2, tig = lane & 3;
    const int wm = wid & 3, wn = wid >> 2;
    const int m0 = blockIdx.y * 128, n0 = blockIdx.x * 128;

    float acc[2][8][4];
    #pragma unroll
    for (int mf = 0; mf < 2; mf++)
        #pragma unroll
        for (int nf = 0; nf < 8; nf++)
            #pragma unroll
            for (int e = 0; e < 4; e++) acc[mf][nf][e] = 0.f;

    auto issue = [&](int t) {
        int k0 = t * 64;
        uint32_t* As = sm + (t & 1) * 4608;
        uint32_t* Bs = sm + 9216 + (t & 1) * 4608;
        #pragma unroll
        for (int l = 0; l < 4; l++) {
            int item = tid + l * 256;
            int row = item >> 3, c = item & 7;
            CP16(s2u(As + row * 36 + c * 4),
                 A + (size_t)(m0 + row) * 512 + k0 + c * 8);
        }
        #pragma unroll
        for (int l = 0; l < 4; l++) {
            int item = tid + l * 256;
            int row = item >> 3, c = item & 7;
            CP16(s2u(Bs + row * 36 + c * 4),
                 Wt + (size_t)(n0 + row) * 512 + k0 + c * 8);
        }
        CP_COMMIT();
    };

    issue(0);
    #pragma unroll 1
    for (int t = 0; t < 8; t++) {
        if (t + 1 < 8) {
            issue(t + 1);
            asm volatile("cp.async.wait_group 1;\n");
        } else {
            asm volatile("cp.async.wait_group 0;\n");
        }
        __syncthreads();
        const uint32_t* As = sm + (t & 1) * 4608;
        const uint32_t* Bs = sm + 9216 + (t & 1) * 4608;
        #pragma unroll
        for (int kc = 0; kc < 4; kc++) {
            uint32_t a[2][4];
            #pragma unroll
            for (int mf = 0; mf < 2; mf++) {
                const uint32_t* pa = As + (wm * 32 + mf * 16 + g) * 36 + kc * 8 + tig;
                a[mf][0] = pa[0];
                a[mf][1] = pa[8 * 36];
                a[mf][2] = pa[4];
                a[mf][3] = pa[8 * 36 + 4];
            }
            #pragma unroll
            for (int nf = 0; nf < 8; nf++) {
                const uint32_t* pb = Bs + (wn * 64 + nf * 8 + g) * 36 + kc * 8 + tig;
                uint32_t b0 = pb[0], b1 = pb[4];
                hmma(acc[0][nf], a[0][0], a[0][1], a[0][2], a[0][3], b0, b1);
                hmma(acc[1][nf], a[1][0], a[1][1], a[1][2], a[1][3], b0, b1);
            }
        }
        __syncthreads();
    }

    #pragma unroll
    for (int mf = 0; mf < 2; mf++) {
        int row0 = m0 + wm * 32 + mf * 16 + g;
        int row1 = row0 + 8;
        #pragma unroll
        for (int nf = 0; nf < 8; nf++) {
            int col = n0 + wn * 64 + nf * 8 + 2 * tig;
            float bi0 = __ldg(bias + col), bi1 = __ldg(bias + col + 1);
            float v00 = acc[mf][nf][0] + bi0, v01 = acc[mf][nf][1] + bi1;
            float v10 = acc[mf][nf][2] + bi0, v11 = acc[mf][nf][3] + bi1;
            if (MODE == 1) {
                int rows[2] = {row0, row1};
                float vs[2][2] = {{v00, v01}, {v10, v11}};
                #pragma unroll
                for (int r = 0; r < 2; r++) {
                    int m = rows[r];
                    int q = m >> 2, b = m & 3;
                    if (q < RCU_ROWS) {
                        *(float2*)(C + (size_t)m * DD + col) =
                            make_float2(vs[r][0], vs[r][1]);
                    } else if (q < QL - 1) {
                        float a0 = fminf(fmaxf(vs[r][0], -10.f), 10.f);
                        float a1 = fminf(fmaxf(vs[r][1], -10.f), 10.f);
                        *(float2*)(C + RCU_SZ +
                            (size_t)((q - RCU_ROWS) * BB + b) * DD + col) =
                            make_float2(a0, a1);
                    }
                }
            } else if (MODE == 2) {
                *(__half2*)(&g_q16[(size_t)row0 * DD + col]) =
                    __floats2half2_rn(v00 * QSCALE, v01 * QSCALE);
                *(__half2*)(&g_q16[(size_t)row1 * DD + col]) =
                    __floats2half2_rn(v10 * QSCALE, v11 * QSCALE);
            } else {   // MODE 3
                if (col < 512) {
                    *(__half2*)(&g_k16[(size_t)row0 * DD + col]) =
                        __floats2half2_rn(v00, v01);
                    *(__half2*)(&g_k16[(size_t)row1 * DD + col]) =
                        __floats2half2_rn(v10, v11);
                } else {
                    int vc = col - 512;
                    int rows[2] = {row0, row1};
                    float vs[2][2] = {{v00, v01}, {v10, v11}};
                    #pragma unroll
                    for (int r = 0; r < 2; r++) {
                        int k = rows[r] >> 2, b = rows[r] & 3;
                        size_t base = (((size_t)(k >> 1) * BB + b) * DD + vc) * 2 + (k & 1);
                        g_v16[base]     = __float2half_rn(vs[r][0]);
                        g_v16[base + 2] = __float2half_rn(vs[r][1]);
                    }
                }
            }
        }
    }
}

// -------------------- fp16 flash attention -----------------------------------
// Br=128, Bc=64, 256 threads (8 warps x 16 rows). cp.async double-buffered K/V.
__global__ __launch_bounds__(256)
void attn_h16(const int* __restrict__ lengths) {
    extern __shared__ uint32_t sm[];
    uint32_t* Qs = sm;

    const int tid = threadIdx.x;
    const int wid = tid >> 5, lane = tid & 31;
    const int g = lane >> 2, tig = lane & 3;
    const int b = blockIdx.y >> 3, h = blockIdx.y & 7;
    const int q0 = blockIdx.x * 128;
    const int wrow = wid * 16;
    const int limit = 128 + __ldg(lengths + b);
    const int qg0 = q0 + wrow + g;
    const int qg1 = qg0 + 8;

    #pragma unroll
    for (int l = 0; l < 4; l++) {
        int item = tid + l * 256;
        int row = item >> 3, c = item & 7;
        const __half* src = g_q16 + ((size_t)(q0 + row) * BB + b) * DD + h * DH + c * 8;
        CP16(s2u(Qs + row * 36 + c * 4), src);
    }
    {
        uint32_t* Ks = sm + 4608;
        uint32_t* Vs = Ks + 2304;
        #pragma unroll
        for (int l = 0; l < 2; l++) {
            int item = tid + l * 256;
            int row = item >> 3, c = item & 7;
            const __half* src = g_k16 + ((size_t)row * BB + b) * DD + h * DH + c * 8;
            CP16(s2u(Ks + row * 36 + c * 4), src);
        }
        #pragma unroll
        for (int l = 0; l < 2; l++) {
            int item = tid + l * 256;
            int row = item >> 4, c = item & 15;
            const __half* src = g_v16 + (((size_t)row * BB + b) * DD + h * DH + c * 4) * 2;
            CP16(s2u(Vs + row * 72 + c * 4), src);
        }
    }
    CP_COMMIT();

    float m_[2] = {-3.0e38f, -3.0e38f};
    float l_[2] = {0.f, 0.f};
    float o[8][4];
    #pragma unroll
    for (int nf = 0; nf < 8; nf++)
        #pragma unroll
        for (int e = 0; e < 4; e++) o[nf][e] = 0.f;

    const int NT = KVL / 64;
    for (int t = 0; t < NT; t++) {
        if (t + 1 < NT) {
            int k0 = (t + 1) * 64;
            uint32_t* Ks = sm + 4608 + ((t + 1) & 1) * 4608;
            uint32_t* Vs = Ks + 2304;
            #pragma unroll
            for (int l = 0; l < 2; l++) {
                int item = tid + l * 256;
                int row = item >> 3, c = item & 7;
                const __half* src = g_k16 + ((size_t)(k0 + row) * BB + b) * DD + h * DH + c * 8;
                CP16(s2u(Ks + row * 36 + c * 4), src);
            }
            int p0 = k0 >> 1;
            #pragma unroll
            for (int l = 0; l < 2; l++) {
                int item = tid + l * 256;
                int row = item >> 4, c = item & 15;
                const __half* src = g_v16 + (((size_t)(p0 + row) * BB + b) * DD + h * DH + c * 4) * 2;
                CP16(s2u(Vs + row * 72 + c * 4), src);
            }
            CP_COMMIT();
            asm volatile("cp.async.wait_group 1;\n");
        } else {
            asm volatile("cp.async.wait_group 0;\n");
        }
        __syncthreads();

        uint32_t* Ks = sm + 4608 + (t & 1) * 4608;
        uint32_t* Vs = Ks + 2304;

        float s[8][4];
        #pragma unroll
        for (int nf = 0; nf < 8; nf++)
            #pragma unroll
            for (int e = 0; e < 4; e++) s[nf][e] = 0.f;
        #pragma unroll
        for (int kc = 0; kc < 4; kc++) {
            const uint32_t* pa = Qs + (wrow + g) * 36 + kc * 8 + tig;
            uint32_t a0 = pa[0], a1 = pa[8 * 36], a2 = pa[4], a3 = pa[8 * 36 + 4];
            #pragma unroll
            for (int nf = 0; nf < 8; nf++) {
                const uint32_t* pb = Ks + (nf * 8 + g) * 36 + kc * 8 + tig;
                hmma(s[nf], a0, a1, a2, a3, pb[0], pb[4]);
            }
        }

        int kbase = t * 64;
        #pragma unroll
        for (int nf = 0; nf < 8; nf++) {
            int cg = kbase + nf * 8 + 2 * tig;
            uchar2 mv0 = *(const uchar2*)(g_mask + (size_t)qg0 * KVL + cg);
            uchar2 mv1 = *(const uchar2*)(g_mask + (size_t)qg1 * KVL + cg);
            if (mv0.x || cg     >= limit) s[nf][0] = NEGINF;
            if (mv0.y || cg + 1 >= limit) s[nf][1] = NEGINF;
            if (mv1.x || cg     >= limit) s[nf][2] = NEGINF;
            if (mv1.y || cg + 1 >= limit) s[nf][3] = NEGINF;
        }

        float tm0 = -3.0e38f, tm1 = -3.0e38f;
        #pragma unroll
        for (int nf = 0; nf < 8; nf++) {
            tm0 = fmaxf(tm0, fmaxf(s[nf][0], s[nf][1]));
            tm1 = fmaxf(tm1, fmaxf(s[nf][2], s[nf][3]));
        }
        tm0 = fmaxf(tm0, __shfl_xor_sync(0xffffffffu, tm0, 1));
        tm0 = fmaxf(tm0, __shfl_xor_sync(0xffffffffu, tm0, 2));
        tm1 = fmaxf(tm1, __shfl_xor_sync(0xffffffffu, tm1, 1));
        tm1 = fmaxf(tm1, __shfl_xor_sync(0xffffffffu, tm1, 2));
        float mn0 = fmaxf(m_[0], tm0), mn1 = fmaxf(m_[1], tm1);
        float corr0 = ex2(m_[0] - mn0), corr1 = ex2(m_[1] - mn1);
        float ps0 = 0.f, ps1 = 0.f;
        #pragma unroll
        for (int nf = 0; nf < 8; nf++) {
            s[nf][0] = ex2(s[nf][0] - mn0);
            s[nf][1] = ex2(s[nf][1] - mn0);
            s[nf][2] = ex2(s[nf][2] - mn1);
            s[nf][3] = ex2(s[nf][3] - mn1);
            ps0 += s[nf][0] + s[nf][1];
            ps1 += s[nf][2] + s[nf][3];
        }
        ps0 += __shfl_xor_sync(0xffffffffu, ps0, 1);
        ps0 += __shfl_xor_sync(0xffffffffu, ps0, 2);
        ps1 += __shfl_xor_sync(0xffffffffu, ps1, 1);
        ps1 += __shfl_xor_sync(0xffffffffu, ps1, 2);
        l_[0] = l_[0] * corr0 + ps0; m_[0] = mn0;
        l_[1] = l_[1] * corr1 + ps1; m_[1] = mn1;
        #pragma unroll
        for (int nf = 0; nf < 8; nf++) {
            o[nf][0] *= corr0; o[nf][1] *= corr0;
            o[nf][2] *= corr1; o[nf][3] *= corr1;
        }

        #pragma unroll
        for (int kc = 0; kc < 4; kc++) {
            uint32_t pa0 = packh2(s[2 * kc][0],     s[2 * kc][1]);
            uint32_t pa1 = packh2(s[2 * kc][2],     s[2 * kc][3]);
            uint32_t pa2 = packh2(s[2 * kc + 1][0], s[2 * kc + 1][1]);
            uint32_t pa3 = packh2(s[2 * kc + 1][2], s[2 * kc + 1][3]);
            #pragma unroll
            for (int nf = 0; nf < 8; nf++) {
                const uint32_t* pb = Vs + (kc * 8 + tig) * 72 + nf * 8 + g;
                hmma(o[nf], pa0, pa1, pa2, pa3, pb[0], pb[4 * 72]);
            }
        }
        __syncthreads();
    }

    float inv0 = 1.0f / l_[0], inv1 = 1.0f / l_[1];
    #pragma unroll
    for (int nf = 0; nf < 8; nf++) {
        int col = h * DH + nf * 8 + 2 * tig;
        *(__half2*)(&g_attn16[((size_t)qg0 * BB + b) * DD + col]) =
            __floats2half2_rn(o[nf][0] * inv0, o[nf][1] * inv0);
        *(__half2*)(&g_attn16[((size_t)qg1 * BB + b) * DD + col]) =
            __floats2half2_rn(o[nf][2] * inv1, o[nf][3] * inv1);
    }
}

// -------------------- launch ------------------------------------------------
extern "C" void kernel_launch(void* const* d_in, const int* in_sizes, int n_in,
                              void* d_out, int out_size) {
    const float* utt      = (const float*)d_in[0];
    const int*   lengths  = (const int*)d_in[1];
    const float* rc       = (const float*)d_in[2];
    const float* summ     = (const float*)d_in[3];
    const float* mem      = (const float*)d_in[4];
    const void*  mask_raw = (const void*)d_in[5];
    const float* w_q   = (const float*)d_in[6];
    const float* b_q   = (const float*)d_in[7];
    const float* w_kv  = (const float*)d_in[8];
    const float* b_kv  = (const float*)d_in[9];
    const float* w_out = (const float*)d_in[10];
    const float* b_out = (const float*)d_in[11];
    float* out = (float*)d_out;

    void *p;
    cudaGetSymbolAddress(&p, g_qin16);  __half* qin16  = (__half*)p;
    cudaGetSymbolAddress(&p, g_kvin16); __half* kvin16 = (__half*)p;
    cudaGetSymbolAddress(&p, g_attn16); __half* attn16 = (__half*)p;
    cudaGetSymbolAddress(&p, g_wqt);    __half* wqt    = (__half*)p;
    cudaGetSymbolAddress(&p, g_wkvt);   __half* wkvt   = (__half*)p;
    cudaGetSymbolAddress(&p, g_wot);    __half* wot    = (__half*)p;

    const int GSM = 18432 * 4;   // 73728 B for h16_gemm
    cudaFuncSetAttribute(h16_gemm<512, 2>,
                         cudaFuncAttributeMaxDynamicSharedMemorySize, GSM);
    cudaFuncSetAttribute(h16_gemm<1024, 3>,
                         cudaFuncAttributeMaxDynamicSharedMemorySize, GSM);
    cudaFuncSetAttribute(h16_gemm<512, 1>,
                         cudaFuncAttributeMaxDynamicSharedMemorySize, GSM);
    const int ASM = 13824 * 4;   // 55296 B for attention
    cudaFuncSetAttribute(attn_h16,
                         cudaFuncAttributeMaxDynamicSharedMemorySize, ASM);

    // 0. mask prep
    flags_reset<<<1, 1>>>();
    mask_sniff<<<64, 256>>>((const unsigned char*)mask_raw);
    mask_convert<<<512, 256>>>(mask_raw);

    // 1. gather + fp16 convert inputs
    in_convert<<<2 * MROWS * 128 / 256, 256>>>(utt, rc, summ, mem);

    // 2. weight transpose + fp16 convert
    wconv<512> <<<dim3(16, 16), 256>>>(w_q, wqt);
    wconv<1024><<<dim3(32, 16), 256>>>(w_kv, wkvt);
    wconv<512> <<<dim3(16, 16), 256>>>(w_out, wot);

    // 3. Q projection -> g_q16 (scaled)
    h16_gemm<512, 2><<<dim3(4, 68), 256, GSM>>>(qin16, wqt, b_q, nullptr);
    // 4. KV projection -> g_k16 / g_v16
    h16_gemm<1024, 3><<<dim3(8, 68), 256, GSM>>>(kvin16, wkvt, b_kv, nullptr);
    // 5. attention -> g_attn16
    attn_h16<<<dim3(QL / 128, BB * NH), 256, ASM>>>(lengths);
    // 6. output projection + slice/clip -> d_out
    h16_gemm<512, 1><<<dim3(4, 68), 256, GSM>>>(attn16, wot, b_out, out);
}

// round 6
// speedup vs baseline: 8.0344x; 1.1322x over previous
#include <cuda_runtime.h>
#include <cuda_fp16.h>
#include <cstdint>

#define UQ   2048
#define BB   4
#define DD   512
#define QL   2176
#define KVL  2176
#define NH   8
#define DH   64
#define NEGINF (-100000000.0f)
#define MROWS (QL*BB)          // 8704
#define RCU_ROWS 2112
#define RCU_SZ (2112*4*512)
#define NWORD 34               // KVL/64
#define QSCALE (0.125f * 1.44269504088896f)   // dh^-0.5 * log2(e)

// -------------------- device scratch ----------------------------------------
__device__ __half g_qin16 [MROWS * DD];
__device__ __half g_kvin16[MROWS * DD];
__device__ __half g_q16   [MROWS * DD];
__device__ __half g_k16   [MROWS * DD];
__device__ __half g_v16   [MROWS * DD];   // k-pair interleaved
__device__ __half g_attn16[MROWS * DD];
__device__ __half g_wqt [512 * 512];
__device__ __half g_wkvt[1024 * 512];
__device__ __half g_wot [512 * 512];
__device__ unsigned long long g_mbits[BB * QL * NWORD];  // mask|pad bits per batch
__device__ int g_flags[3];

// -------------------- helpers ------------------------------------------------
__device__ __forceinline__ void hmma(float* c,
    uint32_t a0, uint32_t a1, uint32_t a2, uint32_t a3,
    uint32_t b0, uint32_t b1) {
    asm volatile(
        "mma.sync.aligned.m16n8k16.row.col.f32.f16.f16.f32 "
        "{%0,%1,%2,%3}, {%4,%5,%6,%7}, {%8,%9}, {%0,%1,%2,%3};\n"
        : "+f"(c[0]), "+f"(c[1]), "+f"(c[2]), "+f"(c[3])
        : "r"(a0), "r"(a1), "r"(a2), "r"(a3), "r"(b0), "r"(b1));
}
__device__ __forceinline__ uint32_t packh2(float lo, float hi) {
    uint32_t r; asm("cvt.rn.f16x2.f32 %0, %1, %2;" : "=r"(r) : "f"(hi), "f"(lo));
    return r;
}
__device__ __forceinline__ float ex2(float x) {
    float r; asm("ex2.approx.f32 %0, %1;" : "=f"(r) : "f"(x)); return r;
}
__device__ __forceinline__ uint32_t s2u(const void* p) {
    return (uint32_t)__cvta_generic_to_shared(p);
}
#define CP16(dst, src) \
    asm volatile("cp.async.cg.shared.global [%0], [%1], 16;\n" :: "r"(dst), "l"(src))
#define CP_COMMIT() asm volatile("cp.async.commit_group;\n")

// -------------------- mask prep ----------------------------------------------
__global__ void flags_reset() { g_flags[0] = 0; g_flags[1] = 0; g_flags[2] = 0; }

__global__ void mask_sniff(const unsigned char* __restrict__ raw) {
    int f0 = 0, f1 = 0, f2 = 0;
    const int SCAN = 1 << 20;
    int stride = gridDim.x * blockDim.x * 4;
    for (int i = (blockIdx.x * blockDim.x + threadIdx.x) * 4; i < SCAN; i += stride) {
        uchar4 v = *(const uchar4*)(raw + i);
        if (v.x > 1 || v.y > 1) f0 = 1;
        if (v.z > 1 || v.w > 1) f1 = 1;
        if (v.y | v.z | v.w)    f2 = 1;
    }
    if (f0) atomicOr(&g_flags[0], 1);
    if (f1) atomicOr(&g_flags[1], 1);
    if (f2) atomicOr(&g_flags[2], 1);
}

// One warp packs one (q, word) pair: 64 mask values -> 1 uint64 via ballots,
// then ORs in the per-batch length-padding bits and stores 4 batch variants.
__global__ void mask_pack(const void* __restrict__ raw,
                          const int* __restrict__ lengths) {
    int warp = (blockIdx.x * blockDim.x + threadIdx.x) >> 5;
    int lane = threadIdx.x & 31;
    if (warp >= QL * NWORD) return;
    int q = warp / NWORD, w = warp - q * NWORD;

    int kind;
    if (g_flags[0])      kind = 3;   // bf16
    else if (g_flags[1]) kind = 2;   // f32
    else if (g_flags[2]) kind = 0;   // u8
    else                 kind = 1;   // i32

    size_t base = (size_t)q * KVL + w * 64;
    bool m0, m1;
    if (kind == 0) {
        const unsigned char* p = (const unsigned char*)raw;
        m0 = p[base + lane] != 0; m1 = p[base + 32 + lane] != 0;
    } else if (kind == 1) {
        const int* p = (const int*)raw;
        m0 = p[base + lane] != 0; m1 = p[base + 32 + lane] != 0;
    } else if (kind == 2) {
        const float* p = (const float*)raw;
        m0 = p[base + lane] != 0.f; m1 = p[base + 32 + lane] != 0.f;
    } else {
        const unsigned short* p = (const unsigned short*)raw;
        m0 = (p[base + lane] & 0x7fff) != 0;
        m1 = (p[base + 32 + lane] & 0x7fff) != 0;
    }
    uint32_t lo = __ballot_sync(0xffffffffu, m0);
    uint32_t hi = __ballot_sync(0xffffffffu, m1);
    unsigned long long word = (unsigned long long)lo |
                              ((unsigned long long)hi << 32);
    if (lane < 4) {
        int limit = 128 + __ldg(lengths + lane);   // pad: k >= limit masked
        int k0 = w * 64;
        unsigned long long pad;
        if (limit <= k0)           pad = ~0ull;
        else if (limit >= k0 + 64) pad = 0ull;
        else                       pad = (~0ull) << (limit - k0);
        g_mbits[((size_t)lane * QL + q) * NWORD + w] = word | pad;
    }
}

// -------------------- gather + fp16 convert ----------------------------------
__global__ void in_convert(const float* __restrict__ utt,
                           const float* __restrict__ rc,
                           const float* __restrict__ summ,
                           const float* __restrict__ mem) {
    const int QN = MROWS * 128;
    int i = blockIdx.x * blockDim.x + threadIdx.x;
    if (i < QN) {
        int row = i >> 7;
        float4 v;
        if (row < 256)       v = ((const float4*)rc)[i];
        else if (row < 8448) v = ((const float4*)utt)[i - 256 * 128];
        else                 v = ((const float4*)summ)[i - 8448 * 128];
        uint2 o; o.x = packh2(v.x, v.y); o.y = packh2(v.z, v.w);
        ((uint2*)g_qin16)[i] = o;
    } else if (i < 2 * QN) {
        int j = i - QN;
        int row = j >> 7;
        float4 v;
        if (row < 256)      v = ((const float4*)mem)[j];
        else if (row < 512) v = ((const float4*)rc)[j - 256 * 128];
        else                v = ((const float4*)utt)[j - 512 * 128];
        uint2 o; o.x = packh2(v.x, v.y); o.y = packh2(v.z, v.w);
        ((uint2*)g_kvin16)[j] = o;
    }
}

// -------------------- weight transpose + fp16 convert ------------------------
template<int NN>
__global__ void wconv(const float* __restrict__ W, __half* __restrict__ Wt) {
    __shared__ float tile[32][33];
    int bx = blockIdx.x, by = blockIdx.y;
    int x = threadIdx.x & 31, y0 = threadIdx.x >> 5;
    #pragma unroll
    for (int yy = y0; yy < 32; yy += 8)
        tile[yy][x] = W[(size_t)(by * 32 + yy) * NN + bx * 32 + x];
    __syncthreads();
    #pragma unroll
    for (int yy = y0; yy < 32; yy += 8)
        Wt[(size_t)(bx * 32 + yy) * 512 + by * 32 + x] =
            __float2half_rn(tile[x][yy]);
}

// -------------------- fp16 GEMM ----------------------------------------------
template<int NN, int MODE>
__global__ __launch_bounds__(256, 2)
void h16_gemm(const __half* __restrict__ A, const __half* __restrict__ Wt,
              const float* __restrict__ bias, float* __restrict__ C) {
    extern __shared__ uint32_t sm[];
    const int tid = threadIdx.x;
    const int wid = tid >> 5, lane = tid & 31;
    const int g = lane >> 2, tig = lane & 3;
    const int wm = wid & 3, wn = wid >> 2;
    const int m0 = blockIdx.y * 128, n0 = blockIdx.x * 128;

    float acc[2][8][4];
    #pragma unroll
    for (int mf = 0; mf < 2; mf++)
        #pragma unroll
        for (int nf = 0; nf < 8; nf++)
            #pragma unroll
            for (int e = 0; e < 4; e++) acc[mf][nf][e] = 0.f;

    auto issue = [&](int t) {
        int k0 = t * 64;
        uint32_t* As = sm + (t & 1) * 4608;
        uint32_t* Bs = sm + 9216 + (t & 1) * 4608;
        #pragma unroll
        for (int l = 0; l < 4; l++) {
            int item = tid + l * 256;
            int row = item >> 3, c = item & 7;
            CP16(s2u(As + row * 36 + c * 4),
                 A + (size_t)(m0 + row) * 512 + k0 + c * 8);
        }
        #pragma unroll
        for (int l = 0; l < 4; l++) {
            int item = tid + l * 256;
            int row = item >> 3, c = item & 7;
            CP16(s2u(Bs + row * 36 + c * 4),
                 Wt + (size_t)(n0 + row) * 512 + k0 + c * 8);
        }
        CP_COMMIT();
    };

    issue(0);
    #pragma unroll 1
    for (int t = 0; t < 8; t++) {
        if (t + 1 < 8) {
            issue(t + 1);
            asm volatile("cp.async.wait_group 1;\n");
        } else {
            asm volatile("cp.async.wait_group 0;\n");
        }
        __syncthreads();
        const uint32_t* As = sm + (t & 1) * 4608;
        const uint32_t* Bs = sm + 9216 + (t & 1) * 4608;
        #pragma unroll
        for (int kc = 0; kc < 4; kc++) {
            uint32_t a[2][4];
            #pragma unroll
            for (int mf = 0; mf < 2; mf++) {
                const uint32_t* pa = As + (wm * 32 + mf * 16 + g) * 36 + kc * 8 + tig;
                a[mf][0] = pa[0];
                a[mf][1] = pa[8 * 36];
                a[mf][2] = pa[4];
                a[mf][3] = pa[8 * 36 + 4];
            }
            #pragma unroll
            for (int nf = 0; nf < 8; nf++) {
                const uint32_t* pb = Bs + (wn * 64 + nf * 8 + g) * 36 + kc * 8 + tig;
                uint32_t b0 = pb[0], b1 = pb[4];
                hmma(acc[0][nf], a[0][0], a[0][1], a[0][2], a[0][3], b0, b1);
                hmma(acc[1][nf], a[1][0], a[1][1], a[1][2], a[1][3], b0, b1);
            }
        }
        __syncthreads();
    }

    #pragma unroll
    for (int mf = 0; mf < 2; mf++) {
        int row0 = m0 + wm * 32 + mf * 16 + g;
        int row1 = row0 + 8;
        #pragma unroll
        for (int nf = 0; nf < 8; nf++) {
            int col = n0 + wn * 64 + nf * 8 + 2 * tig;
            float bi0 = __ldg(bias + col), bi1 = __ldg(bias + col + 1);
            float v00 = acc[mf][nf][0] + bi0, v01 = acc[mf][nf][1] + bi1;
            float v10 = acc[mf][nf][2] + bi0, v11 = acc[mf][nf][3] + bi1;
            if (MODE == 1) {
                int rows[2] = {row0, row1};
                float vs[2][2] = {{v00, v01}, {v10, v11}};
                #pragma unroll
                for (int r = 0; r < 2; r++) {
                    int m = rows[r];
                    int q = m >> 2, b = m & 3;
                    if (q < RCU_ROWS) {
                        *(float2*)(C + (size_t)m * DD + col) =
                            make_float2(vs[r][0], vs[r][1]);
                    } else if (q < QL - 1) {
                        float a0 = fminf(fmaxf(vs[r][0], -10.f), 10.f);
                        float a1 = fminf(fmaxf(vs[r][1], -10.f), 10.f);
                        *(float2*)(C + RCU_SZ +
                            (size_t)((q - RCU_ROWS) * BB + b) * DD + col) =
                            make_float2(a0, a1);
                    }
                }
            } else if (MODE == 2) {
                *(__half2*)(&g_q16[(size_t)row0 * DD + col]) =
                    __floats2half2_rn(v00 * QSCALE, v01 * QSCALE);
                *(__half2*)(&g_q16[(size_t)row1 * DD + col]) =
                    __floats2half2_rn(v10 * QSCALE, v11 * QSCALE);
            } else {   // MODE 3
                if (col < 512) {
                    *(__half2*)(&g_k16[(size_t)row0 * DD + col]) =
                        __floats2half2_rn(v00, v01);
                    *(__half2*)(&g_k16[(size_t)row1 * DD + col]) =
                        __floats2half2_rn(v10, v11);
                } else {
                    int vc = col - 512;
                    int rows[2] = {row0, row1};
                    float vs[2][2] = {{v00, v01}, {v10, v11}};
                    #pragma unroll
                    for (int r = 0; r < 2; r++) {
                        int k = rows[r] >> 2, b = rows[r] & 3;
                        size_t base = (((size_t)(k >> 1) * BB + b) * DD + vc) * 2 + (k & 1);
                        g_v16[base]     = __float2half_rn(vs[r][0]);
                        g_v16[base + 2] = __float2half_rn(vs[r][1]);
                    }
                }
            }
        }
    }
}

// -------------------- fp16 flash attention (bit-packed mask) ------------------
__global__ __launch_bounds__(256)
void attn_h16(const int* __restrict__ lengths) {
    extern __shared__ uint32_t sm[];
    uint32_t* Qs = sm;

    const int tid = threadIdx.x;
    const int wid = tid >> 5, lane = tid & 31;
    const int g = lane >> 2, tig = lane & 3;
    const int b = blockIdx.y >> 3, h = blockIdx.y & 7;
    const int q0 = blockIdx.x * 128;
    const int wrow = wid * 16;
    const int qg0 = q0 + wrow + g;
    const int qg1 = qg0 + 8;
    const unsigned long long* mrow0 = g_mbits + ((size_t)b * QL + qg0) * NWORD;
    const unsigned long long* mrow1 = g_mbits + ((size_t)b * QL + qg1) * NWORD;

    #pragma unroll
    for (int l = 0; l < 4; l++) {
        int item = tid + l * 256;
        int row = item >> 3, c = item & 7;
        const __half* src = g_q16 + ((size_t)(q0 + row) * BB + b) * DD + h * DH + c * 8;
        CP16(s2u(Qs + row * 36 + c * 4), src);
    }
    {
        uint32_t* Ks = sm + 4608;
        uint32_t* Vs = Ks + 2304;
        #pragma unroll
        for (int l = 0; l < 2; l++) {
            int item = tid + l * 256;
            int row = item >> 3, c = item & 7;
            const __half* src = g_k16 + ((size_t)row * BB + b) * DD + h * DH + c * 8;
            CP16(s2u(Ks + row * 36 + c * 4), src);
        }
        #pragma unroll
        for (int l = 0; l < 2; l++) {
            int item = tid + l * 256;
            int row = item >> 4, c = item & 15;
            const __half* src = g_v16 + (((size_t)row * BB + b) * DD + h * DH + c * 4) * 2;
            CP16(s2u(Vs + row * 72 + c * 4), src);
        }
    }
    CP_COMMIT();

    float m_[2] = {-3.0e38f, -3.0e38f};
    float l_[2] = {0.f, 0.f};
    float o[8][4];
    #pragma unroll
    for (int nf = 0; nf < 8; nf++)
        #pragma unroll
        for (int e = 0; e < 4; e++) o[nf][e] = 0.f;

    const int NT = KVL / 64;
    for (int t = 0; t < NT; t++) {
        // prefetch mask words for this tile
        unsigned long long w0 = mrow0[t], w1 = mrow1[t];

        if (t + 1 < NT) {
            int k0 = (t + 1) * 64;
            uint32_t* Ks = sm + 4608 + ((t + 1) & 1) * 4608;
            uint32_t* Vs = Ks + 2304;
            #pragma unroll
            for (int l = 0; l < 2; l++) {
                int item = tid + l * 256;
                int row = item >> 3, c = item & 7;
                const __half* src = g_k16 + ((size_t)(k0 + row) * BB + b) * DD + h * DH + c * 8;
                CP16(s2u(Ks + row * 36 + c * 4), src);
            }
            int p0 = k0 >> 1;
            #pragma unroll
            for (int l = 0; l < 2; l++) {
                int item = tid + l * 256;
                int row = item >> 4, c = item & 15;
                const __half* src = g_v16 + (((size_t)(p0 + row) * BB + b) * DD + h * DH + c * 4) * 2;
                CP16(s2u(Vs + row * 72 + c * 4), src);
            }
            CP_COMMIT();
            asm volatile("cp.async.wait_group 1;\n");
        } else {
            asm volatile("cp.async.wait_group 0;\n");
        }
        __syncthreads();

        uint32_t* Ks = sm + 4608 + (t & 1) * 4608;
        uint32_t* Vs = Ks + 2304;

        float s[8][4];
        #pragma unroll
        for (int nf = 0; nf < 8; nf++)
            #pragma unroll
            for (int e = 0; e < 4; e++) s[nf][e] = 0.f;
        #pragma unroll
        for (int kc = 0; kc < 4; kc++) {
            const uint32_t* pa = Qs + (wrow + g) * 36 + kc * 8 + tig;
            uint32_t a0 = pa[0], a1 = pa[8 * 36], a2 = pa[4], a3 = pa[8 * 36 + 4];
            #pragma unroll
            for (int nf = 0; nf < 8; nf++) {
                const uint32_t* pb = Ks + (nf * 8 + g) * 36 + kc * 8 + tig;
                hmma(s[nf], a0, a1, a2, a3, pb[0], pb[4]);
            }
        }

        // apply bit-packed mask (pad already folded in)
        #pragma unroll
        for (int nf = 0; nf < 8; nf++) {
            int sh = nf * 8 + 2 * tig;
            uint32_t b0 = (uint32_t)(w0 >> sh);
            uint32_t b1 = (uint32_t)(w1 >> sh);
            if (b0 & 1) s[nf][0] = NEGINF;
            if (b0 & 2) s[nf][1] = NEGINF;
            if (b1 & 1) s[nf][2] = NEGINF;
            if (b1 & 2) s[nf][3] = NEGINF;
        }

        float tm0 = -3.0e38f, tm1 = -3.0e38f;
        #pragma unroll
        for (int nf = 0; nf < 8; nf++) {
            tm0 = fmaxf(tm0, fmaxf(s[nf][0], s[nf][1]));
            tm1 = fmaxf(tm1, fmaxf(s[nf][2], s[nf][3]));
        }
        tm0 = fmaxf(tm0, __shfl_xor_sync(0xffffffffu, tm0, 1));
        tm0 = fmaxf(tm0, __shfl_xor_sync(0xffffffffu, tm0, 2));
        tm1 = fmaxf(tm1, __shfl_xor_sync(0xffffffffu, tm1, 1));
        tm1 = fmaxf(tm1, __shfl_xor_sync(0xffffffffu, tm1, 2));
        float mn0 = fmaxf(m_[0], tm0), mn1 = fmaxf(m_[1], tm1);
        float corr0 = ex2(m_[0] - mn0), corr1 = ex2(m_[1] - mn1);
        float ps0 = 0.f, ps1 = 0.f;
        #pragma unroll
        for (int nf = 0; nf < 8; nf++) {
            s[nf][0] = ex2(s[nf][0] - mn0);
            s[nf][1] = ex2(s[nf][1] - mn0);
            s[nf][2] = ex2(s[nf][2] - mn1);
            s[nf][3] = ex2(s[nf][3] - mn1);
            ps0 += s[nf][0] + s[nf][1];
            ps1 += s[nf][2] + s[nf][3];
        }
        ps0 += __shfl_xor_sync(0xffffffffu, ps0, 1);
        ps0 += __shfl_xor_sync(0xffffffffu, ps0, 2);
        ps1 += __shfl_xor_sync(0xffffffffu, ps1, 1);
        ps1 += __shfl_xor_sync(0xffffffffu, ps1, 2);
        l_[0] = l_[0] * corr0 + ps0; m_[0] = mn0;
        l_[1] = l_[1] * corr1 + ps1; m_[1] = mn1;
        #pragma unroll
        for (int nf = 0; nf < 8; nf++) {
            o[nf][0] *= corr0; o[nf][1] *= corr0;
            o[nf][2] *= corr1; o[nf][3] *= corr1;
        }

        #pragma unroll
        for (int kc = 0; kc < 4; kc++) {
            uint32_t pa0 = packh2(s[2 * kc][0],     s[2 * kc][1]);
            uint32_t pa1 = packh2(s[2 * kc][2],     s[2 * kc][3]);
            uint32_t pa2 = packh2(s[2 * kc + 1][0], s[2 * kc + 1][1]);
            uint32_t pa3 = packh2(s[2 * kc + 1][2], s[2 * kc + 1][3]);
            #pragma unroll
            for (int nf = 0; nf < 8; nf++) {
                const uint32_t* pb = Vs + (kc * 8 + tig) * 72 + nf * 8 + g;
                hmma(o[nf], pa0, pa1, pa2, pa3, pb[0], pb[4 * 72]);
            }
        }
        __syncthreads();
    }

    float inv0 = 1.0f / l_[0], inv1 = 1.0f / l_[1];
    #pragma unroll
    for (int nf = 0; nf < 8; nf++) {
        int col = h * DH + nf * 8 + 2 * tig;
        *(__half2*)(&g_attn16[((size_t)qg0 * BB + b) * DD + col]) =
            __floats2half2_rn(o[nf][0] * inv0, o[nf][1] * inv0);
        *(__half2*)(&g_attn16[((size_t)qg1 * BB + b) * DD + col]) =
            __floats2half2_rn(o[nf][2] * inv1, o[nf][3] * inv1);
    }
}

// -------------------- launch ------------------------------------------------
extern "C" void kernel_launch(void* const* d_in, const int* in_sizes, int n_in,
                              void* d_out, int out_size) {
    const float* utt      = (const float*)d_in[0];
    const int*   lengths  = (const int*)d_in[1];
    const float* rc       = (const float*)d_in[2];
    const float* summ     = (const float*)d_in[3];
    const float* mem      = (const float*)d_in[4];
    const void*  mask_raw = (const void*)d_in[5];
    const float* w_q   = (const float*)d_in[6];
    const float* b_q   = (const float*)d_in[7];
    const float* w_kv  = (const float*)d_in[8];
    const float* b_kv  = (const float*)d_in[9];
    const float* w_out = (const float*)d_in[10];
    const float* b_out = (const float*)d_in[11];
    float* out = (float*)d_out;

    void *p;
    cudaGetSymbolAddress(&p, g_qin16);  __half* qin16  = (__half*)p;
    cudaGetSymbolAddress(&p, g_kvin16); __half* kvin16 = (__half*)p;
    cudaGetSymbolAddress(&p, g_attn16); __half* attn16 = (__half*)p;
    cudaGetSymbolAddress(&p, g_wqt);    __half* wqt    = (__half*)p;
    cudaGetSymbolAddress(&p, g_wkvt);   __half* wkvt   = (__half*)p;
    cudaGetSymbolAddress(&p, g_wot);    __half* wot    = (__half*)p;

    const int GSM = 18432 * 4;
    cudaFuncSetAttribute(h16_gemm<512, 2>,
                         cudaFuncAttributeMaxDynamicSharedMemorySize, GSM);
    cudaFuncSetAttribute(h16_gemm<1024, 3>,
                         cudaFuncAttributeMaxDynamicSharedMemorySize, GSM);
    cudaFuncSetAttribute(h16_gemm<512, 1>,
                         cudaFuncAttributeMaxDynamicSharedMemorySize, GSM);
    const int ASM = 13824 * 4;
    cudaFuncSetAttribute(attn_h16,
                         cudaFuncAttributeMaxDynamicSharedMemorySize, ASM);

    // 0. mask prep: sniff dtype, then pack to bits with pad folded in
    flags_reset<<<1, 1>>>();
    mask_sniff<<<64, 256>>>((const unsigned char*)mask_raw);
    {
        int warps = QL * NWORD;                 // 73984
        mask_pack<<<(warps * 32 + 255) / 256, 256>>>(mask_raw, lengths);
    }

    // 1. gather + fp16 convert inputs
    in_convert<<<2 * MROWS * 128 / 256, 256>>>(utt, rc, summ, mem);

    // 2. weight transpose + fp16 convert
    wconv<512> <<<dim3(16, 16), 256>>>(w_q, wqt);
    wconv<1024><<<dim3(32, 16), 256>>>(w_kv, wkvt);
    wconv<512> <<<dim3(16, 16), 256>>>(w_out, wot);

    // 3. Q projection -> g_q16 (scaled)
    h16_gemm<512, 2><<<dim3(4, 68), 256, GSM>>>(qin16, wqt, b_q, nullptr);
    // 4. KV projection -> g_k16 / g_v16
    h16_gemm<1024, 3><<<dim3(8, 68), 256, GSM>>>(kvin16, wkvt, b_kv, nullptr);
    // 5. attention -> g_attn16
    attn_h16<<<dim3(QL / 128, BB * NH), 256, ASM>>>(lengths);
    // 6. output projection + slice/clip -> d_out
    h16_gemm<512, 1><<<dim3(4, 68), 256, GSM>>>(attn16, wot, b_out, out);
}

// round 7
// speedup vs baseline: 8.4583x; 1.0528x over previous
#include <cuda_runtime.h>
#include <cuda_fp16.h>
#include <cstdint>

#define UQ   2048
#define BB   4
#define DD   512
#define QL   2176
#define KVL  2176
#define NH   8
#define DH   64
#define NEGINF (-100000000.0f)
#define MROWS (QL*BB)          // 8704
#define RCU_ROWS 2112
#define RCU_SZ (2112*4*512)
#define NWORD 34               // KVL/64
#define QSCALE (0.125f * 1.44269504088896f)   // dh^-0.5 * log2(e)

// -------------------- device scratch ----------------------------------------
__device__ __half g_qin16 [MROWS * DD];
__device__ __half g_kvin16[MROWS * DD];
__device__ __half g_q16   [MROWS * DD];
__device__ __half g_k16   [MROWS * DD];
__device__ __half g_v16   [MROWS * DD];   // k-pair interleaved
__device__ __half g_attn16[MROWS * DD];
__device__ __half g_wqt [512 * 512];
__device__ __half g_wkvt[1024 * 512];
__device__ __half g_wot [512 * 512];
__device__ unsigned long long g_mbits[BB * QL * NWORD];  // mask|pad bits per batch
__device__ int g_flags[3];

// -------------------- helpers ------------------------------------------------
__device__ __forceinline__ void hmma(float* c,
    uint32_t a0, uint32_t a1, uint32_t a2, uint32_t a3,
    uint32_t b0, uint32_t b1) {
    asm volatile(
        "mma.sync.aligned.m16n8k16.row.col.f32.f16.f16.f32 "
        "{%0,%1,%2,%3}, {%4,%5,%6,%7}, {%8,%9}, {%0,%1,%2,%3};\n"
        : "+f"(c[0]), "+f"(c[1]), "+f"(c[2]), "+f"(c[3])
        : "r"(a0), "r"(a1), "r"(a2), "r"(a3), "r"(b0), "r"(b1));
}
__device__ __forceinline__ uint32_t packh2(float lo, float hi) {
    uint32_t r; asm("cvt.rn.f16x2.f32 %0, %1, %2;" : "=r"(r) : "f"(hi), "f"(lo));
    return r;
}
__device__ __forceinline__ float ex2(float x) {
    float r; asm("ex2.approx.f32 %0, %1;" : "=f"(r) : "f"(x)); return r;
}
__device__ __forceinline__ uint32_t s2u(const void* p) {
    return (uint32_t)__cvta_generic_to_shared(p);
}
#define CP16(dst, src) \
    asm volatile("cp.async.cg.shared.global [%0], [%1], 16;\n" :: "r"(dst), "l"(src))
#define CP_COMMIT() asm volatile("cp.async.commit_group;\n")

// -------------------- mask prep ----------------------------------------------
__global__ void flags_reset() { g_flags[0] = 0; g_flags[1] = 0; g_flags[2] = 0; }

__global__ void mask_sniff(const unsigned char* __restrict__ raw) {
    int f0 = 0, f1 = 0, f2 = 0;
    const int SCAN = 1 << 20;
    int stride = gridDim.x * blockDim.x * 4;
    for (int i = (blockIdx.x * blockDim.x + threadIdx.x) * 4; i < SCAN; i += stride) {
        uchar4 v = *(const uchar4*)(raw + i);
        if (v.x > 1 || v.y > 1) f0 = 1;
        if (v.z > 1 || v.w > 1) f1 = 1;
        if (v.y | v.z | v.w)    f2 = 1;
    }
    if (f0) atomicOr(&g_flags[0], 1);
    if (f1) atomicOr(&g_flags[1], 1);
    if (f2) atomicOr(&g_flags[2], 1);
}

__global__ void mask_pack(const void* __restrict__ raw,
                          const int* __restrict__ lengths) {
    int warp = (blockIdx.x * blockDim.x + threadIdx.x) >> 5;
    int lane = threadIdx.x & 31;
    if (warp >= QL * NWORD) return;
    int q = warp / NWORD, w = warp - q * NWORD;

    int kind;
    if (g_flags[0])      kind = 3;   // bf16
    else if (g_flags[1]) kind = 2;   // f32
    else if (g_flags[2]) kind = 0;   // u8
    else                 kind = 1;   // i32

    size_t base = (size_t)q * KVL + w * 64;
    bool m0, m1;
    if (kind == 0) {
        const unsigned char* p = (const unsigned char*)raw;
        m0 = p[base + lane] != 0; m1 = p[base + 32 + lane] != 0;
    } else if (kind == 1) {
        const int* p = (const int*)raw;
        m0 = p[base + lane] != 0; m1 = p[base + 32 + lane] != 0;
    } else if (kind == 2) {
        const float* p = (const float*)raw;
        m0 = p[base + lane] != 0.f; m1 = p[base + 32 + lane] != 0.f;
    } else {
        const unsigned short* p = (const unsigned short*)raw;
        m0 = (p[base + lane] & 0x7fff) != 0;
        m1 = (p[base + 32 + lane] & 0x7fff) != 0;
    }
    uint32_t lo = __ballot_sync(0xffffffffu, m0);
    uint32_t hi = __ballot_sync(0xffffffffu, m1);
    unsigned long long word = (unsigned long long)lo |
                              ((unsigned long long)hi << 32);
    if (lane < 4) {
        int limit = 128 + __ldg(lengths + lane);
        int k0 = w * 64;
        unsigned long long pad;
        if (limit <= k0)           pad = ~0ull;
        else if (limit >= k0 + 64) pad = 0ull;
        else                       pad = (~0ull) << (limit - k0);
        g_mbits[((size_t)lane * QL + q) * NWORD + w] = word | pad;
    }
}

// -------------------- gather + fp16 convert ----------------------------------
__global__ void in_convert(const float* __restrict__ utt,
                           const float* __restrict__ rc,
                           const float* __restrict__ summ,
                           const float* __restrict__ mem) {
    const int QN = MROWS * 128;
    int i = blockIdx.x * blockDim.x + threadIdx.x;
    if (i < QN) {
        int row = i >> 7;
        float4 v;
        if (row < 256)       v = ((const float4*)rc)[i];
        else if (row < 8448) v = ((const float4*)utt)[i - 256 * 128];
        else                 v = ((const float4*)summ)[i - 8448 * 128];
        uint2 o; o.x = packh2(v.x, v.y); o.y = packh2(v.z, v.w);
        ((uint2*)g_qin16)[i] = o;
    } else if (i < 2 * QN) {
        int j = i - QN;
        int row = j >> 7;
        float4 v;
        if (row < 256)      v = ((const float4*)mem)[j];
        else if (row < 512) v = ((const float4*)rc)[j - 256 * 128];
        else                v = ((const float4*)utt)[j - 512 * 128];
        uint2 o; o.x = packh2(v.x, v.y); o.y = packh2(v.z, v.w);
        ((uint2*)g_kvin16)[j] = o;
    }
}

// -------------------- weight transpose + fp16 convert ------------------------
template<int NN>
__global__ void wconv(const float* __restrict__ W, __half* __restrict__ Wt) {
    __shared__ float tile[32][33];
    int bx = blockIdx.x, by = blockIdx.y;
    int x = threadIdx.x & 31, y0 = threadIdx.x >> 5;
    #pragma unroll
    for (int yy = y0; yy < 32; yy += 8)
        tile[yy][x] = W[(size_t)(by * 32 + yy) * NN + bx * 32 + x];
    __syncthreads();
    #pragma unroll
    for (int yy = y0; yy < 32; yy += 8)
        Wt[(size_t)(bx * 32 + yy) * 512 + by * 32 + x] =
            __float2half_rn(tile[x][yy]);
}

// -------------------- fp16 GEMM core (shared by both GEMM kernels) -----------
struct GemmAcc { float a[2][8][4]; };

__device__ __forceinline__ void gemm_main(uint32_t* sm, const __half* A,
                                          const __half* Wt, int m0, int n0,
                                          GemmAcc& acc) {
    const int tid = threadIdx.x;
    const int wid = tid >> 5, lane = tid & 31;
    const int g = lane >> 2, tig = lane & 3;
    const int wm = wid & 3, wn = wid >> 2;

    #pragma unroll
    for (int mf = 0; mf < 2; mf++)
        #pragma unroll
        for (int nf = 0; nf < 8; nf++)
            #pragma unroll
            for (int e = 0; e < 4; e++) acc.a[mf][nf][e] = 0.f;

    auto issue = [&](int t) {
        int k0 = t * 64;
        uint32_t* As = sm + (t & 1) * 4608;
        uint32_t* Bs = sm + 9216 + (t & 1) * 4608;
        #pragma unroll
        for (int l = 0; l < 4; l++) {
            int item = tid + l * 256;
            int row = item >> 3, c = item & 7;
            CP16(s2u(As + row * 36 + c * 4),
                 A + (size_t)(m0 + row) * 512 + k0 + c * 8);
        }
        #pragma unroll
        for (int l = 0; l < 4; l++) {
            int item = tid + l * 256;
            int row = item >> 3, c = item & 7;
            CP16(s2u(Bs + row * 36 + c * 4),
                 Wt + (size_t)(n0 + row) * 512 + k0 + c * 8);
        }
        CP_COMMIT();
    };

    issue(0);
    #pragma unroll 1
    for (int t = 0; t < 8; t++) {
        if (t + 1 < 8) {
            issue(t + 1);
            asm volatile("cp.async.wait_group 1;\n");
        } else {
            asm volatile("cp.async.wait_group 0;\n");
        }
        __syncthreads();
        const uint32_t* As = sm + (t & 1) * 4608;
        const uint32_t* Bs = sm + 9216 + (t & 1) * 4608;
        #pragma unroll
        for (int kc = 0; kc < 4; kc++) {
            uint32_t a[2][4];
            #pragma unroll
            for (int mf = 0; mf < 2; mf++) {
                const uint32_t* pa = As + (wm * 32 + mf * 16 + g) * 36 + kc * 8 + tig;
                a[mf][0] = pa[0];
                a[mf][1] = pa[8 * 36];
                a[mf][2] = pa[4];
                a[mf][3] = pa[8 * 36 + 4];
            }
            #pragma unroll
            for (int nf = 0; nf < 8; nf++) {
                const uint32_t* pb = Bs + (wn * 64 + nf * 8 + g) * 36 + kc * 8 + tig;
                uint32_t b0 = pb[0], b1 = pb[4];
                hmma(acc.a[0][nf], a[0][0], a[0][1], a[0][2], a[0][3], b0, b1);
                hmma(acc.a[1][nf], a[1][0], a[1][1], a[1][2], a[1][3], b0, b1);
            }
        }
        __syncthreads();
    }
}

// -------------------- merged Q + KV projection -------------------------------
// grid (12, 68): bx<4 -> Q tile (epilogue: scale+fp16), bx>=4 -> KV tile.
__global__ __launch_bounds__(256, 2)
void qkv_gemm(const __half* __restrict__ qA, const __half* __restrict__ kvA,
              const __half* __restrict__ wq, const __half* __restrict__ wkv,
              const float* __restrict__ bq, const float* __restrict__ bkv) {
    extern __shared__ uint32_t sm[];
    const bool isQ = blockIdx.x < 4;
    const int n0 = isQ ? blockIdx.x * 128 : (blockIdx.x - 4) * 128;
    const int m0 = blockIdx.y * 128;
    const __half* A  = isQ ? qA : kvA;
    const __half* Wt = isQ ? wq : wkv;
    const float* bias = isQ ? bq : bkv;

    GemmAcc acc;
    gemm_main(sm, A, Wt, m0, n0, acc);

    const int lane = threadIdx.x & 31, wid = threadIdx.x >> 5;
    const int g = lane >> 2, tig = lane & 3;
    const int wm = wid & 3, wn = wid >> 2;
    #pragma unroll
    for (int mf = 0; mf < 2; mf++) {
        int row0 = m0 + wm * 32 + mf * 16 + g;
        int row1 = row0 + 8;
        #pragma unroll
        for (int nf = 0; nf < 8; nf++) {
            int col = n0 + wn * 64 + nf * 8 + 2 * tig;
            float bi0 = __ldg(bias + col), bi1 = __ldg(bias + col + 1);
            float v00 = acc.a[mf][nf][0] + bi0, v01 = acc.a[mf][nf][1] + bi1;
            float v10 = acc.a[mf][nf][2] + bi0, v11 = acc.a[mf][nf][3] + bi1;
            if (isQ) {
                *(__half2*)(&g_q16[(size_t)row0 * DD + col]) =
                    __floats2half2_rn(v00 * QSCALE, v01 * QSCALE);
                *(__half2*)(&g_q16[(size_t)row1 * DD + col]) =
                    __floats2half2_rn(v10 * QSCALE, v11 * QSCALE);
            } else if (col < 512) {
                *(__half2*)(&g_k16[(size_t)row0 * DD + col]) =
                    __floats2half2_rn(v00, v01);
                *(__half2*)(&g_k16[(size_t)row1 * DD + col]) =
                    __floats2half2_rn(v10, v11);
            } else {
                int vc = col - 512;
                int rows[2] = {row0, row1};
                float vs[2][2] = {{v00, v01}, {v10, v11}};
                #pragma unroll
                for (int r = 0; r < 2; r++) {
                    int k = rows[r] >> 2, b = rows[r] & 3;
                    size_t base = (((size_t)(k >> 1) * BB + b) * DD + vc) * 2 + (k & 1);
                    g_v16[base]     = __float2half_rn(vs[r][0]);
                    g_v16[base + 2] = __float2half_rn(vs[r][1]);
                }
            }
        }
    }
}

// -------------------- output projection (slice/clip scatter) -----------------
__global__ __launch_bounds__(256, 2)
void out_gemm(const __half* __restrict__ A, const __half* __restrict__ Wt,
              const float* __restrict__ bias, float* __restrict__ C) {
    extern __shared__ uint32_t sm[];
    const int m0 = blockIdx.y * 128, n0 = blockIdx.x * 128;
    GemmAcc acc;
    gemm_main(sm, A, Wt, m0, n0, acc);

    const int lane = threadIdx.x & 31, wid = threadIdx.x >> 5;
    const int g = lane >> 2, tig = lane & 3;
    const int wm = wid & 3, wn = wid >> 2;
    #pragma unroll
    for (int mf = 0; mf < 2; mf++) {
        int row0 = m0 + wm * 32 + mf * 16 + g;
        #pragma unroll
        for (int nf = 0; nf < 8; nf++) {
            int col = n0 + wn * 64 + nf * 8 + 2 * tig;
            float bi0 = __ldg(bias + col), bi1 = __ldg(bias + col + 1);
            float vs[2][2] = {
                {acc.a[mf][nf][0] + bi0, acc.a[mf][nf][1] + bi1},
                {acc.a[mf][nf][2] + bi0, acc.a[mf][nf][3] + bi1}};
            #pragma unroll
            for (int r = 0; r < 2; r++) {
                int m = row0 + r * 8;
                int q = m >> 2, b = m & 3;
                if (q < RCU_ROWS) {
                    *(float2*)(C + (size_t)m * DD + col) =
                        make_float2(vs[r][0], vs[r][1]);
                } else if (q < QL - 1) {
                    float a0 = fminf(fmaxf(vs[r][0], -10.f), 10.f);
                    float a1 = fminf(fmaxf(vs[r][1], -10.f), 10.f);
                    *(float2*)(C + RCU_SZ +
                        (size_t)((q - RCU_ROWS) * BB + b) * DD + col) =
                        make_float2(a0, a1);
                }
            }
        }
    }
}

// -------------------- fp16 flash attention (bit mask + tail skip) -------------
__global__ __launch_bounds__(256)
void attn_h16(const int* __restrict__ lengths) {
    extern __shared__ uint32_t sm[];
    uint32_t* Qs = sm;

    const int tid = threadIdx.x;
    const int wid = tid >> 5, lane = tid & 31;
    const int g = lane >> 2, tig = lane & 3;
    const int b = blockIdx.y >> 3, h = blockIdx.y & 7;
    const int q0 = blockIdx.x * 128;
    const int wrow = wid * 16;
    const int qg0 = q0 + wrow + g;
    const int qg1 = qg0 + 8;
    const unsigned long long* mrow0 = g_mbits + ((size_t)b * QL + qg0) * NWORD;
    const unsigned long long* mrow1 = g_mbits + ((size_t)b * QL + qg1) * NWORD;

    // per-batch tile count: tiles at k >= 128+len are fully pad-masked -> skip
    const int limit = 128 + __ldg(lengths + b);
    const int NTb = min(NWORD, (limit + 63) >> 6);

    #pragma unroll
    for (int l = 0; l < 4; l++) {
        int item = tid + l * 256;
        int row = item >> 3, c = item & 7;
        const __half* src = g_q16 + ((size_t)(q0 + row) * BB + b) * DD + h * DH + c * 8;
        CP16(s2u(Qs + row * 36 + c * 4), src);
    }
    {
        uint32_t* Ks = sm + 4608;
        uint32_t* Vs = Ks + 2304;
        #pragma unroll
        for (int l = 0; l < 2; l++) {
            int item = tid + l * 256;
            int row = item >> 3, c = item & 7;
            const __half* src = g_k16 + ((size_t)row * BB + b) * DD + h * DH + c * 8;
            CP16(s2u(Ks + row * 36 + c * 4), src);
        }
        #pragma unroll
        for (int l = 0; l < 2; l++) {
            int item = tid + l * 256;
            int row = item >> 4, c = item & 15;
            const __half* src = g_v16 + (((size_t)row * BB + b) * DD + h * DH + c * 4) * 2;
            CP16(s2u(Vs + row * 72 + c * 4), src);
        }
    }
    CP_COMMIT();

    float m_[2] = {-3.0e38f, -3.0e38f};
    float l_[2] = {0.f, 0.f};
    float o[8][4];
    #pragma unroll
    for (int nf = 0; nf < 8; nf++)
        #pragma unroll
        for (int e = 0; e < 4; e++) o[nf][e] = 0.f;

    #pragma unroll 1
    for (int t = 0; t < NTb; t++) {
        unsigned long long w0 = mrow0[t], w1 = mrow1[t];

        if (t + 1 < NTb) {
            int k0 = (t + 1) * 64;
            uint32_t* Ks = sm + 4608 + ((t + 1) & 1) * 4608;
            uint32_t* Vs = Ks + 2304;
            #pragma unroll
            for (int l = 0; l < 2; l++) {
                int item = tid + l * 256;
                int row = item >> 3, c = item & 7;
                const __half* src = g_k16 + ((size_t)(k0 + row) * BB + b) * DD + h * DH + c * 8;
                CP16(s2u(Ks + row * 36 + c * 4), src);
            }
            int p0 = k0 >> 1;
            #pragma unroll
            for (int l = 0; l < 2; l++) {
                int item = tid + l * 256;
                int row = item >> 4, c = item & 15;
                const __half* src = g_v16 + (((size_t)(p0 + row) * BB + b) * DD + h * DH + c * 4) * 2;
                CP16(s2u(Vs + row * 72 + c * 4), src);
            }
            CP_COMMIT();
            asm volatile("cp.async.wait_group 1;\n");
        } else {
            asm volatile("cp.async.wait_group 0;\n");
        }
        __syncthreads();

        uint32_t* Ks = sm + 4608 + (t & 1) * 4608;
        uint32_t* Vs = Ks + 2304;

        float s[8][4];
        #pragma unroll
        for (int nf = 0; nf < 8; nf++)
            #pragma unroll
            for (int e = 0; e < 4; e++) s[nf][e] = 0.f;
        #pragma unroll
        for (int kc = 0; kc < 4; kc++) {
            const uint32_t* pa = Qs + (wrow + g) * 36 + kc * 8 + tig;
            uint32_t a0 = pa[0], a1 = pa[8 * 36], a2 = pa[4], a3 = pa[8 * 36 + 4];
            #pragma unroll
            for (int nf = 0; nf < 8; nf++) {
                const uint32_t* pb = Ks + (nf * 8 + g) * 36 + kc * 8 + tig;
                hmma(s[nf], a0, a1, a2, a3, pb[0], pb[4]);
            }
        }

        #pragma unroll
        for (int nf = 0; nf < 8; nf++) {
            int sh = nf * 8 + 2 * tig;
            uint32_t b0 = (uint32_t)(w0 >> sh);
            uint32_t b1 = (uint32_t)(w1 >> sh);
            if (b0 & 1) s[nf][0] = NEGINF;
            if (b0 & 2) s[nf][1] = NEGINF;
            if (b1 & 1) s[nf][2] = NEGINF;
            if (b1 & 2) s[nf][3] = NEGINF;
        }

        float tm0 = -3.0e38f, tm1 = -3.0e38f;
        #pragma unroll
        for (int nf = 0; nf < 8; nf++) {
            tm0 = fmaxf(tm0, fmaxf(s[nf][0], s[nf][1]));
            tm1 = fmaxf(tm1, fmaxf(s[nf][2], s[nf][3]));
        }
        tm0 = fmaxf(tm0, __shfl_xor_sync(0xffffffffu, tm0, 1));
        tm0 = fmaxf(tm0, __shfl_xor_sync(0xffffffffu, tm0, 2));
        tm1 = fmaxf(tm1, __shfl_xor_sync(0xffffffffu, tm1, 1));
        tm1 = fmaxf(tm1, __shfl_xor_sync(0xffffffffu, tm1, 2));
        float mn0 = fmaxf(m_[0], tm0), mn1 = fmaxf(m_[1], tm1);
        float corr0 = ex2(m_[0] - mn0), corr1 = ex2(m_[1] - mn1);
        float ps0 = 0.f, ps1 = 0.f;
        #pragma unroll
        for (int nf = 0; nf < 8; nf++) {
            s[nf][0] = ex2(s[nf][0] - mn0);
            s[nf][1] = ex2(s[nf][1] - mn0);
            s[nf][2] = ex2(s[nf][2] - mn1);
            s[nf][3] = ex2(s[nf][3] - mn1);
            ps0 += s[nf][0] + s[nf][1];
            ps1 += s[nf][2] + s[nf][3];
        }
        ps0 += __shfl_xor_sync(0xffffffffu, ps0, 1);
        ps0 += __shfl_xor_sync(0xffffffffu, ps0, 2);
        ps1 += __shfl_xor_sync(0xffffffffu, ps1, 1);
        ps1 += __shfl_xor_sync(0xffffffffu, ps1, 2);
        l_[0] = l_[0] * corr0 + ps0; m_[0] = mn0;
        l_[1] = l_[1] * corr1 + ps1; m_[1] = mn1;
        #pragma unroll
        for (int nf = 0; nf < 8; nf++) {
            o[nf][0] *= corr0; o[nf][1] *= corr0;
            o[nf][2] *= corr1; o[nf][3] *= corr1;
        }

        #pragma unroll
        for (int kc = 0; kc < 4; kc++) {
            uint32_t pa0 = packh2(s[2 * kc][0],     s[2 * kc][1]);
            uint32_t pa1 = packh2(s[2 * kc][2],     s[2 * kc][3]);
            uint32_t pa2 = packh2(s[2 * kc + 1][0], s[2 * kc + 1][1]);
            uint32_t pa3 = packh2(s[2 * kc + 1][2], s[2 * kc + 1][3]);
            #pragma unroll
            for (int nf = 0; nf < 8; nf++) {
                const uint32_t* pb = Vs + (kc * 8 + tig) * 72 + nf * 8 + g;
                hmma(o[nf], pa0, pa1, pa2, pa3, pb[0], pb[4 * 72]);
            }
        }
        __syncthreads();
    }

    float inv0 = 1.0f / l_[0], inv1 = 1.0f / l_[1];
    #pragma unroll
    for (int nf = 0; nf < 8; nf++) {
        int col = h * DH + nf * 8 + 2 * tig;
        *(__half2*)(&g_attn16[((size_t)qg0 * BB + b) * DD + col]) =
            __floats2half2_rn(o[nf][0] * inv0, o[nf][1] * inv0);
        *(__half2*)(&g_attn16[((size_t)qg1 * BB + b) * DD + col]) =
            __floats2half2_rn(o[nf][2] * inv1, o[nf][3] * inv1);
    }
}

// -------------------- launch ------------------------------------------------
extern "C" void kernel_launch(void* const* d_in, const int* in_sizes, int n_in,
                              void* d_out, int out_size) {
    const float* utt      = (const float*)d_in[0];
    const int*   lengths  = (const int*)d_in[1];
    const float* rc       = (const float*)d_in[2];
    const float* summ     = (const float*)d_in[3];
    const float* mem      = (const float*)d_in[4];
    const void*  mask_raw = (const void*)d_in[5];
    const float* w_q   = (const float*)d_in[6];
    const float* b_q   = (const float*)d_in[7];
    const float* w_kv  = (const float*)d_in[8];
    const float* b_kv  = (const float*)d_in[9];
    const float* w_out = (const float*)d_in[10];
    const float* b_out = (const float*)d_in[11];
    float* out = (float*)d_out;

    void *p;
    cudaGetSymbolAddress(&p, g_qin16);  __half* qin16  = (__half*)p;
    cudaGetSymbolAddress(&p, g_kvin16); __half* kvin16 = (__half*)p;
    cudaGetSymbolAddress(&p, g_attn16); __half* attn16 = (__half*)p;
    cudaGetSymbolAddress(&p, g_wqt);    __half* wqt    = (__half*)p;
    cudaGetSymbolAddress(&p, g_wkvt);   __half* wkvt   = (__half*)p;
    cudaGetSymbolAddress(&p, g_wot);    __half* wot    = (__half*)p;

    const int GSM = 18432 * 4;
    cudaFuncSetAttribute(qkv_gemm,
                         cudaFuncAttributeMaxDynamicSharedMemorySize, GSM);
    cudaFuncSetAttribute(out_gemm,
                         cudaFuncAttributeMaxDynamicSharedMemorySize, GSM);
    const int ASM = 13824 * 4;
    cudaFuncSetAttribute(attn_h16,
                         cudaFuncAttributeMaxDynamicSharedMemorySize, ASM);

    // 0. mask prep
    flags_reset<<<1, 1>>>();
    mask_sniff<<<64, 256>>>((const unsigned char*)mask_raw);
    {
        int warps = QL * NWORD;
        mask_pack<<<(warps * 32 + 255) / 256, 256>>>(mask_raw, lengths);
    }

    // 1. gather + fp16 convert inputs
    in_convert<<<2 * MROWS * 128 / 256, 256>>>(utt, rc, summ, mem);

    // 2. weight transpose + fp16 convert
    wconv<512> <<<dim3(16, 16), 256>>>(w_q, wqt);
    wconv<1024><<<dim3(32, 16), 256>>>(w_kv, wkvt);
    wconv<512> <<<dim3(16, 16), 256>>>(w_out, wot);

    // 3. merged Q + KV projection
    qkv_gemm<<<dim3(12, 68), 256, GSM>>>(qin16, kvin16, wqt, wkvt, b_q, b_kv);
    // 4. attention -> g_attn16 (per-batch KV tail skipped)
    attn_h16<<<dim3(QL / 128, BB * NH), 256, ASM>>>(lengths);
    // 5. output projection + slice/clip -> d_out
    out_gemm<<<dim3(4, 68), 256, GSM>>>(attn16, wot, b_out, out);
}

// round 8
// speedup vs baseline: 8.8208x; 1.0429x over previous
#include <cuda_runtime.h>
#include <cuda_fp16.h>
#include <cstdint>

#define UQ   2048
#define BB   4
#define DD   512
#define QL   2176
#define KVL  2176
#define NH   8
#define DH   64
#define NEGINF (-100000000.0f)
#define MROWS (QL*BB)          // 8704
#define RCU_ROWS 2112
#define RCU_SZ (2112*4*512)
#define NWORD 34               // KVL/64
#define QSCALE (0.125f * 1.44269504088896f)   // dh^-0.5 * log2(e)

// -------------------- device scratch ----------------------------------------
__device__ __half g_qin16 [MROWS * DD];
__device__ __half g_kvin16[MROWS * DD];
__device__ __half g_q16   [MROWS * DD];
__device__ __half g_k16   [MROWS * DD];
__device__ __half g_v16   [MROWS * DD];   // k-pair interleaved
__device__ __half g_attn16[MROWS * DD];
__device__ __half g_wqt [512 * 512];
__device__ __half g_wkvt[1024 * 512];
__device__ __half g_wot [512 * 512];
__device__ unsigned long long g_mbits[BB * QL * NWORD];
__device__ int g_flags[3];    // static-zero; set by monotone atomicOr (replay-stable)
__device__ int g_perm[BB];    // batches sorted by length desc (LPT)

// -------------------- helpers ------------------------------------------------
__device__ __forceinline__ void hmma(float* c,
    uint32_t a0, uint32_t a1, uint32_t a2, uint32_t a3,
    uint32_t b0, uint32_t b1) {
    asm volatile(
        "mma.sync.aligned.m16n8k16.row.col.f32.f16.f16.f32 "
        "{%0,%1,%2,%3}, {%4,%5,%6,%7}, {%8,%9}, {%0,%1,%2,%3};\n"
        : "+f"(c[0]), "+f"(c[1]), "+f"(c[2]), "+f"(c[3])
        : "r"(a0), "r"(a1), "r"(a2), "r"(a3), "r"(b0), "r"(b1));
}
__device__ __forceinline__ uint32_t packh2(float lo, float hi) {
    uint32_t r; asm("cvt.rn.f16x2.f32 %0, %1, %2;" : "=r"(r) : "f"(hi), "f"(lo));
    return r;
}
__device__ __forceinline__ float ex2(float x) {
    float r; asm("ex2.approx.f32 %0, %1;" : "=f"(r) : "f"(x)); return r;
}
__device__ __forceinline__ uint32_t s2u(const void* p) {
    return (uint32_t)__cvta_generic_to_shared(p);
}
#define CP16(dst, src) \
    asm volatile("cp.async.cg.shared.global [%0], [%1], 16;\n" :: "r"(dst), "l"(src))
#define CP_COMMIT() asm volatile("cp.async.commit_group;\n")

// -------------------- fused prep: gather/convert + mask sniff + LPT perm -----
__global__ void prep_convert(const float* __restrict__ utt,
                             const float* __restrict__ rc,
                             const float* __restrict__ summ,
                             const float* __restrict__ mem,
                             const unsigned char* __restrict__ rawmask,
                             const int* __restrict__ lengths) {
    const int QN = MROWS * 128;
    int bid = blockIdx.x;
    if (bid < 8704) {
        int i = bid * blockDim.x + threadIdx.x;
        if (i < QN) {
            int row = i >> 7;
            float4 v;
            if (row < 256)       v = ((const float4*)rc)[i];
            else if (row < 8448) v = ((const float4*)utt)[i - 256 * 128];
            else                 v = ((const float4*)summ)[i - 8448 * 128];
            uint2 o; o.x = packh2(v.x, v.y); o.y = packh2(v.z, v.w);
            ((uint2*)g_qin16)[i] = o;
        } else {
            int j = i - QN;
            int row = j >> 7;
            float4 v;
            if (row < 256)      v = ((const float4*)mem)[j];
            else if (row < 512) v = ((const float4*)rc)[j - 256 * 128];
            else                v = ((const float4*)utt)[j - 512 * 128];
            uint2 o; o.x = packh2(v.x, v.y); o.y = packh2(v.z, v.w);
            ((uint2*)g_kvin16)[j] = o;
        }
    } else {
        // mask dtype sniff over first 1MB (buffer >= 4.7MB under all hypotheses)
        int sb = bid - 8704;
        int f0 = 0, f1 = 0, f2 = 0;
        const int SCAN = 1 << 20;
        int stride = 64 * blockDim.x * 4;
        for (int i = (sb * blockDim.x + threadIdx.x) * 4; i < SCAN; i += stride) {
            uchar4 v = *(const uchar4*)(rawmask + i);
            if (v.x > 1 || v.y > 1) f0 = 1;
            if (v.z > 1 || v.w > 1) f1 = 1;
            if (v.y | v.z | v.w)    f2 = 1;
        }
        if (f0) atomicOr(&g_flags[0], 1);
        if (f1) atomicOr(&g_flags[1], 1);
        if (f2) atomicOr(&g_flags[2], 1);
        if (sb == 0 && threadIdx.x == 0) {
            // LPT permutation: batches sorted by length descending
            int len[BB], idx[BB];
            for (int i = 0; i < BB; i++) { len[i] = __ldg(lengths + i); idx[i] = i; }
            for (int i = 1; i < BB; i++) {
                int l = len[i], ix = idx[i], j = i - 1;
                while (j >= 0 && len[j] < l) {
                    len[j + 1] = len[j]; idx[j + 1] = idx[j]; j--;
                }
                len[j + 1] = l; idx[j + 1] = ix;
            }
            for (int i = 0; i < BB; i++) g_perm[i] = idx[i];
        }
    }
}

// -------------------- mask pack (ballot -> uint64, pad folded per batch) -----
__global__ void mask_pack(const void* __restrict__ raw,
                          const int* __restrict__ lengths) {
    int warp = (blockIdx.x * blockDim.x + threadIdx.x) >> 5;
    int lane = threadIdx.x & 31;
    if (warp >= QL * NWORD) return;
    int q = warp / NWORD, w = warp - q * NWORD;

    int kind;
    if (g_flags[0])      kind = 3;   // bf16
    else if (g_flags[1]) kind = 2;   // f32
    else if (g_flags[2]) kind = 0;   // u8
    else                 kind = 1;   // i32

    size_t base = (size_t)q * KVL + w * 64;
    bool m0, m1;
    if (kind == 0) {
        const unsigned char* p = (const unsigned char*)raw;
        m0 = p[base + lane] != 0; m1 = p[base + 32 + lane] != 0;
    } else if (kind == 1) {
        const int* p = (const int*)raw;
        m0 = p[base + lane] != 0; m1 = p[base + 32 + lane] != 0;
    } else if (kind == 2) {
        const float* p = (const float*)raw;
        m0 = p[base + lane] != 0.f; m1 = p[base + 32 + lane] != 0.f;
    } else {
        const unsigned short* p = (const unsigned short*)raw;
        m0 = (p[base + lane] & 0x7fff) != 0;
        m1 = (p[base + 32 + lane] & 0x7fff) != 0;
    }
    uint32_t lo = __ballot_sync(0xffffffffu, m0);
    uint32_t hi = __ballot_sync(0xffffffffu, m1);
    unsigned long long word = (unsigned long long)lo |
                              ((unsigned long long)hi << 32);
    if (lane < 4) {
        int limit = 128 + __ldg(lengths + lane);
        int k0 = w * 64;
        unsigned long long pad;
        if (limit <= k0)           pad = ~0ull;
        else if (limit >= k0 + 64) pad = 0ull;
        else                       pad = (~0ull) << (limit - k0);
        g_mbits[((size_t)lane * QL + q) * NWORD + w] = word | pad;
    }
}

// -------------------- fused weight transpose + fp16 convert -------------------
__global__ void wconv_all(const float* __restrict__ wq,
                          const float* __restrict__ wkv,
                          const float* __restrict__ wo) {
    __shared__ float tile[32][33];
    int bid = blockIdx.x;
    const float* W; __half* Wt; int NN, bx, by;
    if (bid < 256)      { W = wq;  Wt = g_wqt;  NN = 512;  bx = bid & 15; by = bid >> 4; }
    else if (bid < 768) { int b2 = bid - 256; W = wkv; Wt = g_wkvt; NN = 1024; bx = b2 & 31; by = b2 >> 5; }
    else                { int b2 = bid - 768; W = wo;  Wt = g_wot;  NN = 512;  bx = b2 & 15; by = b2 >> 4; }
    int x = threadIdx.x & 31, y0 = threadIdx.x >> 5;
    #pragma unroll
    for (int yy = y0; yy < 32; yy += 8)
        tile[yy][x] = W[(size_t)(by * 32 + yy) * NN + bx * 32 + x];
    __syncthreads();
    #pragma unroll
    for (int yy = y0; yy < 32; yy += 8)
        Wt[(size_t)(bx * 32 + yy) * 512 + by * 32 + x] =
            __float2half_rn(tile[x][yy]);
}

// -------------------- fp16 GEMM core -----------------------------------------
struct GemmAcc { float a[2][8][4]; };

__device__ __forceinline__ void gemm_main(uint32_t* sm, const __half* A,
                                          const __half* Wt, int m0, int n0,
                                          GemmAcc& acc) {
    const int tid = threadIdx.x;
    const int wid = tid >> 5, lane = tid & 31;
    const int g = lane >> 2, tig = lane & 3;
    const int wm = wid & 3, wn = wid >> 2;

    #pragma unroll
    for (int mf = 0; mf < 2; mf++)
        #pragma unroll
        for (int nf = 0; nf < 8; nf++)
            #pragma unroll
            for (int e = 0; e < 4; e++) acc.a[mf][nf][e] = 0.f;

    auto issue = [&](int t) {
        int k0 = t * 64;
        uint32_t* As = sm + (t & 1) * 4608;
        uint32_t* Bs = sm + 9216 + (t & 1) * 4608;
        #pragma unroll
        for (int l = 0; l < 4; l++) {
            int item = tid + l * 256;
            int row = item >> 3, c = item & 7;
            CP16(s2u(As + row * 36 + c * 4),
                 A + (size_t)(m0 + row) * 512 + k0 + c * 8);
        }
        #pragma unroll
        for (int l = 0; l < 4; l++) {
            int item = tid + l * 256;
            int row = item >> 3, c = item & 7;
            CP16(s2u(Bs + row * 36 + c * 4),
                 Wt + (size_t)(n0 + row) * 512 + k0 + c * 8);
        }
        CP_COMMIT();
    };

    issue(0);
    #pragma unroll 1
    for (int t = 0; t < 8; t++) {
        if (t + 1 < 8) {
            issue(t + 1);
            asm volatile("cp.async.wait_group 1;\n");
        } else {
            asm volatile("cp.async.wait_group 0;\n");
        }
        __syncthreads();
        const uint32_t* As = sm + (t & 1) * 4608;
        const uint32_t* Bs = sm + 9216 + (t & 1) * 4608;
        #pragma unroll
        for (int kc = 0; kc < 4; kc++) {
            uint32_t a[2][4];
            #pragma unroll
            for (int mf = 0; mf < 2; mf++) {
                const uint32_t* pa = As + (wm * 32 + mf * 16 + g) * 36 + kc * 8 + tig;
                a[mf][0] = pa[0];
                a[mf][1] = pa[8 * 36];
                a[mf][2] = pa[4];
                a[mf][3] = pa[8 * 36 + 4];
            }
            #pragma unroll
            for (int nf = 0; nf < 8; nf++) {
                const uint32_t* pb = Bs + (wn * 64 + nf * 8 + g) * 36 + kc * 8 + tig;
                uint32_t b0 = pb[0], b1 = pb[4];
                hmma(acc.a[0][nf], a[0][0], a[0][1], a[0][2], a[0][3], b0, b1);
                hmma(acc.a[1][nf], a[1][0], a[1][1], a[1][2], a[1][3], b0, b1);
            }
        }
        __syncthreads();
    }
}

// -------------------- merged Q + KV projection -------------------------------
__global__ __launch_bounds__(256, 2)
void qkv_gemm(const __half* __restrict__ qA, const __half* __restrict__ kvA,
              const __half* __restrict__ wq, const __half* __restrict__ wkv,
              const float* __restrict__ bq, const float* __restrict__ bkv) {
    extern __shared__ uint32_t sm[];
    const bool isQ = blockIdx.x < 4;
    const int n0 = isQ ? blockIdx.x * 128 : (blockIdx.x - 4) * 128;
    const int m0 = blockIdx.y * 128;
    const __half* A  = isQ ? qA : kvA;
    const __half* Wt = isQ ? wq : wkv;
    const float* bias = isQ ? bq : bkv;

    GemmAcc acc;
    gemm_main(sm, A, Wt, m0, n0, acc);

    const int lane = threadIdx.x & 31, wid = threadIdx.x >> 5;
    const int g = lane >> 2, tig = lane & 3;
    const int wm = wid & 3, wn = wid >> 2;
    #pragma unroll
    for (int mf = 0; mf < 2; mf++) {
        int row0 = m0 + wm * 32 + mf * 16 + g;
        int row1 = row0 + 8;
        #pragma unroll
        for (int nf = 0; nf < 8; nf++) {
            int col = n0 + wn * 64 + nf * 8 + 2 * tig;
            float bi0 = __ldg(bias + col), bi1 = __ldg(bias + col + 1);
            float v00 = acc.a[mf][nf][0] + bi0, v01 = acc.a[mf][nf][1] + bi1;
            float v10 = acc.a[mf][nf][2] + bi0, v11 = acc.a[mf][nf][3] + bi1;
            if (isQ) {
                *(__half2*)(&g_q16[(size_t)row0 * DD + col]) =
                    __floats2half2_rn(v00 * QSCALE, v01 * QSCALE);
                *(__half2*)(&g_q16[(size_t)row1 * DD + col]) =
                    __floats2half2_rn(v10 * QSCALE, v11 * QSCALE);
            } else if (col < 512) {
                *(__half2*)(&g_k16[(size_t)row0 * DD + col]) =
                    __floats2half2_rn(v00, v01);
                *(__half2*)(&g_k16[(size_t)row1 * DD + col]) =
                    __floats2half2_rn(v10, v11);
            } else {
                int vc = col - 512;
                int rows[2] = {row0, row1};
                float vs[2][2] = {{v00, v01}, {v10, v11}};
                #pragma unroll
                for (int r = 0; r < 2; r++) {
                    int k = rows[r] >> 2, b = rows[r] & 3;
                    size_t base = (((size_t)(k >> 1) * BB + b) * DD + vc) * 2 + (k & 1);
                    g_v16[base]     = __float2half_rn(vs[r][0]);
                    g_v16[base + 2] = __float2half_rn(vs[r][1]);
                }
            }
        }
    }
}

// -------------------- output projection (slice/clip scatter) -----------------
__global__ __launch_bounds__(256, 2)
void out_gemm(const __half* __restrict__ A, const __half* __restrict__ Wt,
              const float* __restrict__ bias, float* __restrict__ C) {
    extern __shared__ uint32_t sm[];
    const int m0 = blockIdx.y * 128, n0 = blockIdx.x * 128;
    GemmAcc acc;
    gemm_main(sm, A, Wt, m0, n0, acc);

    const int lane = threadIdx.x & 31, wid = threadIdx.x >> 5;
    const int g = lane >> 2, tig = lane & 3;
    const int wm = wid & 3, wn = wid >> 2;
    #pragma unroll
    for (int mf = 0; mf < 2; mf++) {
        int row0 = m0 + wm * 32 + mf * 16 + g;
        #pragma unroll
        for (int nf = 0; nf < 8; nf++) {
            int col = n0 + wn * 64 + nf * 8 + 2 * tig;
            float bi0 = __ldg(bias + col), bi1 = __ldg(bias + col + 1);
            float vs[2][2] = {
                {acc.a[mf][nf][0] + bi0, acc.a[mf][nf][1] + bi1},
                {acc.a[mf][nf][2] + bi0, acc.a[mf][nf][3] + bi1}};
            #pragma unroll
            for (int r = 0; r < 2; r++) {
                int m = row0 + r * 8;
                int q = m >> 2, b = m & 3;
                if (q < RCU_ROWS) {
                    *(float2*)(C + (size_t)m * DD + col) =
                        make_float2(vs[r][0], vs[r][1]);
                } else if (q < QL - 1) {
                    float a0 = fminf(fmaxf(vs[r][0], -10.f), 10.f);
                    float a1 = fminf(fmaxf(vs[r][1], -10.f), 10.f);
                    *(float2*)(C + RCU_SZ +
                        (size_t)((q - RCU_ROWS) * BB + b) * DD + col) =
                        make_float2(a0, a1);
                }
            }
        }
    }
}

// -------------------- fp16 flash attention (3-stage pipeline) -----------------
// smem (u32): Qs[4608] | stage0[4608] | stage1[4608] | stage2[4608]
__global__ __launch_bounds__(256)
void attn_h16(const int* __restrict__ lengths) {
    extern __shared__ uint32_t sm[];
    uint32_t* Qs = sm;

    const int tid = threadIdx.x;
    const int wid = tid >> 5, lane = tid & 31;
    const int g = lane >> 2, tig = lane & 3;
    const int b = g_perm[blockIdx.y >> 3];        // LPT: longest batches first
    const int h = blockIdx.y & 7;
    const int q0 = blockIdx.x * 128;
    const int wrow = wid * 16;
    const int qg0 = q0 + wrow + g;
    const int qg1 = qg0 + 8;
    const unsigned long long* mrow0 = g_mbits + ((size_t)b * QL + qg0) * NWORD;
    const unsigned long long* mrow1 = g_mbits + ((size_t)b * QL + qg1) * NWORD;

    const int limit = 128 + __ldg(lengths + b);
    const int NTb = min(NWORD, (limit + 63) >> 6);

    auto load_kv = [&](int t, uint32_t* stage) {
        int k0 = t * 64;
        uint32_t* Ks = stage;
        uint32_t* Vs = stage + 2304;
        #pragma unroll
        for (int l = 0; l < 2; l++) {
            int item = tid + l * 256;
            int row = item >> 3, c = item & 7;
            const __half* src = g_k16 + ((size_t)(k0 + row) * BB + b) * DD + h * DH + c * 8;
            CP16(s2u(Ks + row * 36 + c * 4), src);
        }
        int p0 = k0 >> 1;
        #pragma unroll
        for (int l = 0; l < 2; l++) {
            int item = tid + l * 256;
            int row = item >> 4, c = item & 15;
            const __half* src = g_v16 + (((size_t)(p0 + row) * BB + b) * DD + h * DH + c * 4) * 2;
            CP16(s2u(Vs + row * 72 + c * 4), src);
        }
    };

    // prologue: group0 = Q + KV(0), group1 = KV(1)
    #pragma unroll
    for (int l = 0; l < 4; l++) {
        int item = tid + l * 256;
        int row = item >> 3, c = item & 7;
        const __half* src = g_q16 + ((size_t)(q0 + row) * BB + b) * DD + h * DH + c * 8;
        CP16(s2u(Qs + row * 36 + c * 4), src);
    }
    load_kv(0, sm + 4608);
    CP_COMMIT();
    if (1 < NTb) load_kv(1, sm + 4608 + 4608);
    CP_COMMIT();

    float m_[2] = {-3.0e38f, -3.0e38f};
    float l_[2] = {0.f, 0.f};
    float o[8][4];
    #pragma unroll
    for (int nf = 0; nf < 8; nf++)
        #pragma unroll
        for (int e = 0; e < 4; e++) o[nf][e] = 0.f;

    int st = 0, st2 = 2;   // current stage, stage for t+2
    #pragma unroll 1
    for (int t = 0; t < NTb; t++) {
        unsigned long long w0 = mrow0[t], w1 = mrow1[t];

        // issue tile t+2 into the buffer tile t-1 vacated (barrier at loop end
        // of iter t-1 guarantees it's free); exactly one group per iteration.
        if (t + 2 < NTb) load_kv(t + 2, sm + 4608 + st2 * 4608);
        CP_COMMIT();
        asm volatile("cp.async.wait_group 2;\n");   // group t complete
        __syncthreads();

        uint32_t* Ks = sm + 4608 + st * 4608;
        uint32_t* Vs = Ks + 2304;

        float s[8][4];
        #pragma unroll
        for (int nf = 0; nf < 8; nf++)
            #pragma unroll
            for (int e = 0; e < 4; e++) s[nf][e] = 0.f;
        #pragma unroll
        for (int kc = 0; kc < 4; kc++) {
            const uint32_t* pa = Qs + (wrow + g) * 36 + kc * 8 + tig;
            uint32_t a0 = pa[0], a1 = pa[8 * 36], a2 = pa[4], a3 = pa[8 * 36 + 4];
            #pragma unroll
            for (int nf = 0; nf < 8; nf++) {
                const uint32_t* pb = Ks + (nf * 8 + g) * 36 + kc * 8 + tig;
                hmma(s[nf], a0, a1, a2, a3, pb[0], pb[4]);
            }
        }

        #pragma unroll
        for (int nf = 0; nf < 8; nf++) {
            int sh = nf * 8 + 2 * tig;
            uint32_t b0 = (uint32_t)(w0 >> sh);
            uint32_t b1 = (uint32_t)(w1 >> sh);
            if (b0 & 1) s[nf][0] = NEGINF;
            if (b0 & 2) s[nf][1] = NEGINF;
            if (b1 & 1) s[nf][2] = NEGINF;
            if (b1 & 2) s[nf][3] = NEGINF;
        }

        float tm0 = -3.0e38f, tm1 = -3.0e38f;
        #pragma unroll
        for (int nf = 0; nf < 8; nf++) {
            tm0 = fmaxf(tm0, fmaxf(s[nf][0], s[nf][1]));
            tm1 = fmaxf(tm1, fmaxf(s[nf][2], s[nf][3]));
        }
        tm0 = fmaxf(tm0, __shfl_xor_sync(0xffffffffu, tm0, 1));
        tm0 = fmaxf(tm0, __shfl_xor_sync(0xffffffffu, tm0, 2));
        tm1 = fmaxf(tm1, __shfl_xor_sync(0xffffffffu, tm1, 1));
        tm1 = fmaxf(tm1, __shfl_xor_sync(0xffffffffu, tm1, 2));
        float mn0 = fmaxf(m_[0], tm0), mn1 = fmaxf(m_[1], tm1);
        float corr0 = ex2(m_[0] - mn0), corr1 = ex2(m_[1] - mn1);
        float ps0 = 0.f, ps1 = 0.f;
        #pragma unroll
        for (int nf = 0; nf < 8; nf++) {
            s[nf][0] = ex2(s[nf][0] - mn0);
            s[nf][1] = ex2(s[nf][1] - mn0);
            s[nf][2] = ex2(s[nf][2] - mn1);
            s[nf][3] = ex2(s[nf][3] - mn1);
            ps0 += s[nf][0] + s[nf][1];
            ps1 += s[nf][2] + s[nf][3];
        }
        ps0 += __shfl_xor_sync(0xffffffffu, ps0, 1);
        ps0 += __shfl_xor_sync(0xffffffffu, ps0, 2);
        ps1 += __shfl_xor_sync(0xffffffffu, ps1, 1);
        ps1 += __shfl_xor_sync(0xffffffffu, ps1, 2);
        l_[0] = l_[0] * corr0 + ps0; m_[0] = mn0;
        l_[1] = l_[1] * corr1 + ps1; m_[1] = mn1;
        #pragma unroll
        for (int nf = 0; nf < 8; nf++) {
            o[nf][0] *= corr0; o[nf][1] *= corr0;
            o[nf][2] *= corr1; o[nf][3] *= corr1;
        }

        #pragma unroll
        for (int kc = 0; kc < 4; kc++) {
            uint32_t pa0 = packh2(s[2 * kc][0],     s[2 * kc][1]);
            uint32_t pa1 = packh2(s[2 * kc][2],     s[2 * kc][3]);
            uint32_t pa2 = packh2(s[2 * kc + 1][0], s[2 * kc + 1][1]);
            uint32_t pa3 = packh2(s[2 * kc + 1][2], s[2 * kc + 1][3]);
            #pragma unroll
            for (int nf = 0; nf < 8; nf++) {
                const uint32_t* pb = Vs + (kc * 8 + tig) * 72 + nf * 8 + g;
                hmma(o[nf], pa0, pa1, pa2, pa3, pb[0], pb[4 * 72]);
            }
        }
        __syncthreads();   // stage st free for reuse by iteration t+1's issue

        st  = (st  == 2) ? 0 : st + 1;
        st2 = (st2 == 2) ? 0 : st2 + 1;
    }

    float inv0 = 1.0f / l_[0], inv1 = 1.0f / l_[1];
    #pragma unroll
    for (int nf = 0; nf < 8; nf++) {
        int col = h * DH + nf * 8 + 2 * tig;
        *(__half2*)(&g_attn16[((size_t)qg0 * BB + b) * DD + col]) =
            __floats2half2_rn(o[nf][0] * inv0, o[nf][1] * inv0);
        *(__half2*)(&g_attn16[((size_t)qg1 * BB + b) * DD + col]) =
            __floats2half2_rn(o[nf][2] * inv1, o[nf][3] * inv1);
    }
}

// -------------------- launch ------------------------------------------------
extern "C" void kernel_launch(void* const* d_in, const int* in_sizes, int n_in,
                              void* d_out, int out_size) {
    const float* utt      = (const float*)d_in[0];
    const int*   lengths  = (const int*)d_in[1];
    const float* rc       = (const float*)d_in[2];
    const float* summ     = (const float*)d_in[3];
    const float* mem      = (const float*)d_in[4];
    const void*  mask_raw = (const void*)d_in[5];
    const float* w_q   = (const float*)d_in[6];
    const float* b_q   = (const float*)d_in[7];
    const float* w_kv  = (const float*)d_in[8];
    const float* b_kv  = (const float*)d_in[9];
    const float* w_out = (const float*)d_in[10];
    const float* b_out = (const float*)d_in[11];
    float* out = (float*)d_out;

    void *p;
    cudaGetSymbolAddress(&p, g_qin16);  __half* qin16  = (__half*)p;
    cudaGetSymbolAddress(&p, g_kvin16); __half* kvin16 = (__half*)p;
    cudaGetSymbolAddress(&p, g_attn16); __half* attn16 = (__half*)p;
    cudaGetSymbolAddress(&p, g_wqt);    __half* wqt    = (__half*)p;
    cudaGetSymbolAddress(&p, g_wkvt);   __half* wkvt   = (__half*)p;
    cudaGetSymbolAddress(&p, g_wot);    __half* wot    = (__half*)p;

    const int GSM = 18432 * 4;
    cudaFuncSetAttribute(qkv_gemm,
                         cudaFuncAttributeMaxDynamicSharedMemorySize, GSM);
    cudaFuncSetAttribute(out_gemm,
                         cudaFuncAttributeMaxDynamicSharedMemorySize, GSM);
    const int ASM = 18432 * 4;   // Q + 3 stages
    cudaFuncSetAttribute(attn_h16,
                         cudaFuncAttributeMaxDynamicSharedMemorySize, ASM);

    // 1. fused: gather+convert inputs, mask dtype sniff, LPT perm
    prep_convert<<<8704 + 64, 256>>>(utt, rc, summ, mem,
                                     (const unsigned char*)mask_raw, lengths);
    // 2. fused weight transposes
    wconv_all<<<1024, 256>>>(w_q, w_kv, w_out);
    // 3. mask pack (needs sniff flags)
    {
        int warps = QL * NWORD;
        mask_pack<<<(warps * 32 + 255) / 256, 256>>>(mask_raw, lengths);
    }
    // 4. merged Q + KV projection
    qkv_gemm<<<dim3(12, 68), 256, GSM>>>(qin16, kvin16, wqt, wkvt, b_q, b_kv);
    // 5. attention (3-stage pipeline, LPT order, tail skip)
    attn_h16<<<dim3(QL / 128, BB * NH), 256, ASM>>>(lengths);
    // 6. output projection + slice/clip -> d_out
    out_gemm<<<dim3(4, 68), 256, GSM>>>(attn16, wot, b_out, out);
}

// round 9
// speedup vs baseline: 9.4879x; 1.0756x over previous
#include <cuda_runtime.h>
#include <cuda_fp16.h>
#include <cstdint>

#define UQ   2048
#define BB   4
#define DD   512
#define QL   2176
#define KVL  2176
#define NH   8
#define DH   64
#define NEGINF (-100000000.0f)
#define MROWS (QL*BB)          // 8704
#define RCU_ROWS 2112
#define RCU_SZ (2112*4*512)
#define NWORD 34               // KVL/64
#define QSCALE (0.125f * 1.44269504088896f)   // dh^-0.5 * log2(e)

// -------------------- device scratch ----------------------------------------
__device__ __half g_qin16 [MROWS * DD];
__device__ __half g_kvin16[MROWS * DD];
__device__ __half g_q16   [MROWS * DD];
__device__ __half g_k16   [MROWS * DD];
__device__ __half g_v16   [MROWS * DD];   // plain [token*BB+b][dh] (same as K)
__device__ __half g_attn16[MROWS * DD];
__device__ __half g_wqt [512 * 512];
__device__ __half g_wkvt[1024 * 512];
__device__ __half g_wot [512 * 512];
__device__ unsigned long long g_mbits[BB * QL * NWORD];
__device__ int g_flags[3];    // static-zero; monotone atomicOr (replay-stable)
__device__ int g_perm[BB];    // batches sorted by length desc (LPT)

// -------------------- helpers ------------------------------------------------
__device__ __forceinline__ void hmma(float* c,
    uint32_t a0, uint32_t a1, uint32_t a2, uint32_t a3,
    uint32_t b0, uint32_t b1) {
    asm volatile(
        "mma.sync.aligned.m16n8k16.row.col.f32.f16.f16.f32 "
        "{%0,%1,%2,%3}, {%4,%5,%6,%7}, {%8,%9}, {%0,%1,%2,%3};\n"
        : "+f"(c[0]), "+f"(c[1]), "+f"(c[2]), "+f"(c[3])
        : "r"(a0), "r"(a1), "r"(a2), "r"(a3), "r"(b0), "r"(b1));
}
__device__ __forceinline__ void ldsm4(uint32_t& r0, uint32_t& r1,
                                      uint32_t& r2, uint32_t& r3, uint32_t a) {
    asm volatile("ldmatrix.sync.aligned.m8n8.x4.shared.b16 {%0,%1,%2,%3}, [%4];"
        : "=r"(r0), "=r"(r1), "=r"(r2), "=r"(r3) : "r"(a));
}
__device__ __forceinline__ void ldsm4t(uint32_t& r0, uint32_t& r1,
                                       uint32_t& r2, uint32_t& r3, uint32_t a) {
    asm volatile("ldmatrix.sync.aligned.m8n8.x4.trans.shared.b16 {%0,%1,%2,%3}, [%4];"
        : "=r"(r0), "=r"(r1), "=r"(r2), "=r"(r3) : "r"(a));
}
__device__ __forceinline__ uint32_t packh2(float lo, float hi) {
    uint32_t r; asm("cvt.rn.f16x2.f32 %0, %1, %2;" : "=r"(r) : "f"(hi), "f"(lo));
    return r;
}
__device__ __forceinline__ float ex2(float x) {
    float r; asm("ex2.approx.f32 %0, %1;" : "=f"(r) : "f"(x)); return r;
}
__device__ __forceinline__ uint32_t s2u(const void* p) {
    return (uint32_t)__cvta_generic_to_shared(p);
}
#define CP16(dst, src) \
    asm volatile("cp.async.cg.shared.global [%0], [%1], 16;\n" :: "r"(dst), "l"(src))
#define CP_COMMIT() asm volatile("cp.async.commit_group;\n")

// -------------------- fused prep: gather/convert + mask sniff + LPT perm -----
__global__ void prep_convert(const float* __restrict__ utt,
                             const float* __restrict__ rc,
                             const float* __restrict__ summ,
                             const float* __restrict__ mem,
                             const unsigned char* __restrict__ rawmask,
                             const int* __restrict__ lengths) {
    const int QN = MROWS * 128;
    int bid = blockIdx.x;
    if (bid < 8704) {
        int i = bid * blockDim.x + threadIdx.x;
        if (i < QN) {
            int row = i >> 7;
            float4 v;
            if (row < 256)       v = ((const float4*)rc)[i];
            else if (row < 8448) v = ((const float4*)utt)[i - 256 * 128];
            else                 v = ((const float4*)summ)[i - 8448 * 128];
            uint2 o; o.x = packh2(v.x, v.y); o.y = packh2(v.z, v.w);
            ((uint2*)g_qin16)[i] = o;
        } else {
            int j = i - QN;
            int row = j >> 7;
            float4 v;
            if (row < 256)      v = ((const float4*)mem)[j];
            else if (row < 512) v = ((const float4*)rc)[j - 256 * 128];
            else                v = ((const float4*)utt)[j - 512 * 128];
            uint2 o; o.x = packh2(v.x, v.y); o.y = packh2(v.z, v.w);
            ((uint2*)g_kvin16)[j] = o;
        }
    } else {
        int sb = bid - 8704;
        int f0 = 0, f1 = 0, f2 = 0;
        const int SCAN = 1 << 20;
        int stride = 64 * blockDim.x * 4;
        for (int i = (sb * blockDim.x + threadIdx.x) * 4; i < SCAN; i += stride) {
            uchar4 v = *(const uchar4*)(rawmask + i);
            if (v.x > 1 || v.y > 1) f0 = 1;
            if (v.z > 1 || v.w > 1) f1 = 1;
            if (v.y | v.z | v.w)    f2 = 1;
        }
        if (f0) atomicOr(&g_flags[0], 1);
        if (f1) atomicOr(&g_flags[1], 1);
        if (f2) atomicOr(&g_flags[2], 1);
        if (sb == 0 && threadIdx.x == 0) {
            int len[BB], idx[BB];
            for (int i = 0; i < BB; i++) { len[i] = __ldg(lengths + i); idx[i] = i; }
            for (int i = 1; i < BB; i++) {
                int l = len[i], ix = idx[i], j = i - 1;
                while (j >= 0 && len[j] < l) {
                    len[j + 1] = len[j]; idx[j + 1] = idx[j]; j--;
                }
                len[j + 1] = l; idx[j + 1] = ix;
            }
            for (int i = 0; i < BB; i++) g_perm[i] = idx[i];
        }
    }
}

// -------------------- mask pack ----------------------------------------------
__global__ void mask_pack(const void* __restrict__ raw,
                          const int* __restrict__ lengths) {
    int warp = (blockIdx.x * blockDim.x + threadIdx.x) >> 5;
    int lane = threadIdx.x & 31;
    if (warp >= QL * NWORD) return;
    int q = warp / NWORD, w = warp - q * NWORD;

    int kind;
    if (g_flags[0])      kind = 3;
    else if (g_flags[1]) kind = 2;
    else if (g_flags[2]) kind = 0;
    else                 kind = 1;

    size_t base = (size_t)q * KVL + w * 64;
    bool m0, m1;
    if (kind == 0) {
        const unsigned char* p = (const unsigned char*)raw;
        m0 = p[base + lane] != 0; m1 = p[base + 32 + lane] != 0;
    } else if (kind == 1) {
        const int* p = (const int*)raw;
        m0 = p[base + lane] != 0; m1 = p[base + 32 + lane] != 0;
    } else if (kind == 2) {
        const float* p = (const float*)raw;
        m0 = p[base + lane] != 0.f; m1 = p[base + 32 + lane] != 0.f;
    } else {
        const unsigned short* p = (const unsigned short*)raw;
        m0 = (p[base + lane] & 0x7fff) != 0;
        m1 = (p[base + 32 + lane] & 0x7fff) != 0;
    }
    uint32_t lo = __ballot_sync(0xffffffffu, m0);
    uint32_t hi = __ballot_sync(0xffffffffu, m1);
    unsigned long long word = (unsigned long long)lo |
                              ((unsigned long long)hi << 32);
    if (lane < 4) {
        int limit = 128 + __ldg(lengths + lane);
        int k0 = w * 64;
        unsigned long long pad;
        if (limit <= k0)           pad = ~0ull;
        else if (limit >= k0 + 64) pad = 0ull;
        else                       pad = (~0ull) << (limit - k0);
        g_mbits[((size_t)lane * QL + q) * NWORD + w] = word | pad;
    }
}

// -------------------- fused weight transpose + fp16 convert -------------------
__global__ void wconv_all(const float* __restrict__ wq,
                          const float* __restrict__ wkv,
                          const float* __restrict__ wo) {
    __shared__ float tile[32][33];
    int bid = blockIdx.x;
    const float* W; __half* Wt; int NN, bx, by;
    if (bid < 256)      { W = wq;  Wt = g_wqt;  NN = 512;  bx = bid & 15; by = bid >> 4; }
    else if (bid < 768) { int b2 = bid - 256; W = wkv; Wt = g_wkvt; NN = 1024; bx = b2 & 31; by = b2 >> 5; }
    else                { int b2 = bid - 768; W = wo;  Wt = g_wot;  NN = 512;  bx = b2 & 15; by = b2 >> 4; }
    int x = threadIdx.x & 31, y0 = threadIdx.x >> 5;
    #pragma unroll
    for (int yy = y0; yy < 32; yy += 8)
        tile[yy][x] = W[(size_t)(by * 32 + yy) * NN + bx * 32 + x];
    __syncthreads();
    #pragma unroll
    for (int yy = y0; yy < 32; yy += 8)
        Wt[(size_t)(bx * 32 + yy) * 512 + by * 32 + x] =
            __float2half_rn(tile[x][yy]);
}

// -------------------- fp16 GEMM core (ldmatrix fragments) --------------------
struct GemmAcc { float a[2][8][4]; };

__device__ __forceinline__ void gemm_main(uint32_t* sm, const __half* A,
                                          const __half* Wt, int m0, int n0,
                                          GemmAcc& acc) {
    const int tid = threadIdx.x;
    const int wid = tid >> 5, lane = tid & 31;
    const int qq = lane >> 3, rr = lane & 7;
    const int wm = wid & 3, wn = wid >> 2;

    // ldmatrix lane offsets (u32 units within the tile buffer)
    // A tiles: row = base + ((qq&1)<<3) + rr, col = kc*8 + ((qq>>1)<<2)
    const uint32_t a_off = (uint32_t)((((qq & 1) << 3) + rr) * 36 + ((qq >> 1) << 2));
    // B tiles: row = wn*64 + 16P + ((qq>>1)<<3) + rr, col = kc*8 + ((qq&1)<<2)
    const uint32_t b_off = (uint32_t)(((wn * 64) + ((qq >> 1) << 3) + rr) * 36 + ((qq & 1) << 2));

    #pragma unroll
    for (int mf = 0; mf < 2; mf++)
        #pragma unroll
        for (int nf = 0; nf < 8; nf++)
            #pragma unroll
            for (int e = 0; e < 4; e++) acc.a[mf][nf][e] = 0.f;

    auto issue = [&](int t) {
        int k0 = t * 64;
        uint32_t* As = sm + (t & 1) * 4608;
        uint32_t* Bs = sm + 9216 + (t & 1) * 4608;
        #pragma unroll
        for (int l = 0; l < 4; l++) {
            int item = tid + l * 256;
            int row = item >> 3, c = item & 7;
            CP16(s2u(As + row * 36 + c * 4),
                 A + (size_t)(m0 + row) * 512 + k0 + c * 8);
        }
        #pragma unroll
        for (int l = 0; l < 4; l++) {
            int item = tid + l * 256;
            int row = item >> 3, c = item & 7;
            CP16(s2u(Bs + row * 36 + c * 4),
                 Wt + (size_t)(n0 + row) * 512 + k0 + c * 8);
        }
        CP_COMMIT();
    };

    issue(0);
    #pragma unroll 1
    for (int t = 0; t < 8; t++) {
        if (t + 1 < 8) {
            issue(t + 1);
            asm volatile("cp.async.wait_group 1;\n");
        } else {
            asm volatile("cp.async.wait_group 0;\n");
        }
        __syncthreads();
        uint32_t as_base = s2u(sm + (t & 1) * 4608) + a_off * 4;
        uint32_t bs_base = s2u(sm + 9216 + (t & 1) * 4608) + b_off * 4;
        #pragma unroll
        for (int kc = 0; kc < 4; kc++) {
            uint32_t a[2][4];
            #pragma unroll
            for (int mf = 0; mf < 2; mf++)
                ldsm4(a[mf][0], a[mf][1], a[mf][2], a[mf][3],
                      as_base + (uint32_t)(((wm * 32 + mf * 16) * 36 + kc * 8) * 4));
            #pragma unroll
            for (int P = 0; P < 4; P++) {
                uint32_t b0, b1, b2, b3;
                ldsm4(b0, b1, b2, b3,
                      bs_base + (uint32_t)((P * 16 * 36 + kc * 8) * 4));
                hmma(acc.a[0][2 * P],     a[0][0], a[0][1], a[0][2], a[0][3], b0, b1);
                hmma(acc.a[1][2 * P],     a[1][0], a[1][1], a[1][2], a[1][3], b0, b1);
                hmma(acc.a[0][2 * P + 1], a[0][0], a[0][1], a[0][2], a[0][3], b2, b3);
                hmma(acc.a[1][2 * P + 1], a[1][0], a[1][1], a[1][2], a[1][3], b2, b3);
            }
        }
        __syncthreads();
    }
}

// -------------------- merged Q + KV projection -------------------------------
__global__ __launch_bounds__(256, 2)
void qkv_gemm(const __half* __restrict__ qA, const __half* __restrict__ kvA,
              const __half* __restrict__ wq, const __half* __restrict__ wkv,
              const float* __restrict__ bq, const float* __restrict__ bkv) {
    extern __shared__ uint32_t sm[];
    const bool isQ = blockIdx.x < 4;
    const int n0 = isQ ? blockIdx.x * 128 : (blockIdx.x - 4) * 128;
    const int m0 = blockIdx.y * 128;
    const __half* A  = isQ ? qA : kvA;
    const __half* Wt = isQ ? wq : wkv;
    const float* bias = isQ ? bq : bkv;

    GemmAcc acc;
    gemm_main(sm, A, Wt, m0, n0, acc);

    const int lane = threadIdx.x & 31, wid = threadIdx.x >> 5;
    const int g = lane >> 2, tig = lane & 3;
    const int wm = wid & 3, wn = wid >> 2;
    #pragma unroll
    for (int mf = 0; mf < 2; mf++) {
        int row0 = m0 + wm * 32 + mf * 16 + g;
        int row1 = row0 + 8;
        #pragma unroll
        for (int nf = 0; nf < 8; nf++) {
            int col = n0 + wn * 64 + nf * 8 + 2 * tig;
            float bi0 = __ldg(bias + col), bi1 = __ldg(bias + col + 1);
            float v00 = acc.a[mf][nf][0] + bi0, v01 = acc.a[mf][nf][1] + bi1;
            float v10 = acc.a[mf][nf][2] + bi0, v11 = acc.a[mf][nf][3] + bi1;
            if (isQ) {
                *(__half2*)(&g_q16[(size_t)row0 * DD + col]) =
                    __floats2half2_rn(v00 * QSCALE, v01 * QSCALE);
                *(__half2*)(&g_q16[(size_t)row1 * DD + col]) =
                    __floats2half2_rn(v10 * QSCALE, v11 * QSCALE);
            } else {
                __half* dst = (col < 512) ? g_k16 : g_v16;
                int c = (col < 512) ? col : col - 512;
                *(__half2*)(&dst[(size_t)row0 * DD + c]) = __floats2half2_rn(v00, v01);
                *(__half2*)(&dst[(size_t)row1 * DD + c]) = __floats2half2_rn(v10, v11);
            }
        }
    }
}

// -------------------- output projection (slice/clip scatter) -----------------
__global__ __launch_bounds__(256, 2)
void out_gemm(const __half* __restrict__ A, const __half* __restrict__ Wt,
              const float* __restrict__ bias, float* __restrict__ C) {
    extern __shared__ uint32_t sm[];
    const int m0 = blockIdx.y * 128, n0 = blockIdx.x * 128;
    GemmAcc acc;
    gemm_main(sm, A, Wt, m0, n0, acc);

    const int lane = threadIdx.x & 31, wid = threadIdx.x >> 5;
    const int g = lane >> 2, tig = lane & 3;
    const int wm = wid & 3, wn = wid >> 2;
    #pragma unroll
    for (int mf = 0; mf < 2; mf++) {
        int row0 = m0 + wm * 32 + mf * 16 + g;
        #pragma unroll
        for (int nf = 0; nf < 8; nf++) {
            int col = n0 + wn * 64 + nf * 8 + 2 * tig;
            float bi0 = __ldg(bias + col), bi1 = __ldg(bias + col + 1);
            float vs[2][2] = {
                {acc.a[mf][nf][0] + bi0, acc.a[mf][nf][1] + bi1},
                {acc.a[mf][nf][2] + bi0, acc.a[mf][nf][3] + bi1}};
            #pragma unroll
            for (int r = 0; r < 2; r++) {
                int m = row0 + r * 8;
                int q = m >> 2, b = m & 3;
                if (q < RCU_ROWS) {
                    *(float2*)(C + (size_t)m * DD + col) =
                        make_float2(vs[r][0], vs[r][1]);
                } else if (q < QL - 1) {
                    float a0 = fminf(fmaxf(vs[r][0], -10.f), 10.f);
                    float a1 = fminf(fmaxf(vs[r][1], -10.f), 10.f);
                    *(float2*)(C + RCU_SZ +
                        (size_t)((q - RCU_ROWS) * BB + b) * DD + col) =
                        make_float2(a0, a1);
                }
            }
        }
    }
}

// -------------------- fp16 flash attention (ldmatrix + 3-stage) ---------------
// smem (u32): Qs[4608] | stage{0,1,2}: Ks[64*36] + Vs[64*36] = 4608 each
__global__ __launch_bounds__(256)
void attn_h16(const int* __restrict__ lengths) {
    extern __shared__ uint32_t sm[];
    uint32_t* Qs = sm;

    const int tid = threadIdx.x;
    const int wid = tid >> 5, lane = tid & 31;
    const int g = lane >> 2, tig = lane & 3;
    const int qq = lane >> 3, rr = lane & 7;
    const int b = g_perm[blockIdx.y >> 3];
    const int h = blockIdx.y & 7;
    const int q0 = blockIdx.x * 128;
    const int wrow = wid * 16;
    const int qg0 = q0 + wrow + g;
    const int qg1 = qg0 + 8;
    const unsigned long long* mrow0 = g_mbits + ((size_t)b * QL + qg0) * NWORD;
    const unsigned long long* mrow1 = g_mbits + ((size_t)b * QL + qg1) * NWORD;

    const int limit = 128 + __ldg(lengths + b);
    const int NTb = min(NWORD, (limit + 63) >> 6);

    // ldmatrix lane offsets (u32)
    const uint32_t qa_off = (uint32_t)((wrow + ((qq & 1) << 3) + rr) * 36 + ((qq >> 1) << 2));
    const uint32_t kb_off = (uint32_t)((((qq >> 1) << 3) + rr) * 36 + ((qq & 1) << 2));
    const uint32_t vb_off = (uint32_t)((((qq & 1) << 3) + rr) * 36 + ((qq >> 1) << 2));

    auto load_kv = [&](int t, uint32_t* stage) {
        int k0 = t * 64;
        uint32_t* Ks = stage;
        uint32_t* Vs = stage + 2304;
        #pragma unroll
        for (int l = 0; l < 2; l++) {
            int item = tid + l * 256;
            int row = item >> 3, c = item & 7;
            CP16(s2u(Ks + row * 36 + c * 4),
                 g_k16 + ((size_t)(k0 + row) * BB + b) * DD + h * DH + c * 8);
        }
        #pragma unroll
        for (int l = 0; l < 2; l++) {
            int item = tid + l * 256;
            int row = item >> 3, c = item & 7;
            CP16(s2u(Vs + row * 36 + c * 4),
                 g_v16 + ((size_t)(k0 + row) * BB + b) * DD + h * DH + c * 8);
        }
    };

    #pragma unroll
    for (int l = 0; l < 4; l++) {
        int item = tid + l * 256;
        int row = item >> 3, c = item & 7;
        CP16(s2u(Qs + row * 36 + c * 4),
             g_q16 + ((size_t)(q0 + row) * BB + b) * DD + h * DH + c * 8);
    }
    load_kv(0, sm + 4608);
    CP_COMMIT();
    if (1 < NTb) load_kv(1, sm + 4608 + 4608);
    CP_COMMIT();

    float m_[2] = {-3.0e38f, -3.0e38f};
    float l_[2] = {0.f, 0.f};
    float o[8][4];
    #pragma unroll
    for (int nf = 0; nf < 8; nf++)
        #pragma unroll
        for (int e = 0; e < 4; e++) o[nf][e] = 0.f;

    const uint32_t qa_base = s2u(Qs) + qa_off * 4;
    int st = 0, st2 = 2;
    #pragma unroll 1
    for (int t = 0; t < NTb; t++) {
        unsigned long long w0 = mrow0[t], w1 = mrow1[t];

        if (t + 2 < NTb) load_kv(t + 2, sm + 4608 + st2 * 4608);
        CP_COMMIT();
        asm volatile("cp.async.wait_group 2;\n");
        __syncthreads();

        uint32_t* stage = sm + 4608 + st * 4608;
        const uint32_t ks_base = s2u(stage) + kb_off * 4;
        const uint32_t vs_base = s2u(stage + 2304) + vb_off * 4;

        // S = Q @ K^T
        float s[8][4];
        #pragma unroll
        for (int nf = 0; nf < 8; nf++)
            #pragma unroll
            for (int e = 0; e < 4; e++) s[nf][e] = 0.f;
        #pragma unroll
        for (int kc = 0; kc < 4; kc++) {
            uint32_t a0, a1, a2, a3;
            ldsm4(a0, a1, a2, a3, qa_base + (uint32_t)(kc * 32));
            #pragma unroll
            for (int P = 0; P < 4; P++) {
                uint32_t b0, b1, b2, b3;
                ldsm4(b0, b1, b2, b3,
                      ks_base + (uint32_t)((P * 16 * 36 + kc * 8) * 4));
                hmma(s[2 * P],     a0, a1, a2, a3, b0, b1);
                hmma(s[2 * P + 1], a0, a1, a2, a3, b2, b3);
            }
        }

        #pragma unroll
        for (int nf = 0; nf < 8; nf++) {
            int sh = nf * 8 + 2 * tig;
            uint32_t b0 = (uint32_t)(w0 >> sh);
            uint32_t b1 = (uint32_t)(w1 >> sh);
            if (b0 & 1) s[nf][0] = NEGINF;
            if (b0 & 2) s[nf][1] = NEGINF;
            if (b1 & 1) s[nf][2] = NEGINF;
            if (b1 & 2) s[nf][3] = NEGINF;
        }

        float tm0 = -3.0e38f, tm1 = -3.0e38f;
        #pragma unroll
        for (int nf = 0; nf < 8; nf++) {
            tm0 = fmaxf(tm0, fmaxf(s[nf][0], s[nf][1]));
            tm1 = fmaxf(tm1, fmaxf(s[nf][2], s[nf][3]));
        }
        tm0 = fmaxf(tm0, __shfl_xor_sync(0xffffffffu, tm0, 1));
        tm0 = fmaxf(tm0, __shfl_xor_sync(0xffffffffu, tm0, 2));
        tm1 = fmaxf(tm1, __shfl_xor_sync(0xffffffffu, tm1, 1));
        tm1 = fmaxf(tm1, __shfl_xor_sync(0xffffffffu, tm1, 2));
        float mn0 = fmaxf(m_[0], tm0), mn1 = fmaxf(m_[1], tm1);
        float corr0 = ex2(m_[0] - mn0), corr1 = ex2(m_[1] - mn1);
        float ps0 = 0.f, ps1 = 0.f;
        #pragma unroll
        for (int nf = 0; nf < 8; nf++) {
            s[nf][0] = ex2(s[nf][0] - mn0);
            s[nf][1] = ex2(s[nf][1] - mn0);
            s[nf][2] = ex2(s[nf][2] - mn1);
            s[nf][3] = ex2(s[nf][3] - mn1);
            ps0 += s[nf][0] + s[nf][1];
            ps1 += s[nf][2] + s[nf][3];
        }
        ps0 += __shfl_xor_sync(0xffffffffu, ps0, 1);
        ps0 += __shfl_xor_sync(0xffffffffu, ps0, 2);
        ps1 += __shfl_xor_sync(0xffffffffu, ps1, 1);
        ps1 += __shfl_xor_sync(0xffffffffu, ps1, 2);
        l_[0] = l_[0] * corr0 + ps0; m_[0] = mn0;
        l_[1] = l_[1] * corr1 + ps1; m_[1] = mn1;
        #pragma unroll
        for (int nf = 0; nf < 8; nf++) {
            o[nf][0] *= corr0; o[nf][1] *= corr0;
            o[nf][2] *= corr1; o[nf][3] *= corr1;
        }

        // O += P @ V (V via ldmatrix.trans)
        #pragma unroll
        for (int kc = 0; kc < 4; kc++) {
            uint32_t pa0 = packh2(s[2 * kc][0],     s[2 * kc][1]);
            uint32_t pa1 = packh2(s[2 * kc][2],     s[2 * kc][3]);
            uint32_t pa2 = packh2(s[2 * kc + 1][0], s[2 * kc + 1][1]);
            uint32_t pa3 = packh2(s[2 * kc + 1][2], s[2 * kc + 1][3]);
            #pragma unroll
            for (int P = 0; P < 4; P++) {
                uint32_t b0, b1, b2, b3;
                ldsm4t(b0, b1, b2, b3,
                       vs_base + (uint32_t)((kc * 16 * 36 + P * 8) * 4));
                hmma(o[2 * P],     pa0, pa1, pa2, pa3, b0, b1);
                hmma(o[2 * P + 1], pa0, pa1, pa2, pa3, b2, b3);
            }
        }
        __syncthreads();

        st  = (st  == 2) ? 0 : st + 1;
        st2 = (st2 == 2) ? 0 : st2 + 1;
    }

    float inv0 = 1.0f / l_[0], inv1 = 1.0f / l_[1];
    #pragma unroll
    for (int nf = 0; nf < 8; nf++) {
        int col = h * DH + nf * 8 + 2 * tig;
        *(__half2*)(&g_attn16[((size_t)qg0 * BB + b) * DD + col]) =
            __floats2half2_rn(o[nf][0] * inv0, o[nf][1] * inv0);
        *(__half2*)(&g_attn16[((size_t)qg1 * BB + b) * DD + col]) =
            __floats2half2_rn(o[nf][2] * inv1, o[nf][3] * inv1);
    }
}

// -------------------- launch ------------------------------------------------
extern "C" void kernel_launch(void* const* d_in, const int* in_sizes, int n_in,
                              void* d_out, int out_size) {
    const float* utt      = (const float*)d_in[0];
    const int*   lengths  = (const int*)d_in[1];
    const float* rc       = (const float*)d_in[2];
    const float* summ     = (const float*)d_in[3];
    const float* mem      = (const float*)d_in[4];
    const void*  mask_raw = (const void*)d_in[5];
    const float* w_q   = (const float*)d_in[6];
    const float* b_q   = (const float*)d_in[7];
    const float* w_kv  = (const float*)d_in[8];
    const float* b_kv  = (const float*)d_in[9];
    const float* w_out = (const float*)d_in[10];
    const float* b_out = (const float*)d_in[11];
    float* out = (float*)d_out;

    void *p;
    cudaGetSymbolAddress(&p, g_qin16);  __half* qin16  = (__half*)p;
    cudaGetSymbolAddress(&p, g_kvin16); __half* kvin16 = (__half*)p;
    cudaGetSymbolAddress(&p, g_attn16); __half* attn16 = (__half*)p;
    cudaGetSymbolAddress(&p, g_wqt);    __half* wqt    = (__half*)p;
    cudaGetSymbolAddress(&p, g_wkvt);   __half* wkvt   = (__half*)p;
    cudaGetSymbolAddress(&p, g_wot);    __half* wot    = (__half*)p;

    const int GSM = 18432 * 4;
    cudaFuncSetAttribute(qkv_gemm,
                         cudaFuncAttributeMaxDynamicSharedMemorySize, GSM);
    cudaFuncSetAttribute(out_gemm,
                         cudaFuncAttributeMaxDynamicSharedMemorySize, GSM);
    const int ASM = 18432 * 4;
    cudaFuncSetAttribute(attn_h16,
                         cudaFuncAttributeMaxDynamicSharedMemorySize, ASM);

    prep_convert<<<8704 + 64, 256>>>(utt, rc, summ, mem,
                                     (const unsigned char*)mask_raw, lengths);
    wconv_all<<<1024, 256>>>(w_q, w_kv, w_out);
    {
        int warps = QL * NWORD;
        mask_pack<<<(warps * 32 + 255) / 256, 256>>>(mask_raw, lengths);
    }
    qkv_gemm<<<dim3(12, 68), 256, GSM>>>(qin16, kvin16, wqt, wkvt, b_q, b_kv);
    attn_h16<<<dim3(QL / 128, BB * NH), 256, ASM>>>(lengths);
    out_gemm<<<dim3(4, 68), 256, GSM>>>(attn16, wot, b_out, out);
}

// round 11
// speedup vs baseline: 10.2909x; 1.0846x over previous
#include <cuda_runtime.h>
#include <cuda_fp16.h>
#include <cstdint>

#define UQ   2048
#define BB   4
#define DD   512
#define QL   2176
#define KVL  2176
#define NH   8
#define DH   64
#define NEGINF (-100000000.0f)
#define MROWS (QL*BB)          // 8704
#define RCU_ROWS 2112
#define RCU_SZ (2112*4*512)
#define NWORD 34               // KVL/64
#define QSCALE (0.125f * 1.44269504088896f)   // dh^-0.5 * log2(e)

// -------------------- device scratch ----------------------------------------
__device__ __half g_qin16 [MROWS * DD];
__device__ __half g_kvin16[MROWS * DD];
__device__ __half g_q16   [MROWS * DD];
__device__ __half g_k16   [MROWS * DD];
__device__ __half g_v16   [MROWS * DD];   // plain [token*BB+b][dh] (same as K)
__device__ __half g_attn16[MROWS * DD];
__device__ __half g_wqt [512 * 512];
__device__ __half g_wkvt[1024 * 512];
__device__ __half g_wot [512 * 512];
__device__ unsigned long long g_mbits[BB * QL * NWORD];
__device__ int g_flags[3];    // static-zero; monotone atomicOr (replay-stable)
__device__ int g_perm[BB];    // batches sorted by length desc (LPT)

// -------------------- helpers ------------------------------------------------
__device__ __forceinline__ void hmma(float* c,
    uint32_t a0, uint32_t a1, uint32_t a2, uint32_t a3,
    uint32_t b0, uint32_t b1) {
    asm volatile(
        "mma.sync.aligned.m16n8k16.row.col.f32.f16.f16.f32 "
        "{%0,%1,%2,%3}, {%4,%5,%6,%7}, {%8,%9}, {%0,%1,%2,%3};\n"
        : "+f"(c[0]), "+f"(c[1]), "+f"(c[2]), "+f"(c[3])
        : "r"(a0), "r"(a1), "r"(a2), "r"(a3), "r"(b0), "r"(b1));
}
__device__ __forceinline__ void ldsm4(uint32_t& r0, uint32_t& r1,
                                      uint32_t& r2, uint32_t& r3, uint32_t a) {
    asm volatile("ldmatrix.sync.aligned.m8n8.x4.shared.b16 {%0,%1,%2,%3}, [%4];"
        : "=r"(r0), "=r"(r1), "=r"(r2), "=r"(r3) : "r"(a));
}
__device__ __forceinline__ void ldsm4t(uint32_t& r0, uint32_t& r1,
                                       uint32_t& r2, uint32_t& r3, uint32_t a) {
    asm volatile("ldmatrix.sync.aligned.m8n8.x4.trans.shared.b16 {%0,%1,%2,%3}, [%4];"
        : "=r"(r0), "=r"(r1), "=r"(r2), "=r"(r3) : "r"(a));
}
__device__ __forceinline__ uint32_t packh2(float lo, float hi) {
    uint32_t r; asm("cvt.rn.f16x2.f32 %0, %1, %2;" : "=r"(r) : "f"(hi), "f"(lo));
    return r;
}
__device__ __forceinline__ float ex2(float x) {
    float r; asm("ex2.approx.f32 %0, %1;" : "=f"(r) : "f"(x)); return r;
}
__device__ __forceinline__ uint32_t s2u(const void* p) {
    return (uint32_t)__cvta_generic_to_shared(p);
}
#define CP16(dst, src) \
    asm volatile("cp.async.cg.shared.global [%0], [%1], 16;\n" :: "r"(dst), "l"(src))
#define CP_COMMIT() asm volatile("cp.async.commit_group;\n")

// -------------------- fused prep: gather/convert + mask sniff + LPT perm -----
__global__ void prep_convert(const float* __restrict__ utt,
                             const float* __restrict__ rc,
                             const float* __restrict__ summ,
                             const float* __restrict__ mem,
                             const unsigned char* __restrict__ rawmask,
                             const int* __restrict__ lengths) {
    const int QN = MROWS * 128;
    int bid = blockIdx.x;
    if (bid < 8704) {
        int i = bid * blockDim.x + threadIdx.x;
        if (i < QN) {
            int row = i >> 7;
            float4 v;
            if (row < 256)       v = ((const float4*)rc)[i];
            else if (row < 8448) v = ((const float4*)utt)[i - 256 * 128];
            else                 v = ((const float4*)summ)[i - 8448 * 128];
            uint2 o; o.x = packh2(v.x, v.y); o.y = packh2(v.z, v.w);
            ((uint2*)g_qin16)[i] = o;
        } else {
            int j = i - QN;
            int row = j >> 7;
            float4 v;
            if (row < 256)      v = ((const float4*)mem)[j];
            else if (row < 512) v = ((const float4*)rc)[j - 256 * 128];
            else                v = ((const float4*)utt)[j - 512 * 128];
            uint2 o; o.x = packh2(v.x, v.y); o.y = packh2(v.z, v.w);
            ((uint2*)g_kvin16)[j] = o;
        }
    } else {
        int sb = bid - 8704;
        int f0 = 0, f1 = 0, f2 = 0;
        const int SCAN = 1 << 20;
        int stride = 64 * blockDim.x * 4;
        for (int i = (sb * blockDim.x + threadIdx.x) * 4; i < SCAN; i += stride) {
            uchar4 v = *(const uchar4*)(rawmask + i);
            if (v.x > 1 || v.y > 1) f0 = 1;
            if (v.z > 1 || v.w > 1) f1 = 1;
            if (v.y | v.z | v.w)    f2 = 1;
        }
        if (f0) atomicOr(&g_flags[0], 1);
        if (f1) atomicOr(&g_flags[1], 1);
        if (f2) atomicOr(&g_flags[2], 1);
        if (sb == 0 && threadIdx.x == 0) {
            int len[BB], idx[BB];
            for (int i = 0; i < BB; i++) { len[i] = __ldg(lengths + i); idx[i] = i; }
            for (int i = 1; i < BB; i++) {
                int l = len[i], ix = idx[i], j = i - 1;
                while (j >= 0 && len[j] < l) {
                    len[j + 1] = len[j]; idx[j + 1] = idx[j]; j--;
                }
                len[j + 1] = l; idx[j + 1] = ix;
            }
            for (int i = 0; i < BB; i++) g_perm[i] = idx[i];
        }
    }
}

// -------------------- fused weight transpose + mask pack ----------------------
// blocks [0,1024): weight transpose+convert; blocks [1024,...): mask pack.
__global__ void wconv_pack(const float* __restrict__ wq,
                           const float* __restrict__ wkv,
                           const float* __restrict__ wo,
                           const void* __restrict__ raw,
                           const int* __restrict__ lengths) {
    int bid = blockIdx.x;
    if (bid < 1024) {
        __shared__ float tile[32][33];
        const float* W; __half* Wt; int NN, bx, by;
        if (bid < 256)      { W = wq;  Wt = g_wqt;  NN = 512;  bx = bid & 15; by = bid >> 4; }
        else if (bid < 768) { int b2 = bid - 256; W = wkv; Wt = g_wkvt; NN = 1024; bx = b2 & 31; by = b2 >> 5; }
        else                { int b2 = bid - 768; W = wo;  Wt = g_wot;  NN = 512;  bx = b2 & 15; by = b2 >> 4; }
        int x = threadIdx.x & 31, y0 = threadIdx.x >> 5;
        #pragma unroll
        for (int yy = y0; yy < 32; yy += 8)
            tile[yy][x] = W[(size_t)(by * 32 + yy) * NN + bx * 32 + x];
        __syncthreads();
        #pragma unroll
        for (int yy = y0; yy < 32; yy += 8)
            Wt[(size_t)(bx * 32 + yy) * 512 + by * 32 + x] =
                __float2half_rn(tile[x][yy]);
        return;
    }
    // ---- mask pack: one warp per (q, word) ----
    int warp = ((bid - 1024) * blockDim.x + threadIdx.x) >> 5;
    int lane = threadIdx.x & 31;
    if (warp >= QL * NWORD) return;
    int q = warp / NWORD, w = warp - q * NWORD;

    int kind;
    if (g_flags[0])      kind = 3;
    else if (g_flags[1]) kind = 2;
    else if (g_flags[2]) kind = 0;
    else                 kind = 1;

    size_t base = (size_t)q * KVL + w * 64;
    bool m0, m1;
    if (kind == 0) {
        const unsigned char* p = (const unsigned char*)raw;
        m0 = p[base + lane] != 0; m1 = p[base + 32 + lane] != 0;
    } else if (kind == 1) {
        const int* p = (const int*)raw;
        m0 = p[base + lane] != 0; m1 = p[base + 32 + lane] != 0;
    } else if (kind == 2) {
        const float* p = (const float*)raw;
        m0 = p[base + lane] != 0.f; m1 = p[base + 32 + lane] != 0.f;
    } else {
        const unsigned short* p = (const unsigned short*)raw;
        m0 = (p[base + lane] & 0x7fff) != 0;
        m1 = (p[base + 32 + lane] & 0x7fff) != 0;
    }
    uint32_t lo = __ballot_sync(0xffffffffu, m0);
    uint32_t hi = __ballot_sync(0xffffffffu, m1);
    unsigned long long word = (unsigned long long)lo |
                              ((unsigned long long)hi << 32);
    if (lane < 4) {
        int limit = 128 + __ldg(lengths + lane);
        int k0 = w * 64;
        unsigned long long pad;
        if (limit <= k0)           pad = ~0ull;
        else if (limit >= k0 + 64) pad = 0ull;
        else                       pad = (~0ull) << (limit - k0);
        g_mbits[((size_t)lane * QL + q) * NWORD + w] = word | pad;
    }
}

// -------------------- fp16 GEMM core (ldmatrix fragments) --------------------
struct GemmAcc { float a[2][8][4]; };

__device__ __forceinline__ void gemm_main(uint32_t* sm, const __half* A,
                                          const __half* Wt, int m0, int n0,
                                          GemmAcc& acc) {
    const int tid = threadIdx.x;
    const int wid = tid >> 5, lane = tid & 31;
    const int qq = lane >> 3, rr = lane & 7;
    const int wm = wid & 3, wn = wid >> 2;

    const uint32_t a_off = (uint32_t)((((qq & 1) << 3) + rr) * 36 + ((qq >> 1) << 2));
    const uint32_t b_off = (uint32_t)(((wn * 64) + ((qq >> 1) << 3) + rr) * 36 + ((qq & 1) << 2));

    #pragma unroll
    for (int mf = 0; mf < 2; mf++)
        #pragma unroll
        for (int nf = 0; nf < 8; nf++)
            #pragma unroll
            for (int e = 0; e < 4; e++) acc.a[mf][nf][e] = 0.f;

    auto issue = [&](int t) {
        int k0 = t * 64;
        uint32_t* As = sm + (t & 1) * 4608;
        uint32_t* Bs = sm + 9216 + (t & 1) * 4608;
        #pragma unroll
        for (int l = 0; l < 4; l++) {
            int item = tid + l * 256;
            int row = item >> 3, c = item & 7;
            CP16(s2u(As + row * 36 + c * 4),
                 A + (size_t)(m0 + row) * 512 + k0 + c * 8);
        }
        #pragma unroll
        for (int l = 0; l < 4; l++) {
            int item = tid + l * 256;
            int row = item >> 3, c = item & 7;
            CP16(s2u(Bs + row * 36 + c * 4),
                 Wt + (size_t)(n0 + row) * 512 + k0 + c * 8);
        }
        CP_COMMIT();
    };

    issue(0);
    #pragma unroll 1
    for (int t = 0; t < 8; t++) {
        if (t + 1 < 8) {
            issue(t + 1);
            asm volatile("cp.async.wait_group 1;\n");
        } else {
            asm volatile("cp.async.wait_group 0;\n");
        }
        __syncthreads();
        uint32_t as_base = s2u(sm + (t & 1) * 4608) + a_off * 4;
        uint32_t bs_base = s2u(sm + 9216 + (t & 1) * 4608) + b_off * 4;
        #pragma unroll
        for (int kc = 0; kc < 4; kc++) {
            uint32_t a[2][4];
            #pragma unroll
            for (int mf = 0; mf < 2; mf++)
                ldsm4(a[mf][0], a[mf][1], a[mf][2], a[mf][3],
                      as_base + (uint32_t)(((wm * 32 + mf * 16) * 36 + kc * 8) * 4));
            #pragma unroll
            for (int P = 0; P < 4; P++) {
                uint32_t b0, b1, b2, b3;
                ldsm4(b0, b1, b2, b3,
                      bs_base + (uint32_t)((P * 16 * 36 + kc * 8) * 4));
                hmma(acc.a[0][2 * P],     a[0][0], a[0][1], a[0][2], a[0][3], b0, b1);
                hmma(acc.a[1][2 * P],     a[1][0], a[1][1], a[1][2], a[1][3], b0, b1);
                hmma(acc.a[0][2 * P + 1], a[0][0], a[0][1], a[0][2], a[0][3], b2, b3);
                hmma(acc.a[1][2 * P + 1], a[1][0], a[1][1], a[1][2], a[1][3], b2, b3);
            }
        }
        __syncthreads();
    }
}

// -------------------- merged Q + KV projection -------------------------------
__global__ __launch_bounds__(256, 2)
void qkv_gemm(const __half* __restrict__ qA, const __half* __restrict__ kvA,
              const __half* __restrict__ wq, const __half* __restrict__ wkv,
              const float* __restrict__ bq, const float* __restrict__ bkv) {
    extern __shared__ uint32_t sm[];
    const bool isQ = blockIdx.x < 4;
    const int n0 = isQ ? blockIdx.x * 128 : (blockIdx.x - 4) * 128;
    const int m0 = blockIdx.y * 128;
    const __half* A  = isQ ? qA : kvA;
    const __half* Wt = isQ ? wq : wkv;
    const float* bias = isQ ? bq : bkv;

    GemmAcc acc;
    gemm_main(sm, A, Wt, m0, n0, acc);

    const int lane = threadIdx.x & 31, wid = threadIdx.x >> 5;
    const int g = lane >> 2, tig = lane & 3;
    const int wm = wid & 3, wn = wid >> 2;
    #pragma unroll
    for (int mf = 0; mf < 2; mf++) {
        int row0 = m0 + wm * 32 + mf * 16 + g;
        int row1 = row0 + 8;
        #pragma unroll
        for (int nf = 0; nf < 8; nf++) {
            int col = n0 + wn * 64 + nf * 8 + 2 * tig;
            float bi0 = __ldg(bias + col), bi1 = __ldg(bias + col + 1);
            float v00 = acc.a[mf][nf][0] + bi0, v01 = acc.a[mf][nf][1] + bi1;
            float v10 = acc.a[mf][nf][2] + bi0, v11 = acc.a[mf][nf][3] + bi1;
            if (isQ) {
                *(__half2*)(&g_q16[(size_t)row0 * DD + col]) =
                    __floats2half2_rn(v00 * QSCALE, v01 * QSCALE);
                *(__half2*)(&g_q16[(size_t)row1 * DD + col]) =
                    __floats2half2_rn(v10 * QSCALE, v11 * QSCALE);
            } else {
                __half* dst = (col < 512) ? g_k16 : g_v16;
                int c = (col < 512) ? col : col - 512;
                *(__half2*)(&dst[(size_t)row0 * DD + c]) = __floats2half2_rn(v00, v01);
                *(__half2*)(&dst[(size_t)row1 * DD + c]) = __floats2half2_rn(v10, v11);
            }
        }
    }
}

// -------------------- output projection (slice/clip scatter) -----------------
__global__ __launch_bounds__(256, 2)
void out_gemm(const __half* __restrict__ A, const __half* __restrict__ Wt,
              const float* __restrict__ bias, float* __restrict__ C) {
    extern __shared__ uint32_t sm[];
    const int m0 = blockIdx.y * 128, n0 = blockIdx.x * 128;
    GemmAcc acc;
    gemm_main(sm, A, Wt, m0, n0, acc);

    const int lane = threadIdx.x & 31, wid = threadIdx.x >> 5;
    const int g = lane >> 2, tig = lane & 3;
    const int wm = wid & 3, wn = wid >> 2;
    #pragma unroll
    for (int mf = 0; mf < 2; mf++) {
        int row0 = m0 + wm * 32 + mf * 16 + g;
        #pragma unroll
        for (int nf = 0; nf < 8; nf++) {
            int col = n0 + wn * 64 + nf * 8 + 2 * tig;
            float bi0 = __ldg(bias + col), bi1 = __ldg(bias + col + 1);
            float vs[2][2] = {
                {acc.a[mf][nf][0] + bi0, acc.a[mf][nf][1] + bi1},
                {acc.a[mf][nf][2] + bi0, acc.a[mf][nf][3] + bi1}};
            #pragma unroll
            for (int r = 0; r < 2; r++) {
                int m = row0 + r * 8;
                int q = m >> 2, b = m & 3;
                if (q < RCU_ROWS) {
                    *(float2*)(C + (size_t)m * DD + col) =
                        make_float2(vs[r][0], vs[r][1]);
                } else if (q < QL - 1) {
                    float a0 = fminf(fmaxf(vs[r][0], -10.f), 10.f);
                    float a1 = fminf(fmaxf(vs[r][1], -10.f), 10.f);
                    *(float2*)(C + RCU_SZ +
                        (size_t)((q - RCU_ROWS) * BB + b) * DD + col) =
                        make_float2(a0, a1);
                }
            }
        }
    }
}

// -------------------- fp16 flash attention (max-free softmax) -----------------
// Fixed-base softmax: p = 2^s (s in log2 domain, |s| <~ 12 so no overflow; fp16
// pack of p is scale-invariant in relative precision). No running max, no
// correction rescales, no per-tile reductions — l reduced across lanes once.
__global__ __launch_bounds__(256)
void attn_h16(const int* __restrict__ lengths) {
    extern __shared__ uint32_t sm[];
    uint32_t* Qs = sm;

    const int tid = threadIdx.x;
    const int wid = tid >> 5, lane = tid & 31;
    const int g = lane >> 2, tig = lane & 3;
    const int qq = lane >> 3, rr = lane & 7;
    const int b = g_perm[blockIdx.y >> 3];
    const int h = blockIdx.y & 7;
    const int q0 = blockIdx.x * 128;
    const int wrow = wid * 16;
    const int qg0 = q0 + wrow + g;
    const int qg1 = qg0 + 8;
    const unsigned long long* mrow0 = g_mbits + ((size_t)b * QL + qg0) * NWORD;
    const unsigned long long* mrow1 = g_mbits + ((size_t)b * QL + qg1) * NWORD;

    const int limit = 128 + __ldg(lengths + b);
    const int NTb = min(NWORD, (limit + 63) >> 6);

    const uint32_t qa_off = (uint32_t)((wrow + ((qq & 1) << 3) + rr) * 36 + ((qq >> 1) << 2));
    const uint32_t kb_off = (uint32_t)((((qq >> 1) << 3) + rr) * 36 + ((qq & 1) << 2));
    const uint32_t vb_off = (uint32_t)((((qq & 1) << 3) + rr) * 36 + ((qq >> 1) << 2));

    auto load_kv = [&](int t, uint32_t* stage) {
        int k0 = t * 64;
        uint32_t* Ks = stage;
        uint32_t* Vs = stage + 2304;
        #pragma unroll
        for (int l = 0; l < 2; l++) {
            int item = tid + l * 256;
            int row = item >> 3, c = item & 7;
            CP16(s2u(Ks + row * 36 + c * 4),
                 g_k16 + ((size_t)(k0 + row) * BB + b) * DD + h * DH + c * 8);
        }
        #pragma unroll
        for (int l = 0; l < 2; l++) {
            int item = tid + l * 256;
            int row = item >> 3, c = item & 7;
            CP16(s2u(Vs + row * 36 + c * 4),
                 g_v16 + ((size_t)(k0 + row) * BB + b) * DD + h * DH + c * 8);
        }
    };

    #pragma unroll
    for (int l = 0; l < 4; l++) {
        int item = tid + l * 256;
        int row = item >> 3, c = item & 7;
        CP16(s2u(Qs + row * 36 + c * 4),
             g_q16 + ((size_t)(q0 + row) * BB + b) * DD + h * DH + c * 8);
    }
    load_kv(0, sm + 4608);
    CP_COMMIT();
    if (1 < NTb) load_kv(1, sm + 4608 + 4608);
    CP_COMMIT();

    float l0 = 0.f, l1 = 0.f;
    float o[8][4];
    #pragma unroll
    for (int nf = 0; nf < 8; nf++)
        #pragma unroll
        for (int e = 0; e < 4; e++) o[nf][e] = 0.f;

    const uint32_t qa_base = s2u(Qs) + qa_off * 4;
    int st = 0, st2 = 2;
    #pragma unroll 1
    for (int t = 0; t < NTb; t++) {
        unsigned long long w0 = mrow0[t], w1 = mrow1[t];

        if (t + 2 < NTb) load_kv(t + 2, sm + 4608 + st2 * 4608);
        CP_COMMIT();
        asm volatile("cp.async.wait_group 2;\n");
        __syncthreads();

        uint32_t* stage = sm + 4608 + st * 4608;
        const uint32_t ks_base = s2u(stage) + kb_off * 4;
        const uint32_t vs_base = s2u(stage + 2304) + vb_off * 4;

        // S = Q @ K^T
        float s[8][4];
        #pragma unroll
        for (int nf = 0; nf < 8; nf++)
            #pragma unroll
            for (int e = 0; e < 4; e++) s[nf][e] = 0.f;
        #pragma unroll
        for (int kc = 0; kc < 4; kc++) {
            uint32_t a0, a1, a2, a3;
            ldsm4(a0, a1, a2, a3, qa_base + (uint32_t)(kc * 32));
            #pragma unroll
            for (int P = 0; P < 4; P++) {
                uint32_t b0, b1, b2, b3;
                ldsm4(b0, b1, b2, b3,
                      ks_base + (uint32_t)((P * 16 * 36 + kc * 8) * 4));
                hmma(s[2 * P],     a0, a1, a2, a3, b0, b1);
                hmma(s[2 * P + 1], a0, a1, a2, a3, b2, b3);
            }
        }

        // mask -> p = 2^s -> accumulate l (no max, no reductions)
        #pragma unroll
        for (int nf = 0; nf < 8; nf++) {
            int sh = nf * 8 + 2 * tig;
            uint32_t b0 = (uint32_t)(w0 >> sh);
            uint32_t b1 = (uint32_t)(w1 >> sh);
            if (b0 & 1) s[nf][0] = NEGINF;
            if (b0 & 2) s[nf][1] = NEGINF;
            if (b1 & 1) s[nf][2] = NEGINF;
            if (b1 & 2) s[nf][3] = NEGINF;
            s[nf][0] = ex2(s[nf][0]);
            s[nf][1] = ex2(s[nf][1]);
            s[nf][2] = ex2(s[nf][2]);
            s[nf][3] = ex2(s[nf][3]);
            l0 += s[nf][0] + s[nf][1];
            l1 += s[nf][2] + s[nf][3];
        }

        // O += P @ V (V via ldmatrix.trans)
        #pragma unroll
        for (int kc = 0; kc < 4; kc++) {
            uint32_t pa0 = packh2(s[2 * kc][0],     s[2 * kc][1]);
            uint32_t pa1 = packh2(s[2 * kc][2],     s[2 * kc][3]);
            uint32_t pa2 = packh2(s[2 * kc + 1][0], s[2 * kc + 1][1]);
            uint32_t pa3 = packh2(s[2 * kc + 1][2], s[2 * kc + 1][3]);
            #pragma unroll
            for (int P = 0; P < 4; P++) {
                uint32_t b0, b1, b2, b3;
                ldsm4t(b0, b1, b2, b3,
                       vs_base + (uint32_t)((kc * 16 * 36 + P * 8) * 4));
                hmma(o[2 * P],     pa0, pa1, pa2, pa3, b0, b1);
                hmma(o[2 * P + 1], pa0, pa1, pa2, pa3, b2, b3);
            }
        }
        __syncthreads();

        st  = (st  == 2) ? 0 : st + 1;
        st2 = (st2 == 2) ? 0 : st2 + 1;
    }

    // one final cross-lane reduction of l per row
    l0 += __shfl_xor_sync(0xffffffffu, l0, 1);
    l0 += __shfl_xor_sync(0xffffffffu, l0, 2);
    l1 += __shfl_xor_sync(0xffffffffu, l1, 1);
    l1 += __shfl_xor_sync(0xffffffffu, l1, 2);
    float inv0 = 1.0f / l0, inv1 = 1.0f / l1;
    #pragma unroll
    for (int nf = 0; nf < 8; nf++) {
        int col = h * DH + nf * 8 + 2 * tig;
        *(__half2*)(&g_attn16[((size_t)qg0 * BB + b) * DD + col]) =
            __floats2half2_rn(o[nf][0] * inv0, o[nf][1] * inv0);
        *(__half2*)(&g_attn16[((size_t)qg1 * BB + b) * DD + col]) =
            __floats2half2_rn(o[nf][2] * inv1, o[nf][3] * inv1);
    }
}

// -------------------- launch ------------------------------------------------
extern "C" void kernel_launch(void* const* d_in, const int* in_sizes, int n_in,
                              void* d_out, int out_size) {
    const float* utt      = (const float*)d_in[0];
    const int*   lengths  = (const int*)d_in[1];
    const float* rc       = (const float*)d_in[2];
    const float* summ     = (const float*)d_in[3];
    const float* mem      = (const float*)d_in[4];
    const void*  mask_raw = (const void*)d_in[5];
    const float* w_q   = (const float*)d_in[6];
    const float* b_q   = (const float*)d_in[7];
    const float* w_kv  = (const float*)d_in[8];
    const float* b_kv  = (const float*)d_in[9];
    const float* w_out = (const float*)d_in[10];
    const float* b_out = (const float*)d_in[11];
    float* out = (float*)d_out;

    void *p;
    cudaGetSymbolAddress(&p, g_qin16);  __half* qin16  = (__half*)p;
    cudaGetSymbolAddress(&p, g_kvin16); __half* kvin16 = (__half*)p;
    cudaGetSymbolAddress(&p, g_attn16); __half* attn16 = (__half*)p;
    cudaGetSymbolAddress(&p, g_wqt);    __half* wqt    = (__half*)p;
    cudaGetSymbolAddress(&p, g_wkvt);   __half* wkvt   = (__half*)p;
    cudaGetSymbolAddress(&p, g_wot);    __half* wot    = (__half*)p;

    const int GSM = 18432 * 4;
    cudaFuncSetAttribute(qkv_gemm,
                         cudaFuncAttributeMaxDynamicSharedMemorySize, GSM);
    cudaFuncSetAttribute(out_gemm,
                         cudaFuncAttributeMaxDynamicSharedMemorySize, GSM);
    const int ASM = 18432 * 4;
    cudaFuncSetAttribute(attn_h16,
                         cudaFuncAttributeMaxDynamicSharedMemorySize, ASM);

    prep_convert<<<8704 + 64, 256>>>(utt, rc, summ, mem,
                                     (const unsigned char*)mask_raw, lengths);
    {
        int pack_blocks = (QL * NWORD * 32 + 255) / 256;   // 9248
        wconv_pack<<<1024 + pack_blocks, 256>>>(w_q, w_kv, w_out,
                                                mask_raw, lengths);
    }
    qkv_gemm<<<dim3(12, 68), 256, GSM>>>(qin16, kvin16, wqt, wkvt, b_q, b_kv);
    attn_h16<<<dim3(QL / 128, BB * NH), 256, ASM>>>(lengths);
    out_gemm<<<dim3(4, 68), 256, GSM>>>(attn16, wot, b_out, out);
}